// round 2
// baseline (speedup 1.0000x reference)
#include <cuda_runtime.h>
#include <math.h>

#define D 128
#define E_TOTAL 640000
#define NMAX 40000

// node counts in / pooled out per layer (compile-time, verified vs math.ceil(0.8*n) double rounding)
static const int NS[10] = {40000,32000,25600,20480,16384,13108,10487,8390,6712,5370};
static const int KS[10] = {32000,25600,20480,16384,13108,10487,8390,6712,5370,4296};

// ---------------- device scratch (static globals; no allocations) ----------------
__device__ float g_h  [NMAX*D];   // pooled features (input to each layer >=1)
__device__ float g_h2 [NMAX*D];   // post conv/bn/prelu, pre-pool
__device__ float g_hw [NMAX*D];   // h @ W
__device__ float g_agg[NMAX*D];   // scatter accumulator
__device__ float g_score[NMAX];
__device__ float g_dinv [NMAX];
__device__ int   g_degi [NMAX];
__device__ int   g_remap[NMAX];
__device__ int   g_sel  [NMAX];
__device__ int   g_src[E_TOTAL];
__device__ int   g_dst[E_TOTAL];
__device__ unsigned g_hist[4][65536];
__device__ unsigned long long g_prefix;
__device__ unsigned g_kremain;
__device__ unsigned g_selcnt;
__device__ unsigned g_umax[D];
__device__ float g_colsum[D];
__device__ float g_reads[2560];
__device__ float g_z1[1280];
__device__ float g_bnsc[10*D];
__device__ float g_bnsh[10*D];
__device__ float g_pnorm[10];

// ---------------- helpers ----------------
__device__ __forceinline__ unsigned fmap(float f) {
    unsigned b = __float_as_uint(f);
    return (b & 0x80000000u) ? ~b : (b | 0x80000000u);
}
__device__ __forceinline__ float funmap(unsigned u) {
    unsigned b = (u & 0x80000000u) ? (u ^ 0x80000000u) : ~u;
    return __uint_as_float(b);
}
// key: larger == better. score desc, then index asc (matches jax top_k tie-break).
__device__ __forceinline__ unsigned long long make_key(float s, int i) {
    return (((unsigned long long)fmap(s)) << 32) | (unsigned)(0xFFFFFFFFu - (unsigned)i);
}

// ---------------- init kernels ----------------
__global__ void k_init_edges(const int* __restrict__ ei) {
    int i = blockIdx.x * blockDim.x + threadIdx.x;
    if (i >= E_TOTAL) return;
    g_src[i] = ei[i];
    g_dst[i] = ei[E_TOTAL + i];
}

__global__ void k_bnpre(const float* __restrict__ gamma, const float* __restrict__ beta,
                        const float* __restrict__ mean, const float* __restrict__ var) {
    int idx = blockIdx.x * 128 + threadIdx.x;  // grid 10 x 128
    float sc = gamma[idx] / sqrtf(var[idx] + 1e-5f);
    g_bnsc[idx] = sc;
    g_bnsh[idx] = beta[idx] - mean[idx] * sc;
}

__global__ void k_pnorm(const float* __restrict__ p) {
    int L = blockIdx.x;
    int tid = threadIdx.x;
    __shared__ float sm[128];
    float v = p[L * 128 + tid];
    sm[tid] = v * v;
    __syncthreads();
    for (int s = 64; s > 0; s >>= 1) {
        if (tid < s) sm[tid] += sm[tid + s];
        __syncthreads();
    }
    if (tid == 0) g_pnorm[L] = sqrtf(sm[0]);
}

// per-layer reset: agg, degi, remap, hist, col reducers, scalars
__global__ void k_zero(int n, unsigned k) {
    int idx = blockIdx.x * blockDim.x + threadIdx.x;
    if (idx < n * D) g_agg[idx] = 0.f;
    if (idx < n) { g_degi[idx] = 0; g_remap[idx] = -1; }
    if (idx < 4 * 65536) (&g_hist[0][0])[idx] = 0u;
    if (idx < D) { g_umax[idx] = 0u; g_colsum[idx] = 0.f; }
    if (idx == 0) { g_prefix = 0ull; g_kremain = k; g_selcnt = 0u; }
}

// ---------------- graph conv ----------------
__global__ void k_deg() {
    int i = blockIdx.x * blockDim.x + threadIdx.x;
    if (i >= E_TOTAL) return;
    int s = g_src[i];
    if (s >= 0) atomicAdd(&g_degi[g_dst[i]], 1);
}

__global__ void k_dinv(int n) {
    int i = blockIdx.x * blockDim.x + threadIdx.x;
    if (i >= n) return;
    int d = g_degi[i];
    g_dinv[i] = (d > 0) ? (1.0f / sqrtf((float)d)) : 0.f;
}

// layer 0: hw = x * W1 (rank-1)
__global__ void k_rank1(const float* __restrict__ x, const float* __restrict__ w, int n) {
    int idx = blockIdx.x * blockDim.x + threadIdx.x;
    if (idx >= n * D) return;
    g_hw[idx] = x[idx >> 7] * w[idx & 127];
}

// layer 0: h2 = prelu(bn(relu(x*V1 + agg + b)))
__global__ void k_rank1_epi(const float* __restrict__ x, const float* __restrict__ v,
                            const float* __restrict__ convbL, int L,
                            const float* __restrict__ pa, int n) {
    int idx = blockIdx.x * blockDim.x + threadIdx.x;
    if (idx >= n * D) return;
    int c = idx & 127;
    float a = pa[0];
    float val = x[idx >> 7] * v[c] + g_agg[idx] + convbL[c];
    val = fmaxf(val, 0.f);
    val = val * g_bnsc[L * 128 + c] + g_bnsh[L * 128 + c];
    g_h2[idx] = val > 0.f ? val : a * val;
}

// agg[dst] += hw[src] * dinv[src]*dinv[dst]   (one warp per edge, float4 per lane)
__global__ void k_scatter() {
    int gid = blockIdx.x * blockDim.x + threadIdx.x;
    int e = gid >> 5;
    int lane = gid & 31;
    if (e >= E_TOTAL) return;
    int s = g_src[e];
    if (s < 0) return;
    int d = g_dst[e];
    float coef = g_dinv[s] * g_dinv[d];
    if (coef == 0.f) return;
    float4 v = reinterpret_cast<const float4*>(g_hw)[(size_t)s * 32 + lane];
    float* dp = g_agg + (size_t)d * 128 + lane * 4;
    atomicAdd(dp + 0, v.x * coef);
    atomicAdd(dp + 1, v.y * coef);
    atomicAdd(dp + 2, v.z * coef);
    atomicAdd(dp + 3, v.w * coef);
}

// SGEMM: C(n x 128) = g_h(n x 128) @ B(128 x 128). EPI fuses agg+bias+relu+bn+prelu -> g_h2,
// otherwise writes g_hw.
template <bool EPI>
__global__ void __launch_bounds__(256) k_gemm(const float* __restrict__ B, int n,
                                              const float* __restrict__ convbL, int L,
                                              const float* __restrict__ pa) {
    __shared__ float As[32][65];   // [k][m], padded
    __shared__ float Bs[32][128];  // [k][n]
    int tid = threadIdx.x;
    int row0 = blockIdx.x * 64;
    int tm = tid >> 5;   // 0..7  -> 8 rows each
    int tn = tid & 31;   // 0..31 -> 4 cols each
    float acc[8][4];
#pragma unroll
    for (int i = 0; i < 8; i++)
#pragma unroll
        for (int j = 0; j < 4; j++) acc[i][j] = 0.f;

    int ra = tid >> 3;         // 0..31
    int ca = (tid & 7) * 4;    // 0..28

    for (int k0 = 0; k0 < 128; k0 += 32) {
#pragma unroll
        for (int i = 0; i < 2; i++) {
            int r = ra + i * 32;
            int gr = row0 + r;
            if (gr >= n) gr = n - 1;  // clamped load; store is guarded
            float4 v = *(const float4*)(g_h + (size_t)gr * 128 + k0 + ca);
            As[ca + 0][r] = v.x; As[ca + 1][r] = v.y;
            As[ca + 2][r] = v.z; As[ca + 3][r] = v.w;
        }
#pragma unroll
        for (int i = 0; i < 4; i++) {
            int r = (tid >> 5) + i * 8;
            *(float4*)&Bs[r][tn * 4] = *(const float4*)(B + (size_t)(k0 + r) * 128 + tn * 4);
        }
        __syncthreads();
#pragma unroll
        for (int kk = 0; kk < 32; kk++) {
            float a[8], b[4];
#pragma unroll
            for (int i = 0; i < 8; i++) a[i] = As[kk][tm * 8 + i];
#pragma unroll
            for (int j = 0; j < 4; j++) b[j] = Bs[kk][tn * 4 + j];
#pragma unroll
            for (int i = 0; i < 8; i++)
#pragma unroll
                for (int j = 0; j < 4; j++) acc[i][j] += a[i] * b[j];
        }
        __syncthreads();
    }

    float aP = EPI ? pa[0] : 0.f;
#pragma unroll
    for (int i = 0; i < 8; i++) {
        int r = row0 + tm * 8 + i;
        if (r >= n) continue;
#pragma unroll
        for (int j = 0; j < 4; j++) {
            int c = tn * 4 + j;
            size_t idx = (size_t)r * 128 + c;
            float v = acc[i][j];
            if (EPI) {
                v += g_agg[idx] + convbL[c];
                v = fmaxf(v, 0.f);
                v = v * g_bnsc[L * 128 + c] + g_bnsh[L * 128 + c];
                v = v > 0.f ? v : aP * v;
                g_h2[idx] = v;
            } else {
                g_hw[idx] = v;
            }
        }
    }
}

// score[i] = tanh(h2[i,:] . p / ||p||), one warp per node
__global__ void k_score(const float* __restrict__ pL, int L, int n) {
    int gid = blockIdx.x * blockDim.x + threadIdx.x;
    int node = gid >> 5;
    int lane = gid & 31;
    if (node >= n) return;
    const float* row = g_h2 + (size_t)node * 128;
    float s = 0.f;
#pragma unroll
    for (int j = 0; j < 4; j++) s += row[lane + j * 32] * pL[lane + j * 32];
#pragma unroll
    for (int off = 16; off > 0; off >>= 1) s += __shfl_xor_sync(0xFFFFFFFFu, s, off);
    if (lane == 0) g_score[node] = tanhf(s / g_pnorm[L]);
}

// ---------------- exact top-k via 64-bit radix select (16-bit digits, 4 passes) ----------------
template <int PASS>
__global__ void k_hist(int n) {
    int i = blockIdx.x * blockDim.x + threadIdx.x;
    if (i >= n) return;
    unsigned long long key = make_key(g_score[i], i);
    if (PASS > 0) {
        const int hs = 64 - 16 * PASS;
        if ((key >> hs) != (g_prefix >> hs)) return;
    }
    unsigned digit = (unsigned)((key >> (48 - 16 * PASS)) & 0xFFFFull);
    atomicAdd(&g_hist[PASS][digit], 1u);
}

template <int PASS>
__global__ void k_scan() {
    __shared__ unsigned csum[1024];
    __shared__ unsigned incl[1024];
    int tid = threadIdx.x;
    unsigned kr = g_kremain;  // all threads read before any write below
    const unsigned* H = g_hist[PASS];
    unsigned s = 0;
    int base = tid * 64;
#pragma unroll 8
    for (int i = 0; i < 64; i++) s += H[base + i];
    csum[tid] = s;
    __syncthreads();
    incl[tid] = csum[1023 - tid];
    __syncthreads();
    for (int off = 1; off < 1024; off <<= 1) {
        unsigned v = (tid >= off) ? incl[tid - off] : 0u;
        __syncthreads();
        incl[tid] += v;
        __syncthreads();
    }
    unsigned suf = incl[1023 - tid];       // sum of chunks tid..1023
    unsigned above = suf - csum[tid];      // sum of chunks > tid
    if (above < kr && suf >= kr) {         // crossing inside this chunk (exactly one thread)
        unsigned running = above;
        for (int b = 63; b >= 0; b--) {
            unsigned c = H[base + b];
            if (running + c >= kr) {
                g_kremain = kr - running;
                g_prefix |= ((unsigned long long)(unsigned)(base + b)) << (48 - 16 * PASS);
                break;
            }
            running += c;
        }
    }
}

__global__ void k_select(int n) {
    int i = blockIdx.x * blockDim.x + threadIdx.x;
    if (i >= n) return;
    unsigned long long key = make_key(g_score[i], i);
    if (key >= g_prefix) {  // keys unique -> exactly k selected
        unsigned pos = atomicAdd(&g_selcnt, 1u);
        g_sel[pos] = i;
        g_remap[i] = (int)pos;
    }
}

// gather pooled rows (h = h2[sel]*score[sel]) and fold in column max/sum for reads
__global__ void k_gather(int k) {
    int c = threadIdx.x;            // 128 threads
    int r0 = blockIdx.x * 64;
    float lmax = __int_as_float(0xff800000);  // -inf
    float lsum = 0.f;
    int rend = r0 + 64; if (rend > k) rend = k;
#pragma unroll 4
    for (int r = r0; r < rend; r++) {
        int i = g_sel[r];
        float v = g_h2[(size_t)i * 128 + c] * g_score[i];
        g_h[(size_t)r * 128 + c] = v;
        lmax = fmaxf(lmax, v);
        lsum += v;
    }
    atomicMax(&g_umax[c], fmap(lmax));
    atomicAdd(&g_colsum[c], lsum);
}

__global__ void k_remap_edges() {
    int e = blockIdx.x * blockDim.x + threadIdx.x;
    if (e >= E_TOTAL) return;
    int s = g_src[e];
    if (s < 0) return;
    int ns = g_remap[s];
    int nd = g_remap[g_dst[e]];
    if (ns >= 0 && nd >= 0) { g_src[e] = ns; g_dst[e] = nd; }
    else { g_src[e] = -1; }
}

__global__ void k_readsfin(int L, float invk) {
    int c = threadIdx.x;  // 128
    g_reads[L * 256 + c] = funmap(g_umax[c]);
    g_reads[L * 256 + 128 + c] = g_colsum[c] * invk;
}

// ---------------- MLP head ----------------
__global__ void k_mlpzero() {
    int i = blockIdx.x * blockDim.x + threadIdx.x;
    if (i < 1280) g_z1[i] = 0.f;
}

__global__ void k_lin1(const float* __restrict__ W) {
    int col = blockIdx.x * 256 + threadIdx.x;  // 0..1279
    int r0 = blockIdx.y * 320;
    float acc = 0.f;
    for (int r = r0; r < r0 + 320; r++) acc += g_reads[r] * W[(size_t)r * 1280 + col];
    atomicAdd(&g_z1[col], acc);
}

__global__ void k_lin1act(const float* __restrict__ b, const float* __restrict__ pa) {
    int i = blockIdx.x * 256 + threadIdx.x;
    if (i >= 1280) return;
    float a = pa[0];
    float z = g_z1[i] + b[i];
    g_z1[i] = z > 0.f ? z : a * z;
}

__global__ void k_lin2(const float* __restrict__ W2, const float* __restrict__ b2,
                       const float* __restrict__ pa, float* __restrict__ out) {
    int tid = threadIdx.x;  // 256
    float acc[8] = {0, 0, 0, 0, 0, 0, 0, 0};
    for (int i = tid; i < 1280; i += 256) {
        float v = g_z1[i];
#pragma unroll
        for (int j = 0; j < 8; j++) acc[j] += v * W2[i * 8 + j];
    }
    __shared__ float red[256][8];
#pragma unroll
    for (int j = 0; j < 8; j++) red[tid][j] = acc[j];
    __syncthreads();
    for (int s = 128; s > 0; s >>= 1) {
        if (tid < s)
#pragma unroll
            for (int j = 0; j < 8; j++) red[tid][j] += red[tid + s][j];
        __syncthreads();
    }
    if (tid == 0) {
        float a = pa[0];
        float z[8];
#pragma unroll
        for (int j = 0; j < 8; j++) {
            float s = red[0][j] + b2[j];
            z[j] = s > 0.f ? s : a * s;
        }
        float mn = z[0];
#pragma unroll
        for (int j = 1; j < 8; j++) mn = fminf(mn, z[j]);
#pragma unroll
        for (int j = 0; j < 8; j++) z[j] -= mn;
        float mx = z[0];
#pragma unroll
        for (int j = 1; j < 8; j++) mx = fmaxf(mx, z[j]);
#pragma unroll
        for (int j = 0; j < 8; j++) z[j] /= mx;
        float sm = 0.f;
#pragma unroll
        for (int j = 0; j < 8; j++) sm += z[j];
#pragma unroll
        for (int j = 0; j < 8; j++) out[j] = z[j] / sm;
    }
}

// ---------------- launcher ----------------
extern "C" void kernel_launch(void* const* d_in, const int* in_sizes, int n_in,
                              void* d_out, int out_size) {
    const float* x       = (const float*)d_in[0];
    const int*   ei      = (const int*)  d_in[1];
    const float* W1      = (const float*)d_in[2];
    const float* V1      = (const float*)d_in[3];
    const float* Ws      = (const float*)d_in[4];
    const float* Vs      = (const float*)d_in[5];
    const float* conv_b  = (const float*)d_in[6];
    const float* bn_g    = (const float*)d_in[7];
    const float* bn_b    = (const float*)d_in[8];
    const float* bn_m    = (const float*)d_in[9];
    const float* bn_v    = (const float*)d_in[10];
    const float* pool_p  = (const float*)d_in[11];
    const float* prelu_a = (const float*)d_in[12];
    const float* lin1_w  = (const float*)d_in[13];
    const float* lin1_b  = (const float*)d_in[14];
    const float* lin2_w  = (const float*)d_in[15];
    const float* lin2_b  = (const float*)d_in[16];
    float* out = (float*)d_out;

    const int EB = (E_TOTAL + 255) / 256;

    k_init_edges<<<EB, 256>>>(ei);
    k_bnpre<<<10, 128>>>(bn_g, bn_b, bn_m, bn_v);
    k_pnorm<<<10, 128>>>(pool_p);

    for (int L = 0; L < 10; L++) {
        int n = NS[L], k = KS[L];
        int gN = (n + 255) / 256;
        int gND = (n * D + 255) / 256;

        k_zero<<<gND, 256>>>(n, (unsigned)k);
        k_deg<<<EB, 256>>>();
        k_dinv<<<gN, 256>>>(n);

        if (L == 0)
            k_rank1<<<gND, 256>>>(x, W1, n);
        else
            k_gemm<false><<<(n + 63) / 64, 256>>>(Ws + (size_t)(L - 1) * D * D, n,
                                                  nullptr, 0, nullptr);

        k_scatter<<<(E_TOTAL * 32 + 255) / 256, 256>>>();

        if (L == 0)
            k_rank1_epi<<<gND, 256>>>(x, V1, conv_b, 0, prelu_a, n);
        else
            k_gemm<true><<<(n + 63) / 64, 256>>>(Vs + (size_t)(L - 1) * D * D, n,
                                                 conv_b + (size_t)L * D, L, prelu_a);

        k_score<<<(n + 7) / 8, 256>>>(pool_p + (size_t)L * D, L, n);

        k_hist<0><<<gN, 256>>>(n); k_scan<0><<<1, 1024>>>();
        k_hist<1><<<gN, 256>>>(n); k_scan<1><<<1, 1024>>>();
        k_hist<2><<<gN, 256>>>(n); k_scan<2><<<1, 1024>>>();
        k_hist<3><<<gN, 256>>>(n); k_scan<3><<<1, 1024>>>();

        k_select<<<gN, 256>>>(n);
        k_gather<<<(k + 63) / 64, 128>>>(k);
        k_remap_edges<<<EB, 256>>>();
        k_readsfin<<<1, 128>>>(L, 1.0f / (float)k);
    }

    k_mlpzero<<<5, 256>>>();
    k_lin1<<<dim3(5, 8), 256>>>(lin1_w);
    k_lin1act<<<5, 256>>>(lin1_b, prelu_a);
    k_lin2<<<1, 256>>>(lin2_w, lin2_b, prelu_a, out);

    (void)in_sizes; (void)n_in; (void)out_size;
}

// round 4
// speedup vs baseline: 1.8512x; 1.8512x over previous
#include <cuda_runtime.h>
#include <math.h>

#define D 128
#define E_TOTAL 640000
#define NMAX 40000

// node counts in / pooled out per layer (verified vs math.ceil(0.8*n) double rounding)
static const int NS[10] = {40000,32000,25600,20480,16384,13108,10487,8390,6712,5370};
static const int KS[10] = {32000,25600,20480,16384,13108,10487,8390,6712,5370,4296};

// ---------------- device scratch ----------------
__device__ float g_h  [NMAX*D];
__device__ float g_h2 [NMAX*D];
__device__ float g_hw [NMAX*D];
__device__ float g_agg[NMAX*D];
__device__ float g_score[NMAX];
__device__ float g_dinv [NMAX];
__device__ int   g_degi [NMAX];
__device__ int   g_remap[NMAX];
__device__ int   g_sel  [NMAX];
__device__ int   g_off  [NMAX+1];
__device__ int   g_cur  [NMAX];
__device__ int   g_csr  [E_TOTAL];
__device__ int2  g_edges[2][E_TOTAL];
__device__ int   g_ecnt[11];
__device__ unsigned g_hist[4][65536];
__device__ unsigned g_coarse[4][1024];
__device__ unsigned long long g_prefix;
__device__ unsigned g_kremain;
__device__ unsigned g_selcnt;
__device__ unsigned g_doneA;   // histscan
__device__ unsigned g_doneB;   // gatherremap
__device__ unsigned g_doneC;   // degzero
__device__ unsigned g_umax[D];
__device__ float g_colsum[D];
__device__ float g_reads[2560];
__device__ float g_z1[1280];
__device__ float g_bnsc[10*D];
__device__ float g_bnsh[10*D];
__device__ float g_pnorm[10];

// ---------------- helpers ----------------
__device__ __forceinline__ unsigned fmap(float f) {
    unsigned b = __float_as_uint(f);
    return (b & 0x80000000u) ? ~b : (b | 0x80000000u);
}
__device__ __forceinline__ float funmap(unsigned u) {
    unsigned b = (u & 0x80000000u) ? (u ^ 0x80000000u) : ~u;
    return __uint_as_float(b);
}
__device__ __forceinline__ unsigned long long make_key(float s, int i) {
    return (((unsigned long long)fmap(s)) << 32) | (unsigned)(0xFFFFFFFFu - (unsigned)i);
}

// ---------------- init ----------------
__global__ void k_init(const int* __restrict__ ei) {
    int gid = blockIdx.x * blockDim.x + threadIdx.x;
    int stride = gridDim.x * blockDim.x;
    for (int i = gid; i < E_TOTAL; i += stride)
        g_edges[0][i] = make_int2(ei[i], ei[E_TOTAL + i]);
    for (int i = gid; i < NMAX; i += stride) g_degi[i] = 0;
    if (gid == 0) g_ecnt[0] = E_TOTAL;
}

__global__ void k_bnpre(const float* __restrict__ gamma, const float* __restrict__ beta,
                        const float* __restrict__ mean, const float* __restrict__ var) {
    int idx = blockIdx.x * 128 + threadIdx.x;
    float sc = gamma[idx] / sqrtf(var[idx] + 1e-5f);
    g_bnsc[idx] = sc;
    g_bnsh[idx] = beta[idx] - mean[idx] * sc;
}

__global__ void k_pnorm(const float* __restrict__ p) {
    int L = blockIdx.x;
    int tid = threadIdx.x;
    __shared__ float sm[128];
    float v = p[L * 128 + tid];
    sm[tid] = v * v;
    __syncthreads();
    for (int s = 64; s > 0; s >>= 1) {
        if (tid < s) sm[tid] += sm[tid + s];
        __syncthreads();
    }
    if (tid == 0) g_pnorm[L] = sqrtf(sm[0]);
}

// ---------------- per-layer: zero + degree + (last block) offsets/dinv ----------------
__global__ void __launch_bounds__(256) k_degzero(int L, int n, unsigned k, int ebuf) {
    int gid = blockIdx.x * 256 + threadIdx.x;
    int stride = gridDim.x * 256;
    unsigned* h0 = &g_hist[0][0];
    for (int i = gid; i < 4 * 65536; i += stride) h0[i] = 0u;
    unsigned* c0 = &g_coarse[0][0];
    for (int i = gid; i < 4 * 1024; i += stride) c0[i] = 0u;
    for (int i = gid; i < n; i += stride) g_remap[i] = -1;
    if (gid < 128) { g_umax[gid] = 0u; g_colsum[gid] = 0.f; }
    if (gid == 0) { g_prefix = 0ull; g_kremain = k; g_selcnt = 0u; g_ecnt[L + 1] = 0; }

    int cnt = g_ecnt[L];
    const int2* E = g_edges[ebuf];
    for (int i = gid; i < cnt; i += stride) atomicAdd(&g_degi[E[i].y], 1);

    __threadfence();
    __shared__ int lastb;
    if (threadIdx.x == 0) {
        unsigned v = atomicAdd(&g_doneC, 1u);
        lastb = (v == gridDim.x - 1);
        if (lastb) g_doneC = 0u;
    }
    __syncthreads();
    if (!lastb) return;

    // offsets / cursor / dinv by the last block (256 threads)
    int t = threadIdx.x;
    int chunk = (n + 255) / 256;
    int b0 = t * chunk;
    unsigned s = 0;
    for (int j = 0; j < chunk; j++) {
        int idx = b0 + j;
        if (idx < n) s += (unsigned)g_degi[idx];
    }
    __shared__ unsigned sc[256];
    sc[t] = s;
    __syncthreads();
    for (int off = 1; off < 256; off <<= 1) {
        unsigned v = (t >= off) ? sc[t - off] : 0u;
        __syncthreads();
        sc[t] += v;
        __syncthreads();
    }
    unsigned run = sc[t] - s;  // exclusive
    for (int j = 0; j < chunk; j++) {
        int idx = b0 + j;
        if (idx < n) {
            int d = g_degi[idx];
            g_off[idx] = (int)run;
            g_cur[idx] = (int)run;
            g_dinv[idx] = (d > 0) ? (1.0f / sqrtf((float)d)) : 0.f;
            run += (unsigned)d;
        }
    }
    if (t == 255) g_off[n] = (int)run;
}

// layer 0: hw = x * W1 (rank-1)
__global__ void k_rank1(const float* __restrict__ x, const float* __restrict__ w, int n) {
    int gid = blockIdx.x * blockDim.x + threadIdx.x;
    int stride = gridDim.x * blockDim.x;
    const float4* w4 = (const float4*)w;
    float4* o4 = (float4*)g_hw;
    for (int i = gid; i < n * 32; i += stride) {
        float xv = x[i >> 5];
        float4 wv = w4[i & 31];
        o4[i] = make_float4(xv * wv.x, xv * wv.y, xv * wv.z, xv * wv.w);
    }
}

// CSR fill: 1 atomic per edge
__global__ void k_csrfill(int L, int ebuf) {
    int gid = blockIdx.x * blockDim.x + threadIdx.x;
    int stride = gridDim.x * blockDim.x;
    int cnt = g_ecnt[L];
    const int2* E = g_edges[ebuf];
    for (int i = gid; i < cnt; i += stride) {
        int2 e = E[i];
        int pos = atomicAdd(&g_cur[e.y], 1);
        g_csr[pos] = e.x;
    }
}

// aggregate: warp per dst node, register accumulation, plain store
__global__ void k_agg(int n) {
    int gid = blockIdx.x * blockDim.x + threadIdx.x;
    int node = gid >> 5;
    int lane = gid & 31;
    if (node >= n) return;
    int st = g_off[node], en = g_off[node + 1];
    float dd = g_dinv[node];
    float4 acc = make_float4(0.f, 0.f, 0.f, 0.f);
    const float4* hw4 = (const float4*)g_hw;
    for (int j = st; j < en; j++) {
        int s = g_csr[j];
        float c = g_dinv[s] * dd;
        float4 v = hw4[(size_t)s * 32 + lane];
        acc.x += v.x * c; acc.y += v.y * c; acc.z += v.z * c; acc.w += v.w * c;
    }
    ((float4*)g_agg)[(size_t)node * 32 + lane] = acc;
}

// layer 0 epilogue + score: warp per row
__global__ void k_l0epi(const float* __restrict__ x, const float* __restrict__ V1,
                        const float* __restrict__ convb, const float* __restrict__ pa,
                        const float* __restrict__ p, int n) {
    int gid = blockIdx.x * blockDim.x + threadIdx.x;
    int r = gid >> 5;
    int lane = gid & 31;
    if (r >= n) return;
    float a = pa[0];
    float xr = x[r];
    float4 ag = ((const float4*)g_agg)[(size_t)r * 32 + lane];
    float4 vv = ((const float4*)V1)[lane];
    float4 cb = ((const float4*)convb)[lane];
    float4 s4 = ((const float4*)g_bnsc)[lane];
    float4 h4 = ((const float4*)g_bnsh)[lane];
    float4 p4 = ((const float4*)p)[lane];
    float o[4];
    o[0] = xr * vv.x + ag.x + cb.x;
    o[1] = xr * vv.y + ag.y + cb.y;
    o[2] = xr * vv.z + ag.z + cb.z;
    o[3] = xr * vv.w + ag.w + cb.w;
    float bs[4] = {s4.x, s4.y, s4.z, s4.w};
    float bh[4] = {h4.x, h4.y, h4.z, h4.w};
    float pv[4] = {p4.x, p4.y, p4.z, p4.w};
    float sp = 0.f;
#pragma unroll
    for (int j = 0; j < 4; j++) {
        float v = fmaxf(o[j], 0.f);
        v = v * bs[j] + bh[j];
        v = v > 0.f ? v : a * v;
        o[j] = v;
        sp += v * pv[j];
    }
    ((float4*)g_h2)[(size_t)r * 32 + lane] = make_float4(o[0], o[1], o[2], o[3]);
#pragma unroll
    for (int off = 16; off > 0; off >>= 1) sp += __shfl_xor_sync(0xFFFFFFFFu, sp, off);
    if (lane == 0) g_score[r] = tanhf(sp / g_pnorm[0]);
}

// ---------------- SGEMM 128x128 tile, 8x8 per thread, fused epilogue (+score) ----------------
template <bool EPI>
__global__ void __launch_bounds__(256) k_gemm(const float* __restrict__ B, int n,
                                              const float* __restrict__ convbL, int L,
                                              const float* __restrict__ pa,
                                              const float* __restrict__ pL) {
    __shared__ float As[32][132];
    __shared__ float Bs[32][128];
    __shared__ float Ssc[128][17];
    int tid = threadIdx.x;
    int row0 = blockIdx.x * 128;
    int tm = tid >> 4;   // 0..15
    int tn = tid & 15;   // 0..15
    float acc[8][8];
#pragma unroll
    for (int i = 0; i < 8; i++)
#pragma unroll
        for (int j = 0; j < 8; j++) acc[i][j] = 0.f;

    int lr = tid >> 1;            // 0..127 (A row)
    int lq = (tid & 1) * 4;       // A quad base
    int br = tid >> 3;            // 0..31  (B row)
    int bq = (tid & 7) * 4;       // B quad base

    for (int k0 = 0; k0 < 128; k0 += 32) {
        int gr = row0 + lr;
        if (gr >= n) gr = n - 1;
        const float* arow = g_h + (size_t)gr * 128 + k0;
#pragma unroll
        for (int q = 0; q < 4; q++) {
            float4 v = *(const float4*)(arow + (lq + q) * 4);
            int c = (lq + q) * 4;
            As[c + 0][lr] = v.x; As[c + 1][lr] = v.y;
            As[c + 2][lr] = v.z; As[c + 3][lr] = v.w;
        }
#pragma unroll
        for (int q = 0; q < 4; q++)
            *(float4*)&Bs[br][(bq + q) * 4] =
                *(const float4*)(B + (size_t)(k0 + br) * 128 + (bq + q) * 4);
        __syncthreads();
#pragma unroll
        for (int kk = 0; kk < 32; kk++) {
            float a[8], b[8];
            *(float4*)&a[0] = *(const float4*)&As[kk][tm * 8];
            *(float4*)&a[4] = *(const float4*)&As[kk][tm * 8 + 4];
            *(float4*)&b[0] = *(const float4*)&Bs[kk][tn * 8];
            *(float4*)&b[4] = *(const float4*)&Bs[kk][tn * 8 + 4];
#pragma unroll
            for (int i = 0; i < 8; i++)
#pragma unroll
                for (int j = 0; j < 8; j++) acc[i][j] += a[i] * b[j];
        }
        __syncthreads();
    }

    if (!EPI) {
#pragma unroll
        for (int i = 0; i < 8; i++) {
            int r = row0 + tm * 8 + i;
            if (r >= n) continue;
            float* dst = g_hw + (size_t)r * 128 + tn * 8;
            *(float4*)dst = make_float4(acc[i][0], acc[i][1], acc[i][2], acc[i][3]);
            *(float4*)(dst + 4) = make_float4(acc[i][4], acc[i][5], acc[i][6], acc[i][7]);
        }
    } else {
        float aP = pa[0];
        float pn = g_pnorm[L];
        float pv[8], bs[8], bh[8], cb[8];
#pragma unroll
        for (int j = 0; j < 8; j++) {
            int c = tn * 8 + j;
            pv[j] = pL[c];
            bs[j] = g_bnsc[L * 128 + c];
            bh[j] = g_bnsh[L * 128 + c];
            cb[j] = convbL[c];
        }
#pragma unroll
        for (int i = 0; i < 8; i++) {
            int r = row0 + tm * 8 + i;
            const float* ar = g_agg + (size_t)r * 128 + tn * 8;  // r < NMAX always
            float sp = 0.f;
#pragma unroll
            for (int j = 0; j < 8; j++) {
                float v = acc[i][j] + ar[j] + cb[j];
                v = fmaxf(v, 0.f);
                v = v * bs[j] + bh[j];
                v = v > 0.f ? v : aP * v;
                acc[i][j] = v;
                sp += v * pv[j];
            }
            if (r < n) {
                float* dst = g_h2 + (size_t)r * 128 + tn * 8;
                *(float4*)dst = make_float4(acc[i][0], acc[i][1], acc[i][2], acc[i][3]);
                *(float4*)(dst + 4) = make_float4(acc[i][4], acc[i][5], acc[i][6], acc[i][7]);
            }
            Ssc[tm * 8 + i][tn] = sp;
        }
        __syncthreads();
        if (tid < 128) {
            int r = row0 + tid;
            if (r < n) {
                float s = 0.f;
#pragma unroll
                for (int j = 0; j < 16; j++) s += Ssc[tid][j];
                g_score[r] = tanhf(s / pn);
            }
        }
    }
}

// ---------------- top-k: hist + fused last-block scan ----------------
template <int PASS>
__global__ void __launch_bounds__(256) k_histscan(int n) {
    int i = blockIdx.x * 256 + threadIdx.x;
    if (i < n) {
        unsigned long long key = make_key(g_score[i], i);
        bool act = true;
        if (PASS > 0) {
            const int hs = 64 - 16 * PASS;
            act = ((key >> hs) == (g_prefix >> hs));
        }
        if (act) {
            unsigned digit = (unsigned)((key >> (48 - 16 * PASS)) & 0xFFFFull);
            atomicAdd(&g_hist[PASS][digit], 1u);
            atomicAdd(&g_coarse[PASS][digit >> 6], 1u);
        }
    }
    __threadfence();
    __shared__ int lastb;
    if (threadIdx.x == 0) {
        unsigned v = atomicAdd(&g_doneA, 1u);
        lastb = (v == gridDim.x - 1);
        if (lastb) g_doneA = 0u;
    }
    __syncthreads();
    if (!lastb) return;

    // last block (256 threads) scans the 1024 coarse bins, then 64 fine bins
    int t = threadIdx.x;
    unsigned kr = g_kremain;
    int cb0 = t * 4;
    unsigned s = 0;
#pragma unroll
    for (int q = 0; q < 4; q++) s += g_coarse[PASS][cb0 + q];
    __shared__ unsigned arr[256];
    arr[t] = s;
    __syncthreads();
    // suffix sums over chunks (descending digit order): suf[t] = sum arr[t..255]
    __shared__ unsigned rev[256];
    rev[t] = arr[255 - t];
    __syncthreads();
    for (int off = 1; off < 256; off <<= 1) {
        unsigned v = (t >= off) ? rev[t - off] : 0u;
        __syncthreads();
        rev[t] += v;
        __syncthreads();
    }
    unsigned suf = rev[255 - t];       // includes own chunk
    unsigned above = suf - s;          // chunks with higher digits
    if (above < kr && suf >= kr) {     // crossing inside this chunk (exactly one thread)
        unsigned running = above;
        for (int b = 3; b >= 0; b--) {
            unsigned c = g_coarse[PASS][cb0 + b];
            if (running + c >= kr) {
                // crossing inside coarse bin cb0+b: walk its 64 fine bins descending
                int fb = (cb0 + b) * 64;
                for (int d = 63; d >= 0; d--) {
                    unsigned fc = g_hist[PASS][fb + d];
                    if (running + fc >= kr) {
                        g_kremain = kr - running;
                        g_prefix |= ((unsigned long long)(unsigned)(fb + d)) << (48 - 16 * PASS);
                        break;
                    }
                    running += fc;
                }
                break;
            }
            running += c;
        }
    }
}

__global__ void k_select(int n) {
    int i = blockIdx.x * blockDim.x + threadIdx.x;
    if (i >= n) return;
    unsigned long long key = make_key(g_score[i], i);
    if (key >= g_prefix) {  // keys unique -> exactly k selected
        unsigned pos = atomicAdd(&g_selcnt, 1u);
        g_sel[pos] = i;
        g_remap[i] = (int)pos;
    }
}

// gather pooled rows + column max/sum + edge remap/compact + (last block) reads finalize
__global__ void __launch_bounds__(128) k_gatherremap(int L, int k, int ebuf, float invk) {
    int c = threadIdx.x;   // 128 threads = columns
    int r0 = blockIdx.x * 64;
    float lmax = __int_as_float(0xff800000);
    float lsum = 0.f;
    int rend = r0 + 64; if (rend > k) rend = k;
    for (int r = r0; r < rend; r++) {
        int i = g_sel[r];
        float v = g_h2[(size_t)i * 128 + c] * g_score[i];
        g_h[(size_t)r * 128 + c] = v;
        lmax = fmaxf(lmax, v);
        lsum += v;
        if (c == 0) g_degi[r] = 0;   // clear for next layer
    }
    atomicMax(&g_umax[c], fmap(lmax));
    atomicAdd(&g_colsum[c], lsum);

    // edge remap + compaction
    int cnt = g_ecnt[L];
    const int2* Ein = g_edges[ebuf];
    int2* Eout = g_edges[ebuf ^ 1];
    for (int i = blockIdx.x * 128 + c; i < cnt; i += gridDim.x * 128) {
        int2 e = Ein[i];
        int ns = g_remap[e.x];
        int nd = g_remap[e.y];
        if (ns >= 0 && nd >= 0) {
            int pos = atomicAdd(&g_ecnt[L + 1], 1);
            Eout[pos] = make_int2(ns, nd);
        }
    }

    __threadfence();
    __shared__ int lastb;
    if (c == 0) {
        unsigned v = atomicAdd(&g_doneB, 1u);
        lastb = (v == gridDim.x - 1);
        if (lastb) g_doneB = 0u;
    }
    __syncthreads();
    if (lastb) {
        g_reads[L * 256 + c] = funmap(g_umax[c]);
        g_reads[L * 256 + 128 + c] = g_colsum[c] * invk;
    }
}

// ---------------- MLP head ----------------
__global__ void k_mlpzero() {
    int i = blockIdx.x * blockDim.x + threadIdx.x;
    if (i < 1280) g_z1[i] = 0.f;
}

__global__ void k_lin1(const float* __restrict__ W) {
    int col = blockIdx.x * 256 + threadIdx.x;
    int r0 = blockIdx.y * 320;
    float acc = 0.f;
    for (int r = r0; r < r0 + 320; r++) acc += g_reads[r] * W[(size_t)r * 1280 + col];
    atomicAdd(&g_z1[col], acc);
}

__global__ void k_lin1act(const float* __restrict__ b, const float* __restrict__ pa) {
    int i = blockIdx.x * 256 + threadIdx.x;
    if (i >= 1280) return;
    float a = pa[0];
    float z = g_z1[i] + b[i];
    g_z1[i] = z > 0.f ? z : a * z;
}

__global__ void k_lin2(const float* __restrict__ W2, const float* __restrict__ b2,
                       const float* __restrict__ pa, float* __restrict__ out) {
    int tid = threadIdx.x;  // 256
    float acc[8] = {0, 0, 0, 0, 0, 0, 0, 0};
    for (int i = tid; i < 1280; i += 256) {
        float v = g_z1[i];
#pragma unroll
        for (int j = 0; j < 8; j++) acc[j] += v * W2[i * 8 + j];
    }
    __shared__ float red[256][8];
#pragma unroll
    for (int j = 0; j < 8; j++) red[tid][j] = acc[j];
    __syncthreads();
    for (int s = 128; s > 0; s >>= 1) {
        if (tid < s)
#pragma unroll
            for (int j = 0; j < 8; j++) red[tid][j] += red[tid + s][j];
        __syncthreads();
    }
    if (tid == 0) {
        float a = pa[0];
        float z[8];
#pragma unroll
        for (int j = 0; j < 8; j++) {
            float s = red[0][j] + b2[j];
            z[j] = s > 0.f ? s : a * s;
        }
        float mn = z[0];
#pragma unroll
        for (int j = 1; j < 8; j++) mn = fminf(mn, z[j]);
#pragma unroll
        for (int j = 0; j < 8; j++) z[j] -= mn;
        float mx = z[0];
#pragma unroll
        for (int j = 1; j < 8; j++) mx = fmaxf(mx, z[j]);
#pragma unroll
        for (int j = 0; j < 8; j++) z[j] /= mx;
        float sm = 0.f;
#pragma unroll
        for (int j = 0; j < 8; j++) sm += z[j];
#pragma unroll
        for (int j = 0; j < 8; j++) out[j] = z[j] / sm;
    }
}

// ---------------- launcher ----------------
extern "C" void kernel_launch(void* const* d_in, const int* in_sizes, int n_in,
                              void* d_out, int out_size) {
    const float* x       = (const float*)d_in[0];
    const int*   ei      = (const int*)  d_in[1];
    const float* W1      = (const float*)d_in[2];
    const float* V1      = (const float*)d_in[3];
    const float* Ws      = (const float*)d_in[4];
    const float* Vs      = (const float*)d_in[5];
    const float* conv_b  = (const float*)d_in[6];
    const float* bn_g    = (const float*)d_in[7];
    const float* bn_b    = (const float*)d_in[8];
    const float* bn_m    = (const float*)d_in[9];
    const float* bn_v    = (const float*)d_in[10];
    const float* pool_p  = (const float*)d_in[11];
    const float* prelu_a = (const float*)d_in[12];
    const float* lin1_w  = (const float*)d_in[13];
    const float* lin1_b  = (const float*)d_in[14];
    const float* lin2_w  = (const float*)d_in[15];
    const float* lin2_b  = (const float*)d_in[16];
    float* out = (float*)d_out;

    k_init<<<512, 256>>>(ei);
    k_bnpre<<<10, 128>>>(bn_g, bn_b, bn_m, bn_v);
    k_pnorm<<<10, 128>>>(pool_p);

    for (int L = 0; L < 10; L++) {
        int n = NS[L], k = KS[L];
        int eb = L & 1;

        k_degzero<<<256, 256>>>(L, n, (unsigned)k, eb);

        if (L == 0)
            k_rank1<<<1024, 256>>>(x, W1, n);
        else
            k_gemm<false><<<(n + 127) / 128, 256>>>(Ws + (size_t)(L - 1) * D * D, n,
                                                    nullptr, 0, nullptr, nullptr);

        k_csrfill<<<512, 256>>>(L, eb);
        k_agg<<<(n * 32 + 255) / 256, 256>>>(n);

        if (L == 0)
            k_l0epi<<<(n * 32 + 255) / 256, 256>>>(x, V1, conv_b, prelu_a, pool_p, n);
        else
            k_gemm<true><<<(n + 127) / 128, 256>>>(Vs + (size_t)(L - 1) * D * D, n,
                                                   conv_b + (size_t)L * D, L, prelu_a,
                                                   pool_p + (size_t)L * D);

        int gN = (n + 255) / 256;
        k_histscan<0><<<gN, 256>>>(n);
        k_histscan<1><<<gN, 256>>>(n);
        k_histscan<2><<<gN, 256>>>(n);
        k_histscan<3><<<gN, 256>>>(n);
        k_select<<<gN, 256>>>(n);

        k_gatherremap<<<(k + 63) / 64, 128>>>(L, k, eb, 1.0f / (float)k);
    }

    k_mlpzero<<<5, 256>>>();
    k_lin1<<<dim3(5, 8), 256>>>(lin1_w);
    k_lin1act<<<5, 256>>>(lin1_b, prelu_a);
    k_lin2<<<1, 256>>>(lin2_w, lin2_b, prelu_a, out);

    (void)in_sizes; (void)n_in; (void)out_size;
}

// round 5
// speedup vs baseline: 2.3443x; 1.2663x over previous
#include <cuda_runtime.h>
#include <math.h>

#define D 128
#define E_TOTAL 640000
#define NMAX 40000
#define NPAD (NMAX + 1024)

// node counts in / pooled out per layer (verified vs math.ceil(0.8*n) double rounding)
static const int NS[10] = {40000,32000,25600,20480,16384,13108,10487,8390,6712,5370};
static const int KS[10] = {32000,25600,20480,16384,13108,10487,8390,6712,5370,4296};
static const int NT[10] = {40,32,25,20,16,13,11,9,7,6};  // (n+1023)/1024

// ---------------- device scratch ----------------
__device__ float g_h  [NMAX*D];
__device__ float g_h2 [NMAX*D];
__device__ float g_hw [NMAX*D];
__device__ float g_agg[NMAX*D];
__device__ float g_score[NMAX];
__device__ float g_dinv [NMAX];
__device__ __align__(16) int g_degi[NPAD];
__device__ int   g_remap[NMAX];
__device__ int   g_sel  [NMAX];
__device__ int   g_off  [NMAX+1];
__device__ int   g_cur  [NMAX];
__device__ int   g_csr  [E_TOTAL];
__device__ int2  g_edges[2][E_TOTAL];
__device__ int   g_ecnt[11];
__device__ int   g_tilesum[64];
__device__ int   g_tilepref[64];
__device__ unsigned g_hist[4][65536];
__device__ unsigned g_coarse[4][1024];
__device__ unsigned long long g_prefix;
__device__ unsigned g_kremain;
__device__ unsigned g_selcnt;
__device__ unsigned g_doneA;   // histscan
__device__ unsigned g_doneB;   // gatherremap
__device__ unsigned g_doneC;   // degzero
__device__ unsigned g_umax[D];
__device__ float g_colsum[D];
__device__ float g_reads[2560];
__device__ float g_z1[1280];
__device__ float g_bnsc[10*D];
__device__ float g_bnsh[10*D];
__device__ float g_pnorm[10];

// ---------------- helpers ----------------
__device__ __forceinline__ unsigned fmap(float f) {
    unsigned b = __float_as_uint(f);
    return (b & 0x80000000u) ? ~b : (b | 0x80000000u);
}
__device__ __forceinline__ float funmap(unsigned u) {
    unsigned b = (u & 0x80000000u) ? (u ^ 0x80000000u) : ~u;
    return __uint_as_float(b);
}
__device__ __forceinline__ unsigned long long make_key(float s, int i) {
    return (((unsigned long long)fmap(s)) << 32) | (unsigned)(0xFFFFFFFFu - (unsigned)i);
}

// ---------------- init ----------------
__global__ void k_zerodeg() {
    int gid = blockIdx.x * blockDim.x + threadIdx.x;
    if (gid < NPAD) g_degi[gid] = 0;
}

__global__ void k_init(const int* __restrict__ ei) {
    int gid = blockIdx.x * blockDim.x + threadIdx.x;
    int stride = gridDim.x * blockDim.x;
    for (int i = gid; i < E_TOTAL; i += stride) {
        int d = ei[E_TOTAL + i];
        g_edges[0][i] = make_int2(ei[i], d);
        atomicAdd(&g_degi[d], 1);
    }
    if (gid == 0) g_ecnt[0] = E_TOTAL;
}

__global__ void k_bnpre(const float* __restrict__ gamma, const float* __restrict__ beta,
                        const float* __restrict__ mean, const float* __restrict__ var) {
    int idx = blockIdx.x * 128 + threadIdx.x;
    float sc = gamma[idx] / sqrtf(var[idx] + 1e-5f);
    g_bnsc[idx] = sc;
    g_bnsh[idx] = beta[idx] - mean[idx] * sc;
}

__global__ void k_pnorm(const float* __restrict__ p) {
    int L = blockIdx.x;
    int tid = threadIdx.x;
    __shared__ float sm[128];
    float v = p[L * 128 + tid];
    sm[tid] = v * v;
    __syncthreads();
    for (int s = 64; s > 0; s >>= 1) {
        if (tid < s) sm[tid] += sm[tid + s];
        __syncthreads();
    }
    if (tid == 0) g_pnorm[L] = sqrtf(sm[0]);
}

// ---------------- per-layer: zero scratch + tile degree sums + (last block) tile prefix ----------------
__global__ void __launch_bounds__(256) k_degzero(int L, int n, unsigned k, int ntiles) {
    int t = threadIdx.x;
    int gid = blockIdx.x * 256 + t;
    int stride = gridDim.x * 256;
    unsigned* h0 = &g_hist[0][0];
    for (int i = gid; i < 4 * 65536; i += stride) h0[i] = 0u;
    unsigned* c0 = &g_coarse[0][0];
    for (int i = gid; i < 4 * 1024; i += stride) c0[i] = 0u;
    for (int i = gid; i < n; i += stride) g_remap[i] = -1;
    if (gid < 128) { g_umax[gid] = 0u; g_colsum[gid] = 0.f; }
    if (gid == 0) { g_prefix = 0ull; g_kremain = k; g_selcnt = 0u; g_ecnt[L + 1] = 0; }

    // per-tile degree sums (degrees already accumulated by prior gatherremap / init)
    if (blockIdx.x < ntiles) {
        int base = blockIdx.x * 1024 + t * 4;
        int4 dv = *(const int4*)&g_degi[base];
        int s = 0;
        if (base + 0 < n) s += dv.x;
        if (base + 1 < n) s += dv.y;
        if (base + 2 < n) s += dv.z;
        if (base + 3 < n) s += dv.w;
#pragma unroll
        for (int off = 16; off > 0; off >>= 1) s += __shfl_xor_sync(0xFFFFFFFFu, s, off);
        __shared__ int ws[8];
        if ((t & 31) == 0) ws[t >> 5] = s;
        __syncthreads();
        if (t == 0) {
            int tot = 0;
#pragma unroll
            for (int j = 0; j < 8; j++) tot += ws[j];
            g_tilesum[blockIdx.x] = tot;
        }
    }

    __threadfence();
    __shared__ int lastb;
    if (t == 0) {
        unsigned v = atomicAdd(&g_doneC, 1u);
        lastb = (v == gridDim.x - 1);
        if (lastb) g_doneC = 0u;
    }
    __syncthreads();
    if (!lastb) return;
    if (t == 0) {
        int run = 0;
        for (int i = 0; i < ntiles; i++) { g_tilepref[i] = run; run += g_tilesum[i]; }
        g_off[n] = run;
    }
}

// expand per-tile offsets: one block per 1024-node tile
__global__ void __launch_bounds__(256) k_offsets(int n) {
    int t = threadIdx.x;
    int base = blockIdx.x * 1024 + t * 4;
    int4 dv = *(const int4*)&g_degi[base];
    int d0 = (base + 0 < n) ? dv.x : 0;
    int d1 = (base + 1 < n) ? dv.y : 0;
    int d2 = (base + 2 < n) ? dv.z : 0;
    int d3 = (base + 3 < n) ? dv.w : 0;
    int s = d0 + d1 + d2 + d3;
    int lane = t & 31, wid = t >> 5;
    int incl = s;
#pragma unroll
    for (int off = 1; off < 32; off <<= 1) {
        int v = __shfl_up_sync(0xFFFFFFFFu, incl, off);
        if (lane >= off) incl += v;
    }
    __shared__ int wsum[8], wpref[8];
    if (lane == 31) wsum[wid] = incl;
    __syncthreads();
    if (t < 8) {
        int p = 0;
#pragma unroll
        for (int j = 0; j < 8; j++) {
            int u = wsum[j];
            if (j < t) p += u;
        }
        wpref[t] = p;
    }
    __syncthreads();
    int excl = incl - s + wpref[wid] + g_tilepref[blockIdx.x];
    int dd[4] = {d0, d1, d2, d3};
#pragma unroll
    for (int j = 0; j < 4; j++) {
        int idx = base + j;
        if (idx < n) {
            g_off[idx] = excl;
            g_cur[idx] = excl;
            g_dinv[idx] = (dd[j] > 0) ? (1.0f / sqrtf((float)dd[j])) : 0.f;
            excl += dd[j];
        }
    }
}

// layer 0: hw = x * W1 (rank-1)
__global__ void k_rank1(const float* __restrict__ x, const float* __restrict__ w, int n) {
    int gid = blockIdx.x * blockDim.x + threadIdx.x;
    int stride = gridDim.x * blockDim.x;
    const float4* w4 = (const float4*)w;
    float4* o4 = (float4*)g_hw;
    for (int i = gid; i < n * 32; i += stride) {
        float xv = x[i >> 5];
        float4 wv = w4[i & 31];
        o4[i] = make_float4(xv * wv.x, xv * wv.y, xv * wv.z, xv * wv.w);
    }
}

// CSR fill: 1 atomic per edge
__global__ void k_csrfill(int L, int ebuf) {
    int gid = blockIdx.x * blockDim.x + threadIdx.x;
    int stride = gridDim.x * blockDim.x;
    int cnt = g_ecnt[L];
    const int2* E = g_edges[ebuf];
    for (int i = gid; i < cnt; i += stride) {
        int2 e = E[i];
        int pos = atomicAdd(&g_cur[e.y], 1);
        g_csr[pos] = e.x;
    }
}

// aggregate: warp per dst node, register accumulation, plain store
__global__ void k_agg(int n) {
    int gid = blockIdx.x * blockDim.x + threadIdx.x;
    int node = gid >> 5;
    int lane = gid & 31;
    if (node >= n) return;
    int st = g_off[node], en = g_off[node + 1];
    float dd = g_dinv[node];
    float4 acc = make_float4(0.f, 0.f, 0.f, 0.f);
    const float4* hw4 = (const float4*)g_hw;
    for (int j = st; j < en; j++) {
        int s = g_csr[j];
        float c = g_dinv[s] * dd;
        float4 v = hw4[(size_t)s * 32 + lane];
        acc.x += v.x * c; acc.y += v.y * c; acc.z += v.z * c; acc.w += v.w * c;
    }
    ((float4*)g_agg)[(size_t)node * 32 + lane] = acc;
}

// layer 0 epilogue + score: warp per row
__global__ void k_l0epi(const float* __restrict__ x, const float* __restrict__ V1,
                        const float* __restrict__ convb, const float* __restrict__ pa,
                        const float* __restrict__ p, int n) {
    int gid = blockIdx.x * blockDim.x + threadIdx.x;
    int r = gid >> 5;
    int lane = gid & 31;
    if (r >= n) return;
    float a = pa[0];
    float xr = x[r];
    float4 ag = ((const float4*)g_agg)[(size_t)r * 32 + lane];
    float4 vv = ((const float4*)V1)[lane];
    float4 cb = ((const float4*)convb)[lane];
    float4 s4 = ((const float4*)g_bnsc)[lane];
    float4 h4 = ((const float4*)g_bnsh)[lane];
    float4 p4 = ((const float4*)p)[lane];
    float o[4];
    o[0] = xr * vv.x + ag.x + cb.x;
    o[1] = xr * vv.y + ag.y + cb.y;
    o[2] = xr * vv.z + ag.z + cb.z;
    o[3] = xr * vv.w + ag.w + cb.w;
    float bs[4] = {s4.x, s4.y, s4.z, s4.w};
    float bh[4] = {h4.x, h4.y, h4.z, h4.w};
    float pv[4] = {p4.x, p4.y, p4.z, p4.w};
    float sp = 0.f;
#pragma unroll
    for (int j = 0; j < 4; j++) {
        float v = fmaxf(o[j], 0.f);
        v = v * bs[j] + bh[j];
        v = v > 0.f ? v : a * v;
        o[j] = v;
        sp += v * pv[j];
    }
    ((float4*)g_h2)[(size_t)r * 32 + lane] = make_float4(o[0], o[1], o[2], o[3]);
#pragma unroll
    for (int off = 16; off > 0; off >>= 1) sp += __shfl_xor_sync(0xFFFFFFFFu, sp, off);
    if (lane == 0) g_score[r] = tanhf(sp / g_pnorm[0]);
}

// ---------------- SGEMM 128x128 tile, 8x8 per thread, fused epilogue (+score) ----------------
template <bool EPI>
__global__ void __launch_bounds__(256) k_gemm(const float* __restrict__ B, int n,
                                              const float* __restrict__ convbL, int L,
                                              const float* __restrict__ pa,
                                              const float* __restrict__ pL) {
    __shared__ float As[32][132];
    __shared__ float Bs[32][128];
    __shared__ float Ssc[128][17];
    int tid = threadIdx.x;
    int row0 = blockIdx.x * 128;
    int tm = tid >> 4;   // 0..15
    int tn = tid & 15;   // 0..15
    float acc[8][8];
#pragma unroll
    for (int i = 0; i < 8; i++)
#pragma unroll
        for (int j = 0; j < 8; j++) acc[i][j] = 0.f;

    int lr = tid >> 1;            // 0..127 (A row)
    int lq = (tid & 1) * 4;       // A quad base
    int br = tid >> 3;            // 0..31  (B row)
    int bq = (tid & 7) * 4;       // B quad base

    for (int k0 = 0; k0 < 128; k0 += 32) {
        int gr = row0 + lr;
        if (gr >= n) gr = n - 1;
        const float* arow = g_h + (size_t)gr * 128 + k0;
#pragma unroll
        for (int q = 0; q < 4; q++) {
            float4 v = *(const float4*)(arow + (lq + q) * 4);
            int c = (lq + q) * 4;
            As[c + 0][lr] = v.x; As[c + 1][lr] = v.y;
            As[c + 2][lr] = v.z; As[c + 3][lr] = v.w;
        }
#pragma unroll
        for (int q = 0; q < 4; q++)
            *(float4*)&Bs[br][(bq + q) * 4] =
                *(const float4*)(B + (size_t)(k0 + br) * 128 + (bq + q) * 4);
        __syncthreads();
#pragma unroll
        for (int kk = 0; kk < 32; kk++) {
            float a[8], b[8];
            *(float4*)&a[0] = *(const float4*)&As[kk][tm * 8];
            *(float4*)&a[4] = *(const float4*)&As[kk][tm * 8 + 4];
            *(float4*)&b[0] = *(const float4*)&Bs[kk][tn * 8];
            *(float4*)&b[4] = *(const float4*)&Bs[kk][tn * 8 + 4];
#pragma unroll
            for (int i = 0; i < 8; i++)
#pragma unroll
                for (int j = 0; j < 8; j++) acc[i][j] += a[i] * b[j];
        }
        __syncthreads();
    }

    if (!EPI) {
#pragma unroll
        for (int i = 0; i < 8; i++) {
            int r = row0 + tm * 8 + i;
            if (r >= n) continue;
            float* dst = g_hw + (size_t)r * 128 + tn * 8;
            *(float4*)dst = make_float4(acc[i][0], acc[i][1], acc[i][2], acc[i][3]);
            *(float4*)(dst + 4) = make_float4(acc[i][4], acc[i][5], acc[i][6], acc[i][7]);
        }
    } else {
        float aP = pa[0];
        float pn = g_pnorm[L];
        float pv[8], bs[8], bh[8], cb[8];
#pragma unroll
        for (int j = 0; j < 8; j++) {
            int c = tn * 8 + j;
            pv[j] = pL[c];
            bs[j] = g_bnsc[L * 128 + c];
            bh[j] = g_bnsh[L * 128 + c];
            cb[j] = convbL[c];
        }
#pragma unroll
        for (int i = 0; i < 8; i++) {
            int r = row0 + tm * 8 + i;
            const float* ar = g_agg + (size_t)r * 128 + tn * 8;  // r < NMAX always
            float sp = 0.f;
#pragma unroll
            for (int j = 0; j < 8; j++) {
                float v = acc[i][j] + ar[j] + cb[j];
                v = fmaxf(v, 0.f);
                v = v * bs[j] + bh[j];
                v = v > 0.f ? v : aP * v;
                acc[i][j] = v;
                sp += v * pv[j];
            }
            if (r < n) {
                float* dst = g_h2 + (size_t)r * 128 + tn * 8;
                *(float4*)dst = make_float4(acc[i][0], acc[i][1], acc[i][2], acc[i][3]);
                *(float4*)(dst + 4) = make_float4(acc[i][4], acc[i][5], acc[i][6], acc[i][7]);
            }
            Ssc[tm * 8 + i][tn] = sp;
        }
        __syncthreads();
        if (tid < 128) {
            int r = row0 + tid;
            if (r < n) {
                float s = 0.f;
#pragma unroll
                for (int j = 0; j < 16; j++) s += Ssc[tid][j];
                g_score[r] = tanhf(s / pn);
            }
        }
    }
}

// ---------------- top-k: hist + fused last-block scan ----------------
template <int PASS>
__global__ void __launch_bounds__(256) k_histscan(int n) {
    int i = blockIdx.x * 256 + threadIdx.x;
    if (i < n) {
        unsigned long long key = make_key(g_score[i], i);
        bool act = true;
        if (PASS > 0) {
            const int hs = 64 - 16 * PASS;
            act = ((key >> hs) == (g_prefix >> hs));
        }
        if (act) {
            unsigned digit = (unsigned)((key >> (48 - 16 * PASS)) & 0xFFFFull);
            atomicAdd(&g_hist[PASS][digit], 1u);
            atomicAdd(&g_coarse[PASS][digit >> 6], 1u);
        }
    }
    __threadfence();
    __shared__ int lastb;
    if (threadIdx.x == 0) {
        unsigned v = atomicAdd(&g_doneA, 1u);
        lastb = (v == gridDim.x - 1);
        if (lastb) g_doneA = 0u;
    }
    __syncthreads();
    if (!lastb) return;

    int t = threadIdx.x;
    unsigned kr = g_kremain;
    int cb0 = t * 4;
    unsigned s = 0;
#pragma unroll
    for (int q = 0; q < 4; q++) s += g_coarse[PASS][cb0 + q];
    __shared__ unsigned arr[256];
    arr[t] = s;
    __syncthreads();
    __shared__ unsigned rev[256];
    rev[t] = arr[255 - t];
    __syncthreads();
    for (int off = 1; off < 256; off <<= 1) {
        unsigned v = (t >= off) ? rev[t - off] : 0u;
        __syncthreads();
        rev[t] += v;
        __syncthreads();
    }
    unsigned suf = rev[255 - t];
    unsigned above = suf - s;
    if (above < kr && suf >= kr) {
        unsigned running = above;
        for (int b = 3; b >= 0; b--) {
            unsigned c = g_coarse[PASS][cb0 + b];
            if (running + c >= kr) {
                int fb = (cb0 + b) * 64;
                for (int d = 63; d >= 0; d--) {
                    unsigned fc = g_hist[PASS][fb + d];
                    if (running + fc >= kr) {
                        g_kremain = kr - running;
                        g_prefix |= ((unsigned long long)(unsigned)(fb + d)) << (48 - 16 * PASS);
                        break;
                    }
                    running += fc;
                }
                break;
            }
            running += c;
        }
    }
}

__global__ void k_select(int n) {
    int i = blockIdx.x * blockDim.x + threadIdx.x;
    if (i >= n) return;
    g_degi[i] = 0;  // degrees consumed; clear for next layer's accumulation
    unsigned long long key = make_key(g_score[i], i);
    if (key >= g_prefix) {  // keys unique -> exactly k selected
        unsigned pos = atomicAdd(&g_selcnt, 1u);
        g_sel[pos] = i;
        g_remap[i] = (int)pos;
    }
}

// gather pooled rows + column max/sum + edge remap/compact (+ next-layer degrees) + reads finalize
__global__ void __launch_bounds__(128) k_gatherremap(int L, int k, int ebuf, float invk) {
    int c = threadIdx.x;   // 128 threads = columns
    int r0 = blockIdx.x * 64;
    float lmax = __int_as_float(0xff800000);
    float lsum = 0.f;
    int rend = r0 + 64; if (rend > k) rend = k;
    for (int r = r0; r < rend; r++) {
        int i = g_sel[r];
        float v = g_h2[(size_t)i * 128 + c] * g_score[i];
        g_h[(size_t)r * 128 + c] = v;
        lmax = fmaxf(lmax, v);
        lsum += v;
    }
    atomicMax(&g_umax[c], fmap(lmax));
    atomicAdd(&g_colsum[c], lsum);

    // edge remap + compaction + next-layer degree accumulation
    int cnt = g_ecnt[L];
    const int2* Ein = g_edges[ebuf];
    int2* Eout = g_edges[ebuf ^ 1];
    for (int i = blockIdx.x * 128 + c; i < cnt; i += gridDim.x * 128) {
        int2 e = Ein[i];
        int ns = g_remap[e.x];
        int nd = g_remap[e.y];
        if (ns >= 0 && nd >= 0) {
            int pos = atomicAdd(&g_ecnt[L + 1], 1);
            Eout[pos] = make_int2(ns, nd);
            atomicAdd(&g_degi[nd], 1);
        }
    }

    __threadfence();
    __shared__ int lastb;
    if (c == 0) {
        unsigned v = atomicAdd(&g_doneB, 1u);
        lastb = (v == gridDim.x - 1);
        if (lastb) g_doneB = 0u;
    }
    __syncthreads();
    if (lastb) {
        g_reads[L * 256 + c] = funmap(g_umax[c]);
        g_reads[L * 256 + 128 + c] = g_colsum[c] * invk;
    }
}

// ---------------- MLP head ----------------
__global__ void k_mlpzero() {
    int i = blockIdx.x * blockDim.x + threadIdx.x;
    if (i < 1280) g_z1[i] = 0.f;
}

__global__ void k_lin1(const float* __restrict__ W) {
    int col = blockIdx.x * 256 + threadIdx.x;
    int r0 = blockIdx.y * 320;
    float acc = 0.f;
    for (int r = r0; r < r0 + 320; r++) acc += g_reads[r] * W[(size_t)r * 1280 + col];
    atomicAdd(&g_z1[col], acc);
}

__global__ void k_lin1act(const float* __restrict__ b, const float* __restrict__ pa) {
    int i = blockIdx.x * 256 + threadIdx.x;
    if (i >= 1280) return;
    float a = pa[0];
    float z = g_z1[i] + b[i];
    g_z1[i] = z > 0.f ? z : a * z;
}

__global__ void k_lin2(const float* __restrict__ W2, const float* __restrict__ b2,
                       const float* __restrict__ pa, float* __restrict__ out) {
    int tid = threadIdx.x;  // 256
    float acc[8] = {0, 0, 0, 0, 0, 0, 0, 0};
    for (int i = tid; i < 1280; i += 256) {
        float v = g_z1[i];
#pragma unroll
        for (int j = 0; j < 8; j++) acc[j] += v * W2[i * 8 + j];
    }
    __shared__ float red[256][8];
#pragma unroll
    for (int j = 0; j < 8; j++) red[tid][j] = acc[j];
    __syncthreads();
    for (int s = 128; s > 0; s >>= 1) {
        if (tid < s)
#pragma unroll
            for (int j = 0; j < 8; j++) red[tid][j] += red[tid + s][j];
        __syncthreads();
    }
    if (tid == 0) {
        float a = pa[0];
        float z[8];
#pragma unroll
        for (int j = 0; j < 8; j++) {
            float s = red[0][j] + b2[j];
            z[j] = s > 0.f ? s : a * s;
        }
        float mn = z[0];
#pragma unroll
        for (int j = 1; j < 8; j++) mn = fminf(mn, z[j]);
#pragma unroll
        for (int j = 0; j < 8; j++) z[j] -= mn;
        float mx = z[0];
#pragma unroll
        for (int j = 1; j < 8; j++) mx = fmaxf(mx, z[j]);
#pragma unroll
        for (int j = 0; j < 8; j++) z[j] /= mx;
        float sm = 0.f;
#pragma unroll
        for (int j = 0; j < 8; j++) sm += z[j];
#pragma unroll
        for (int j = 0; j < 8; j++) out[j] = z[j] / sm;
    }
}

// ---------------- launcher ----------------
extern "C" void kernel_launch(void* const* d_in, const int* in_sizes, int n_in,
                              void* d_out, int out_size) {
    const float* x       = (const float*)d_in[0];
    const int*   ei      = (const int*)  d_in[1];
    const float* W1      = (const float*)d_in[2];
    const float* V1      = (const float*)d_in[3];
    const float* Ws      = (const float*)d_in[4];
    const float* Vs      = (const float*)d_in[5];
    const float* conv_b  = (const float*)d_in[6];
    const float* bn_g    = (const float*)d_in[7];
    const float* bn_b    = (const float*)d_in[8];
    const float* bn_m    = (const float*)d_in[9];
    const float* bn_v    = (const float*)d_in[10];
    const float* pool_p  = (const float*)d_in[11];
    const float* prelu_a = (const float*)d_in[12];
    const float* lin1_w  = (const float*)d_in[13];
    const float* lin1_b  = (const float*)d_in[14];
    const float* lin2_w  = (const float*)d_in[15];
    const float* lin2_b  = (const float*)d_in[16];
    float* out = (float*)d_out;

    k_zerodeg<<<(NPAD + 255) / 256, 256>>>();
    k_init<<<512, 256>>>(ei);
    k_bnpre<<<10, 128>>>(bn_g, bn_b, bn_m, bn_v);
    k_pnorm<<<10, 128>>>(pool_p);

    for (int L = 0; L < 10; L++) {
        int n = NS[L], k = KS[L];
        int eb = L & 1;

        k_degzero<<<256, 256>>>(L, n, (unsigned)k, NT[L]);
        k_offsets<<<NT[L], 256>>>(n);

        if (L == 0)
            k_rank1<<<1024, 256>>>(x, W1, n);
        else
            k_gemm<false><<<(n + 127) / 128, 256>>>(Ws + (size_t)(L - 1) * D * D, n,
                                                    nullptr, 0, nullptr, nullptr);

        k_csrfill<<<512, 256>>>(L, eb);
        k_agg<<<(n * 32 + 255) / 256, 256>>>(n);

        if (L == 0)
            k_l0epi<<<(n * 32 + 255) / 256, 256>>>(x, V1, conv_b, prelu_a, pool_p, n);
        else
            k_gemm<true><<<(n + 127) / 128, 256>>>(Vs + (size_t)(L - 1) * D * D, n,
                                                   conv_b + (size_t)L * D, L, prelu_a,
                                                   pool_p + (size_t)L * D);

        int gN = (n + 255) / 256;
        k_histscan<0><<<gN, 256>>>(n);
        k_histscan<1><<<gN, 256>>>(n);
        k_histscan<2><<<gN, 256>>>(n);
        k_histscan<3><<<gN, 256>>>(n);
        k_select<<<gN, 256>>>(n);

        k_gatherremap<<<(k + 63) / 64, 128>>>(L, k, eb, 1.0f / (float)k);
    }

    k_mlpzero<<<5, 256>>>();
    k_lin1<<<dim3(5, 8), 256>>>(lin1_w);
    k_lin1act<<<5, 256>>>(lin1_b, prelu_a);
    k_lin2<<<1, 256>>>(lin2_w, lin2_b, prelu_a, out);

    (void)in_sizes; (void)n_in; (void)out_size;
}

// round 6
// speedup vs baseline: 2.5641x; 1.0938x over previous
#include <cuda_runtime.h>
#include <math.h>

#define D 128
#define E_TOTAL 640000
#define NMAX 40000
#define NPAD (NMAX + 1024)

static const int NS[10] = {40000,32000,25600,20480,16384,13108,10487,8390,6712,5370};
static const int KS[10] = {32000,25600,20480,16384,13108,10487,8390,6712,5370,4296};
static const int NT[10] = {40,32,25,20,16,13,11,9,7,6};  // (n+1023)/1024

// ---------------- device scratch ----------------
__device__ float g_h  [NMAX*D];
__device__ float g_h2 [NMAX*D];
__device__ float g_hw [NMAX*D];
__device__ float g_agg[NMAX*D];
__device__ float g_score[NMAX];
__device__ float g_dinv [NMAX];
__device__ __align__(16) int g_degi[NPAD];
__device__ int   g_remap[NMAX];
__device__ int   g_sel  [NMAX];
__device__ int   g_off  [NMAX+1];
__device__ int   g_cur  [NMAX];
__device__ int   g_csr  [E_TOTAL];
__device__ int2  g_edges[2][E_TOTAL];
__device__ int   g_ecnt[11];
__device__ int   g_tilesum[64];
__device__ int   g_tilepref[64];
__device__ unsigned g_hist[3][65536];
__device__ unsigned g_coarse[3][1024];
__device__ unsigned long long g_prefix;
__device__ unsigned g_kremain;
__device__ unsigned g_selcnt;
__device__ unsigned g_doneA;
__device__ unsigned g_doneB;
__device__ unsigned g_doneC;
__device__ unsigned g_umax[D];
__device__ float g_colsum[D];
__device__ float g_reads[2560];
__device__ float g_z1[1280];
__device__ float g_bnsc[10*D];
__device__ float g_bnsh[10*D];
__device__ float g_pnorm[10];

// ---------------- helpers ----------------
__device__ __forceinline__ unsigned fmap(float f) {
    unsigned b = __float_as_uint(f);
    return (b & 0x80000000u) ? ~b : (b | 0x80000000u);
}
__device__ __forceinline__ float funmap(unsigned u) {
    unsigned b = (u & 0x80000000u) ? (u ^ 0x80000000u) : ~u;
    return __uint_as_float(b);
}
// 48-bit key: score (32) | inverted index (16). larger == better; ties -> smaller index.
__device__ __forceinline__ unsigned long long make_key(float s, int i) {
    return (((unsigned long long)fmap(s)) << 16) | (unsigned)(0xFFFFu - (unsigned)i);
}

__device__ __forceinline__ void mma_tf32(float* c, const unsigned* a, unsigned b0, unsigned b1) {
    asm volatile(
        "mma.sync.aligned.m16n8k8.row.col.f32.tf32.tf32.f32 "
        "{%0,%1,%2,%3}, {%4,%5,%6,%7}, {%8,%9}, {%0,%1,%2,%3};\n"
        : "+f"(c[0]), "+f"(c[1]), "+f"(c[2]), "+f"(c[3])
        : "r"(a[0]), "r"(a[1]), "r"(a[2]), "r"(a[3]), "r"(b0), "r"(b1));
}

// ---------------- init ----------------
__global__ void k_zerodeg() {
    int gid = blockIdx.x * blockDim.x + threadIdx.x;
    if (gid < NPAD) g_degi[gid] = 0;
}

__global__ void k_init(const int* __restrict__ ei) {
    int gid = blockIdx.x * blockDim.x + threadIdx.x;
    int stride = gridDim.x * blockDim.x;
    for (int i = gid; i < E_TOTAL; i += stride) {
        int d = ei[E_TOTAL + i];
        g_edges[0][i] = make_int2(ei[i], d);
        atomicAdd(&g_degi[d], 1);
    }
    if (gid == 0) g_ecnt[0] = E_TOTAL;
}

// fused BN-const precompute + pool-vector norms: grid 10, block 128
__global__ void k_prep(const float* __restrict__ gamma, const float* __restrict__ beta,
                       const float* __restrict__ mean, const float* __restrict__ var,
                       const float* __restrict__ p) {
    int L = blockIdx.x;
    int t = threadIdx.x;
    int idx = L * 128 + t;
    float sc = gamma[idx] / sqrtf(var[idx] + 1e-5f);
    g_bnsc[idx] = sc;
    g_bnsh[idx] = beta[idx] - mean[idx] * sc;
    __shared__ float sm[128];
    float v = p[idx];
    sm[t] = v * v;
    __syncthreads();
    for (int s = 64; s > 0; s >>= 1) {
        if (t < s) sm[t] += sm[t + s];
        __syncthreads();
    }
    if (t == 0) g_pnorm[L] = sqrtf(sm[0]);
}

// ---------------- per-layer: zero scratch + tile degree sums + (last block) tile prefix ----------------
__global__ void __launch_bounds__(256) k_degzero(int L, int n, unsigned k, int ntiles) {
    int t = threadIdx.x;
    int gid = blockIdx.x * 256 + t;
    int stride = gridDim.x * 256;
    unsigned* h0 = &g_hist[0][0];
    for (int i = gid; i < 3 * 65536; i += stride) h0[i] = 0u;
    unsigned* c0 = &g_coarse[0][0];
    for (int i = gid; i < 3 * 1024; i += stride) c0[i] = 0u;
    for (int i = gid; i < n; i += stride) g_remap[i] = -1;
    if (gid < 128) { g_umax[gid] = 0u; g_colsum[gid] = 0.f; }
    if (gid == 0) { g_prefix = 0ull; g_kremain = k; g_selcnt = 0u; g_ecnt[L + 1] = 0; }

    if (blockIdx.x < ntiles) {
        int base = blockIdx.x * 1024 + t * 4;
        int4 dv = *(const int4*)&g_degi[base];
        int s = 0;
        if (base + 0 < n) s += dv.x;
        if (base + 1 < n) s += dv.y;
        if (base + 2 < n) s += dv.z;
        if (base + 3 < n) s += dv.w;
#pragma unroll
        for (int off = 16; off > 0; off >>= 1) s += __shfl_xor_sync(0xFFFFFFFFu, s, off);
        __shared__ int ws[8];
        if ((t & 31) == 0) ws[t >> 5] = s;
        __syncthreads();
        if (t == 0) {
            int tot = 0;
#pragma unroll
            for (int j = 0; j < 8; j++) tot += ws[j];
            g_tilesum[blockIdx.x] = tot;
        }
    }

    __threadfence();
    __shared__ int lastb;
    if (t == 0) {
        unsigned v = atomicAdd(&g_doneC, 1u);
        lastb = (v == gridDim.x - 1);
        if (lastb) g_doneC = 0u;
    }
    __syncthreads();
    if (!lastb) return;
    if (t == 0) {
        int run = 0;
        for (int i = 0; i < ntiles; i++) { g_tilepref[i] = run; run += g_tilesum[i]; }
        g_off[n] = run;
    }
}

__global__ void __launch_bounds__(256) k_offsets(int n) {
    int t = threadIdx.x;
    int base = blockIdx.x * 1024 + t * 4;
    int4 dv = *(const int4*)&g_degi[base];
    int d0 = (base + 0 < n) ? dv.x : 0;
    int d1 = (base + 1 < n) ? dv.y : 0;
    int d2 = (base + 2 < n) ? dv.z : 0;
    int d3 = (base + 3 < n) ? dv.w : 0;
    int s = d0 + d1 + d2 + d3;
    int lane = t & 31, wid = t >> 5;
    int incl = s;
#pragma unroll
    for (int off = 1; off < 32; off <<= 1) {
        int v = __shfl_up_sync(0xFFFFFFFFu, incl, off);
        if (lane >= off) incl += v;
    }
    __shared__ int wsum[8], wpref[8];
    if (lane == 31) wsum[wid] = incl;
    __syncthreads();
    if (t < 8) {
        int p = 0;
#pragma unroll
        for (int j = 0; j < 8; j++) {
            int u = wsum[j];
            if (j < t) p += u;
        }
        wpref[t] = p;
    }
    __syncthreads();
    int excl = incl - s + wpref[wid] + g_tilepref[blockIdx.x];
    int dd[4] = {d0, d1, d2, d3};
#pragma unroll
    for (int j = 0; j < 4; j++) {
        int idx = base + j;
        if (idx < n) {
            g_off[idx] = excl;
            g_cur[idx] = excl;
            g_dinv[idx] = (dd[j] > 0) ? (1.0f / sqrtf((float)dd[j])) : 0.f;
            excl += dd[j];
        }
    }
}

// layer 0: hw = x * W1
__global__ void k_rank1(const float* __restrict__ x, const float* __restrict__ w, int n) {
    int gid = blockIdx.x * blockDim.x + threadIdx.x;
    int stride = gridDim.x * blockDim.x;
    const float4* w4 = (const float4*)w;
    float4* o4 = (float4*)g_hw;
    for (int i = gid; i < n * 32; i += stride) {
        float xv = x[i >> 5];
        float4 wv = w4[i & 31];
        o4[i] = make_float4(xv * wv.x, xv * wv.y, xv * wv.z, xv * wv.w);
    }
}

__global__ void k_csrfill(int L, int ebuf) {
    int gid = blockIdx.x * blockDim.x + threadIdx.x;
    int stride = gridDim.x * blockDim.x;
    int cnt = g_ecnt[L];
    const int2* E = g_edges[ebuf];
    for (int i = gid; i < cnt; i += stride) {
        int2 e = E[i];
        int pos = atomicAdd(&g_cur[e.y], 1);
        g_csr[pos] = e.x;
    }
}

__global__ void k_agg(int n) {
    int gid = blockIdx.x * blockDim.x + threadIdx.x;
    int node = gid >> 5;
    int lane = gid & 31;
    if (node >= n) return;
    int st = g_off[node], en = g_off[node + 1];
    float dd = g_dinv[node];
    float4 acc = make_float4(0.f, 0.f, 0.f, 0.f);
    const float4* hw4 = (const float4*)g_hw;
    for (int j = st; j < en; j++) {
        int s = g_csr[j];
        float c = g_dinv[s] * dd;
        float4 v = hw4[(size_t)s * 32 + lane];
        acc.x += v.x * c; acc.y += v.y * c; acc.z += v.z * c; acc.w += v.w * c;
    }
    ((float4*)g_agg)[(size_t)node * 32 + lane] = acc;
}

// layer 0 epilogue + score
__global__ void k_l0epi(const float* __restrict__ x, const float* __restrict__ V1,
                        const float* __restrict__ convb, const float* __restrict__ pa,
                        const float* __restrict__ p, int n) {
    int gid = blockIdx.x * blockDim.x + threadIdx.x;
    int r = gid >> 5;
    int lane = gid & 31;
    if (r >= n) return;
    float a = pa[0];
    float xr = x[r];
    float4 ag = ((const float4*)g_agg)[(size_t)r * 32 + lane];
    float4 vv = ((const float4*)V1)[lane];
    float4 cb = ((const float4*)convb)[lane];
    float4 s4 = ((const float4*)g_bnsc)[lane];
    float4 h4 = ((const float4*)g_bnsh)[lane];
    float4 p4 = ((const float4*)p)[lane];
    float o[4];
    o[0] = xr * vv.x + ag.x + cb.x;
    o[1] = xr * vv.y + ag.y + cb.y;
    o[2] = xr * vv.z + ag.z + cb.z;
    o[3] = xr * vv.w + ag.w + cb.w;
    float bs[4] = {s4.x, s4.y, s4.z, s4.w};
    float bh[4] = {h4.x, h4.y, h4.z, h4.w};
    float pv[4] = {p4.x, p4.y, p4.z, p4.w};
    float sp = 0.f;
#pragma unroll
    for (int j = 0; j < 4; j++) {
        float v = fmaxf(o[j], 0.f);
        v = v * bs[j] + bh[j];
        v = v > 0.f ? v : a * v;
        o[j] = v;
        sp += v * pv[j];
    }
    ((float4*)g_h2)[(size_t)r * 32 + lane] = make_float4(o[0], o[1], o[2], o[3]);
#pragma unroll
    for (int off = 16; off > 0; off >>= 1) sp += __shfl_xor_sync(0xFFFFFFFFu, sp, off);
    if (lane == 0) g_score[r] = tanhf(sp / g_pnorm[0]);
}

// ---------------- TF32 tensor-core GEMM: C(n x 128) = g_h @ B, 3xTF32 split ----------------
// Block 128x128, 8 warps (2x4), warp tile 64x32, mma m16n8k8.
#define GBK 16
template <bool EPI>
__global__ void __launch_bounds__(256) k_gemm(const float* __restrict__ B, int n,
                                              const float* __restrict__ convbL, int L,
                                              const float* __restrict__ pa,
                                              const float* __restrict__ pL) {
    __shared__ float Ah[GBK][136], Al[GBK][136];
    __shared__ float Bh[GBK][136], Bl[GBK][136];
    __shared__ float Ssc[128][5];
    int tid = threadIdx.x;
    int lane = tid & 31;
    int warp = tid >> 5;
    int wm = warp >> 2;     // 0..1
    int wn = warp & 3;      // 0..3
    int group = lane >> 2;  // 0..7
    int tig = lane & 3;     // 0..3
    int row0 = blockIdx.x * 128;

    float acc[4][4][4];
#pragma unroll
    for (int mt = 0; mt < 4; mt++)
#pragma unroll
        for (int nt = 0; nt < 4; nt++)
#pragma unroll
            for (int e = 0; e < 4; e++) acc[mt][nt][e] = 0.f;

    for (int k0 = 0; k0 < 128; k0 += GBK) {
        // stage A (128 x GBK), transposed into [k][m], split hi/lo
#pragma unroll
        for (int q = 0; q < 2; q++) {
            int f = tid + 256 * q;
            int m = f >> 2;
            int kq = (f & 3) * 4;
            int gr = row0 + m; if (gr >= n) gr = n - 1;
            float4 v = *(const float4*)(g_h + (size_t)gr * 128 + k0 + kq);
            float xs[4] = {v.x, v.y, v.z, v.w};
#pragma unroll
            for (int j = 0; j < 4; j++) {
                float xv = xs[j];
                float hf = __uint_as_float(__float_as_uint(xv) & 0xFFFFE000u);
                Ah[kq + j][m] = hf;
                Al[kq + j][m] = xv - hf;
            }
        }
        // stage B (GBK x 128), split hi/lo
#pragma unroll
        for (int q = 0; q < 2; q++) {
            int f = tid + 256 * q;
            int kk = f >> 5;
            int nq = (f & 31) * 4;
            float4 v = *(const float4*)(B + (size_t)(k0 + kk) * 128 + nq);
            float xs[4] = {v.x, v.y, v.z, v.w};
            float hi[4], lo[4];
#pragma unroll
            for (int j = 0; j < 4; j++) {
                hi[j] = __uint_as_float(__float_as_uint(xs[j]) & 0xFFFFE000u);
                lo[j] = xs[j] - hi[j];
            }
            *(float4*)&Bh[kk][nq] = make_float4(hi[0], hi[1], hi[2], hi[3]);
            *(float4*)&Bl[kk][nq] = make_float4(lo[0], lo[1], lo[2], lo[3]);
        }
        __syncthreads();
#pragma unroll
        for (int ks = 0; ks < GBK; ks += 8) {
            unsigned ah[4][4], al[4][4];
#pragma unroll
            for (int mt = 0; mt < 4; mt++) {
                int m = wm * 64 + mt * 16 + group;
                ah[mt][0] = __float_as_uint(Ah[ks + tig][m]);
                ah[mt][1] = __float_as_uint(Ah[ks + tig][m + 8]);
                ah[mt][2] = __float_as_uint(Ah[ks + tig + 4][m]);
                ah[mt][3] = __float_as_uint(Ah[ks + tig + 4][m + 8]);
                al[mt][0] = __float_as_uint(Al[ks + tig][m]);
                al[mt][1] = __float_as_uint(Al[ks + tig][m + 8]);
                al[mt][2] = __float_as_uint(Al[ks + tig + 4][m]);
                al[mt][3] = __float_as_uint(Al[ks + tig + 4][m + 8]);
            }
#pragma unroll
            for (int nt = 0; nt < 4; nt++) {
                int c = wn * 32 + nt * 8 + group;
                unsigned bh0 = __float_as_uint(Bh[ks + tig][c]);
                unsigned bh1 = __float_as_uint(Bh[ks + tig + 4][c]);
                unsigned bl0 = __float_as_uint(Bl[ks + tig][c]);
                unsigned bl1 = __float_as_uint(Bl[ks + tig + 4][c]);
#pragma unroll
                for (int mt = 0; mt < 4; mt++) {
                    mma_tf32(acc[mt][nt], ah[mt], bh0, bh1);
                    mma_tf32(acc[mt][nt], ah[mt], bl0, bl1);
                    mma_tf32(acc[mt][nt], al[mt], bh0, bh1);
                }
            }
        }
        __syncthreads();
    }

    if (!EPI) {
#pragma unroll
        for (int mt = 0; mt < 4; mt++) {
#pragma unroll
            for (int h = 0; h < 2; h++) {
                int r = row0 + wm * 64 + mt * 16 + group + 8 * h;
                if (r >= n) continue;
#pragma unroll
                for (int nt = 0; nt < 4; nt++) {
                    int cb = wn * 32 + nt * 8 + tig * 2;
                    *(float2*)(g_hw + (size_t)r * 128 + cb) =
                        make_float2(acc[mt][nt][2 * h], acc[mt][nt][2 * h + 1]);
                }
            }
        }
    } else {
        float aP = pa[0];
        float pn = g_pnorm[L];
        float pv[8], bs8[8], bh8[8], cb8[8];
#pragma unroll
        for (int nt = 0; nt < 4; nt++) {
#pragma unroll
            for (int e = 0; e < 2; e++) {
                int c = wn * 32 + nt * 8 + tig * 2 + e;
                pv[nt * 2 + e] = pL[c];
                bs8[nt * 2 + e] = g_bnsc[L * 128 + c];
                bh8[nt * 2 + e] = g_bnsh[L * 128 + c];
                cb8[nt * 2 + e] = convbL[c];
            }
        }
#pragma unroll
        for (int mt = 0; mt < 4; mt++) {
#pragma unroll
            for (int h = 0; h < 2; h++) {
                int rloc = wm * 64 + mt * 16 + group + 8 * h;
                int r = row0 + rloc;
                const float2* agr = (const float2*)(g_agg + (size_t)r * 128);
                float sp = 0.f;
                float2 outv[4];
#pragma unroll
                for (int nt = 0; nt < 4; nt++) {
                    int cb = wn * 32 + nt * 8 + tig * 2;
                    float2 ag = agr[cb >> 1];
                    float v0 = acc[mt][nt][2 * h] + ag.x + cb8[nt * 2];
                    float v1 = acc[mt][nt][2 * h + 1] + ag.y + cb8[nt * 2 + 1];
                    v0 = fmaxf(v0, 0.f) * bs8[nt * 2] + bh8[nt * 2];
                    v1 = fmaxf(v1, 0.f) * bs8[nt * 2 + 1] + bh8[nt * 2 + 1];
                    v0 = v0 > 0.f ? v0 : aP * v0;
                    v1 = v1 > 0.f ? v1 : aP * v1;
                    sp += v0 * pv[nt * 2] + v1 * pv[nt * 2 + 1];
                    outv[nt] = make_float2(v0, v1);
                }
                if (r < n) {
#pragma unroll
                    for (int nt = 0; nt < 4; nt++) {
                        int cb = wn * 32 + nt * 8 + tig * 2;
                        *(float2*)(g_h2 + (size_t)r * 128 + cb) = outv[nt];
                    }
                }
                sp += __shfl_xor_sync(0xFFFFFFFFu, sp, 1);
                sp += __shfl_xor_sync(0xFFFFFFFFu, sp, 2);
                if (tig == 0) Ssc[rloc][wn] = sp;
            }
        }
        __syncthreads();
        if (tid < 128) {
            int r = row0 + tid;
            if (r < n) {
                float s = Ssc[tid][0] + Ssc[tid][1] + Ssc[tid][2] + Ssc[tid][3];
                g_score[r] = tanhf(s / pn);
            }
        }
    }
}

// ---------------- top-k: 3 x 16-bit radix passes over 48-bit keys ----------------
template <int PASS>
__global__ void __launch_bounds__(256) k_histscan(int n) {
    int i = blockIdx.x * 256 + threadIdx.x;
    if (i < n) {
        unsigned long long key = make_key(g_score[i], i);
        bool act = true;
        if (PASS > 0) {
            const int hs = 48 - 16 * PASS;
            act = ((key >> hs) == (g_prefix >> hs));
        }
        if (act) {
            unsigned digit = (unsigned)((key >> (32 - 16 * PASS)) & 0xFFFFull);
            atomicAdd(&g_hist[PASS][digit], 1u);
            atomicAdd(&g_coarse[PASS][digit >> 6], 1u);
        }
    }
    __threadfence();
    __shared__ int lastb;
    if (threadIdx.x == 0) {
        unsigned v = atomicAdd(&g_doneA, 1u);
        lastb = (v == gridDim.x - 1);
        if (lastb) g_doneA = 0u;
    }
    __syncthreads();
    if (!lastb) return;

    int t = threadIdx.x;
    unsigned kr = g_kremain;
    int cb0 = t * 4;
    unsigned s = 0;
#pragma unroll
    for (int q = 0; q < 4; q++) s += g_coarse[PASS][cb0 + q];
    __shared__ unsigned arr[256];
    arr[t] = s;
    __syncthreads();
    __shared__ unsigned rev[256];
    rev[t] = arr[255 - t];
    __syncthreads();
    for (int off = 1; off < 256; off <<= 1) {
        unsigned v = (t >= off) ? rev[t - off] : 0u;
        __syncthreads();
        rev[t] += v;
        __syncthreads();
    }
    unsigned suf = rev[255 - t];
    unsigned above = suf - s;
    if (above < kr && suf >= kr) {
        unsigned running = above;
        for (int b = 3; b >= 0; b--) {
            unsigned c = g_coarse[PASS][cb0 + b];
            if (running + c >= kr) {
                int fb = (cb0 + b) * 64;
                for (int d = 63; d >= 0; d--) {
                    unsigned fc = g_hist[PASS][fb + d];
                    if (running + fc >= kr) {
                        g_kremain = kr - running;
                        g_prefix |= ((unsigned long long)(unsigned)(fb + d)) << (32 - 16 * PASS);
                        break;
                    }
                    running += fc;
                }
                break;
            }
            running += c;
        }
    }
}

__global__ void k_select(int n) {
    int i = blockIdx.x * blockDim.x + threadIdx.x;
    if (i >= n) return;
    g_degi[i] = 0;  // degrees consumed; clear for next layer
    unsigned long long key = make_key(g_score[i], i);
    if (key >= g_prefix) {
        unsigned pos = atomicAdd(&g_selcnt, 1u);
        g_sel[pos] = i;
        g_remap[i] = (int)pos;
    }
}

__global__ void __launch_bounds__(128) k_gatherremap(int L, int k, int ebuf, float invk) {
    int c = threadIdx.x;
    int r0 = blockIdx.x * 64;
    float lmax = __int_as_float(0xff800000);
    float lsum = 0.f;
    int rend = r0 + 64; if (rend > k) rend = k;
    for (int r = r0; r < rend; r++) {
        int i = g_sel[r];
        float v = g_h2[(size_t)i * 128 + c] * g_score[i];
        g_h[(size_t)r * 128 + c] = v;
        lmax = fmaxf(lmax, v);
        lsum += v;
    }
    atomicMax(&g_umax[c], fmap(lmax));
    atomicAdd(&g_colsum[c], lsum);

    int cnt = g_ecnt[L];
    const int2* Ein = g_edges[ebuf];
    int2* Eout = g_edges[ebuf ^ 1];
    for (int i = blockIdx.x * 128 + c; i < cnt; i += gridDim.x * 128) {
        int2 e = Ein[i];
        int ns = g_remap[e.x];
        int nd = g_remap[e.y];
        if (ns >= 0 && nd >= 0) {
            int pos = atomicAdd(&g_ecnt[L + 1], 1);
            Eout[pos] = make_int2(ns, nd);
            atomicAdd(&g_degi[nd], 1);
        }
    }

    __threadfence();
    __shared__ int lastb;
    if (c == 0) {
        unsigned v = atomicAdd(&g_doneB, 1u);
        lastb = (v == gridDim.x - 1);
        if (lastb) g_doneB = 0u;
    }
    __syncthreads();
    if (lastb) {
        g_reads[L * 256 + c] = funmap(g_umax[c]);
        g_reads[L * 256 + 128 + c] = g_colsum[c] * invk;
    }
}

// ---------------- MLP head ----------------
__global__ void k_mlpzero() {
    int i = blockIdx.x * blockDim.x + threadIdx.x;
    if (i < 1280) g_z1[i] = 0.f;
}

__global__ void k_lin1(const float* __restrict__ W) {
    int col = blockIdx.x * 256 + threadIdx.x;
    int r0 = blockIdx.y * 320;
    float acc = 0.f;
    for (int r = r0; r < r0 + 320; r++) acc += g_reads[r] * W[(size_t)r * 1280 + col];
    atomicAdd(&g_z1[col], acc);
}

__global__ void k_lin1act(const float* __restrict__ b, const float* __restrict__ pa) {
    int i = blockIdx.x * 256 + threadIdx.x;
    if (i >= 1280) return;
    float a = pa[0];
    float z = g_z1[i] + b[i];
    g_z1[i] = z > 0.f ? z : a * z;
}

__global__ void k_lin2(const float* __restrict__ W2, const float* __restrict__ b2,
                       const float* __restrict__ pa, float* __restrict__ out) {
    int tid = threadIdx.x;
    float acc[8] = {0, 0, 0, 0, 0, 0, 0, 0};
    for (int i = tid; i < 1280; i += 256) {
        float v = g_z1[i];
#pragma unroll
        for (int j = 0; j < 8; j++) acc[j] += v * W2[i * 8 + j];
    }
    __shared__ float red[256][8];
#pragma unroll
    for (int j = 0; j < 8; j++) red[tid][j] = acc[j];
    __syncthreads();
    for (int s = 128; s > 0; s >>= 1) {
        if (tid < s)
#pragma unroll
            for (int j = 0; j < 8; j++) red[tid][j] += red[tid + s][j];
        __syncthreads();
    }
    if (tid == 0) {
        float a = pa[0];
        float z[8];
#pragma unroll
        for (int j = 0; j < 8; j++) {
            float s = red[0][j] + b2[j];
            z[j] = s > 0.f ? s : a * s;
        }
        float mn = z[0];
#pragma unroll
        for (int j = 1; j < 8; j++) mn = fminf(mn, z[j]);
#pragma unroll
        for (int j = 0; j < 8; j++) z[j] -= mn;
        float mx = z[0];
#pragma unroll
        for (int j = 1; j < 8; j++) mx = fmaxf(mx, z[j]);
#pragma unroll
        for (int j = 0; j < 8; j++) z[j] /= mx;
        float sm = 0.f;
#pragma unroll
        for (int j = 0; j < 8; j++) sm += z[j];
#pragma unroll
        for (int j = 0; j < 8; j++) out[j] = z[j] / sm;
    }
}

// ---------------- launcher ----------------
extern "C" void kernel_launch(void* const* d_in, const int* in_sizes, int n_in,
                              void* d_out, int out_size) {
    const float* x       = (const float*)d_in[0];
    const int*   ei      = (const int*)  d_in[1];
    const float* W1      = (const float*)d_in[2];
    const float* V1      = (const float*)d_in[3];
    const float* Ws      = (const float*)d_in[4];
    const float* Vs      = (const float*)d_in[5];
    const float* conv_b  = (const float*)d_in[6];
    const float* bn_g    = (const float*)d_in[7];
    const float* bn_b    = (const float*)d_in[8];
    const float* bn_m    = (const float*)d_in[9];
    const float* bn_v    = (const float*)d_in[10];
    const float* pool_p  = (const float*)d_in[11];
    const float* prelu_a = (const float*)d_in[12];
    const float* lin1_w  = (const float*)d_in[13];
    const float* lin1_b  = (const float*)d_in[14];
    const float* lin2_w  = (const float*)d_in[15];
    const float* lin2_b  = (const float*)d_in[16];
    float* out = (float*)d_out;

    k_zerodeg<<<(NPAD + 255) / 256, 256>>>();
    k_init<<<512, 256>>>(ei);
    k_prep<<<10, 128>>>(bn_g, bn_b, bn_m, bn_v, pool_p);

    for (int L = 0; L < 10; L++) {
        int n = NS[L], k = KS[L];
        int eb = L & 1;

        k_degzero<<<256, 256>>>(L, n, (unsigned)k, NT[L]);
        k_offsets<<<NT[L], 256>>>(n);

        if (L == 0)
            k_rank1<<<1024, 256>>>(x, W1, n);
        else
            k_gemm<false><<<(n + 127) / 128, 256>>>(Ws + (size_t)(L - 1) * D * D, n,
                                                    nullptr, 0, nullptr, nullptr);

        k_csrfill<<<512, 256>>>(L, eb);
        k_agg<<<(n * 32 + 255) / 256, 256>>>(n);

        if (L == 0)
            k_l0epi<<<(n * 32 + 255) / 256, 256>>>(x, V1, conv_b, prelu_a, pool_p, n);
        else
            k_gemm<true><<<(n + 127) / 128, 256>>>(Vs + (size_t)(L - 1) * D * D, n,
                                                   conv_b + (size_t)L * D, L, prelu_a,
                                                   pool_p + (size_t)L * D);

        int gN = (n + 255) / 256;
        k_histscan<0><<<gN, 256>>>(n);
        k_histscan<1><<<gN, 256>>>(n);
        k_histscan<2><<<gN, 256>>>(n);
        k_select<<<gN, 256>>>(n);

        k_gatherremap<<<(k + 63) / 64, 128>>>(L, k, eb, 1.0f / (float)k);
    }

    k_mlpzero<<<5, 256>>>();
    k_lin1<<<dim3(5, 8), 256>>>(lin1_w);
    k_lin1act<<<5, 256>>>(lin1_b, prelu_a);
    k_lin2<<<1, 256>>>(lin2_w, lin2_b, prelu_a, out);

    (void)in_sizes; (void)n_in; (void)out_size;
}

// round 7
// speedup vs baseline: 2.6426x; 1.0306x over previous
#include <cuda_runtime.h>
#include <math.h>

#define D 128
#define E_TOTAL 640000
#define NMAX 40000
#define NPAD (NMAX + 1024)

static const int NS[10] = {40000,32000,25600,20480,16384,13108,10487,8390,6712,5370};
static const int KS[10] = {32000,25600,20480,16384,13108,10487,8390,6712,5370,4296};
static const int NT[10] = {40,32,25,20,16,13,11,9,7,6};  // (n+1023)/1024

// ---------------- device scratch ----------------
__device__ float g_h  [NMAX*D];
__device__ float g_h2 [NMAX*D];
__device__ float g_hw [NMAX*D];
__device__ float g_agg[NMAX*D];
__device__ float g_score[NMAX];
__device__ float g_dinv [NMAX];
__device__ __align__(16) int g_degi[NPAD];
__device__ int   g_remap[NMAX];
__device__ int   g_sel  [NMAX];
__device__ int   g_off  [NMAX+1];
__device__ int   g_cur  [NMAX];
__device__ int   g_csr  [E_TOTAL];
__device__ int2  g_edges[2][E_TOTAL];
__device__ int   g_ecnt[11];
__device__ int   g_tilesum[64];
__device__ unsigned g_hist[3][65536];
__device__ unsigned g_coarse[3][1024];
__device__ unsigned g_selcnt;
__device__ unsigned g_doneB;
__device__ unsigned g_barArr;
__device__ volatile unsigned g_barGen;
__device__ unsigned g_umax[D];
__device__ float g_colsum[D];
__device__ float g_reads[2560];
__device__ float g_z1[1280];
__device__ float g_bnsc[10*D];
__device__ float g_bnsh[10*D];
__device__ float g_pnorm[10];

// ---------------- helpers ----------------
__device__ __forceinline__ unsigned fmap(float f) {
    unsigned b = __float_as_uint(f);
    return (b & 0x80000000u) ? ~b : (b | 0x80000000u);
}
__device__ __forceinline__ float funmap(unsigned u) {
    unsigned b = (u & 0x80000000u) ? (u ^ 0x80000000u) : ~u;
    return __uint_as_float(b);
}
// 48-bit key: score (32) | inverted index (16). larger == better; ties -> smaller index.
__device__ __forceinline__ unsigned long long make_key(float s, int i) {
    return (((unsigned long long)fmap(s)) << 16) | (unsigned)(0xFFFFu - (unsigned)i);
}

__device__ __forceinline__ void mma_tf32(float* c, const unsigned* a, unsigned b0, unsigned b1) {
    asm volatile(
        "mma.sync.aligned.m16n8k8.row.col.f32.tf32.tf32.f32 "
        "{%0,%1,%2,%3}, {%4,%5,%6,%7}, {%8,%9}, {%0,%1,%2,%3};\n"
        : "+f"(c[0]), "+f"(c[1]), "+f"(c[2]), "+f"(c[3])
        : "r"(a[0]), "r"(a[1]), "r"(a[2]), "r"(a[3]), "r"(b0), "r"(b1));
}

// grid barrier: safe only when ALL nb blocks are resident (single wave).
// All arrivals happen before release, so the generation scheme is race-free.
__device__ __forceinline__ void gridbar(unsigned nb) {
    __syncthreads();
    if (threadIdx.x == 0) {
        __threadfence();
        unsigned gen = g_barGen;
        if (atomicAdd(&g_barArr, 1u) == nb - 1) {
            g_barArr = 0;
            __threadfence();
            g_barGen = gen + 1;
        } else {
            while (g_barGen == gen) __nanosleep(64);
            __threadfence();
        }
    }
    __syncthreads();
}

// ---------------- init ----------------
__global__ void k_zerodeg() {
    int gid = blockIdx.x * blockDim.x + threadIdx.x;
    if (gid < NPAD) g_degi[gid] = 0;
}

__global__ void k_init(const int* __restrict__ ei) {
    int gid = blockIdx.x * blockDim.x + threadIdx.x;
    int stride = gridDim.x * blockDim.x;
    for (int i = gid; i < E_TOTAL; i += stride) {
        int d = ei[E_TOTAL + i];
        g_edges[0][i] = make_int2(ei[i], d);
        atomicAdd(&g_degi[d], 1);
    }
    if (gid == 0) g_ecnt[0] = E_TOTAL;
}

// fused BN-const precompute + pool-vector norms + z1 zero: grid 10, block 128
__global__ void k_prep(const float* __restrict__ gamma, const float* __restrict__ beta,
                       const float* __restrict__ mean, const float* __restrict__ var,
                       const float* __restrict__ p) {
    int L = blockIdx.x;
    int t = threadIdx.x;
    int idx = L * 128 + t;
    float sc = gamma[idx] / sqrtf(var[idx] + 1e-5f);
    g_bnsc[idx] = sc;
    g_bnsh[idx] = beta[idx] - mean[idx] * sc;
    g_z1[idx] = 0.f;
    g_z1[idx + 1280 - 1280] = g_z1[idx];  // no-op keep
    __shared__ float sm[128];
    float v = p[idx];
    sm[t] = v * v;
    __syncthreads();
    for (int s = 64; s > 0; s >>= 1) {
        if (t < s) sm[t] += sm[t + s];
        __syncthreads();
    }
    if (t == 0) g_pnorm[L] = sqrtf(sm[0]);
}

// ---------------- fused per-layer prep: zero scratch + tile sums | offsets | csrfill ----------------
#define PREP_NB 256
__global__ void __launch_bounds__(256) k_prep_layer(int L, int n, int ntiles, int ebuf) {
    int t = threadIdx.x;
    int bid = blockIdx.x;
    int gid = bid * 256 + t;
    const int stride = PREP_NB * 256;

    // ---- phase 1: zeroing + per-tile degree sums ----
    unsigned* h0 = &g_hist[0][0];
    for (int i = gid; i < 3 * 65536; i += stride) h0[i] = 0u;
    unsigned* c0 = &g_coarse[0][0];
    for (int i = gid; i < 3 * 1024; i += stride) c0[i] = 0u;
    for (int i = gid; i < n; i += stride) g_remap[i] = -1;
    if (gid < 128) { g_umax[gid] = 0u; g_colsum[gid] = 0.f; }
    if (gid == 0) { g_selcnt = 0u; g_ecnt[L + 1] = 0; }

    if (bid < ntiles) {
        int base = bid * 1024 + t * 4;
        int4 dv = *(const int4*)&g_degi[base];
        int s = 0;
        if (base + 0 < n) s += dv.x;
        if (base + 1 < n) s += dv.y;
        if (base + 2 < n) s += dv.z;
        if (base + 3 < n) s += dv.w;
#pragma unroll
        for (int off = 16; off > 0; off >>= 1) s += __shfl_xor_sync(0xFFFFFFFFu, s, off);
        __shared__ int ws[8];
        if ((t & 31) == 0) ws[t >> 5] = s;
        __syncthreads();
        if (t == 0) {
            int tot = 0;
#pragma unroll
            for (int j = 0; j < 8; j++) tot += ws[j];
            g_tilesum[bid] = tot;
        }
    }

    gridbar(PREP_NB);

    // ---- phase 2: offsets expansion (blocks < ntiles), redundant tile prefix ----
    if (bid < ntiles) {
        int pref = 0;
        for (int j = 0; j < bid; j++) pref += g_tilesum[j];
        if (bid == ntiles - 1 && t == 0) g_off[n] = pref + g_tilesum[bid];

        int base = bid * 1024 + t * 4;
        int4 dv = *(const int4*)&g_degi[base];
        int d0 = (base + 0 < n) ? dv.x : 0;
        int d1 = (base + 1 < n) ? dv.y : 0;
        int d2 = (base + 2 < n) ? dv.z : 0;
        int d3 = (base + 3 < n) ? dv.w : 0;
        int s = d0 + d1 + d2 + d3;
        int lane = t & 31, wid = t >> 5;
        int incl = s;
#pragma unroll
        for (int off = 1; off < 32; off <<= 1) {
            int v = __shfl_up_sync(0xFFFFFFFFu, incl, off);
            if (lane >= off) incl += v;
        }
        __shared__ int wsum[8], wpref[8];
        if (lane == 31) wsum[wid] = incl;
        __syncthreads();
        if (t < 8) {
            int pp = 0;
#pragma unroll
            for (int j = 0; j < 8; j++) {
                int u = wsum[j];
                if (j < t) pp += u;
            }
            wpref[t] = pp;
        }
        __syncthreads();
        int excl = incl - s + wpref[wid] + pref;
        int dd[4] = {d0, d1, d2, d3};
#pragma unroll
        for (int j = 0; j < 4; j++) {
            int idx = base + j;
            if (idx < n) {
                g_off[idx] = excl;
                g_cur[idx] = excl;
                g_dinv[idx] = (dd[j] > 0) ? (1.0f / sqrtf((float)dd[j])) : 0.f;
                excl += dd[j];
            }
        }
    }

    gridbar(PREP_NB);

    // ---- phase 3: CSR fill ----
    int cnt = g_ecnt[L];
    const int2* E = g_edges[ebuf];
    for (int i = gid; i < cnt; i += stride) {
        int2 e = E[i];
        int pos = atomicAdd(&g_cur[e.y], 1);
        g_csr[pos] = e.x;
    }
}

// layer 0: hw = x * W1
__global__ void k_rank1(const float* __restrict__ x, const float* __restrict__ w, int n) {
    int gid = blockIdx.x * blockDim.x + threadIdx.x;
    int stride = gridDim.x * blockDim.x;
    const float4* w4 = (const float4*)w;
    float4* o4 = (float4*)g_hw;
    for (int i = gid; i < n * 32; i += stride) {
        float xv = x[i >> 5];
        float4 wv = w4[i & 31];
        o4[i] = make_float4(xv * wv.x, xv * wv.y, xv * wv.z, xv * wv.w);
    }
}

__global__ void k_agg(int n) {
    int gid = blockIdx.x * blockDim.x + threadIdx.x;
    int node = gid >> 5;
    int lane = gid & 31;
    if (node >= n) return;
    int st = g_off[node], en = g_off[node + 1];
    float dd = g_dinv[node];
    float4 acc = make_float4(0.f, 0.f, 0.f, 0.f);
    const float4* hw4 = (const float4*)g_hw;
    for (int j = st; j < en; j++) {
        int s = g_csr[j];
        float c = g_dinv[s] * dd;
        float4 v = hw4[(size_t)s * 32 + lane];
        acc.x += v.x * c; acc.y += v.y * c; acc.z += v.z * c; acc.w += v.w * c;
    }
    ((float4*)g_agg)[(size_t)node * 32 + lane] = acc;
}

// layer 0 epilogue + score
__global__ void k_l0epi(const float* __restrict__ x, const float* __restrict__ V1,
                        const float* __restrict__ convb, const float* __restrict__ pa,
                        const float* __restrict__ p, int n) {
    int gid = blockIdx.x * blockDim.x + threadIdx.x;
    int r = gid >> 5;
    int lane = gid & 31;
    if (r >= n) return;
    float a = pa[0];
    float xr = x[r];
    float4 ag = ((const float4*)g_agg)[(size_t)r * 32 + lane];
    float4 vv = ((const float4*)V1)[lane];
    float4 cb = ((const float4*)convb)[lane];
    float4 s4 = ((const float4*)g_bnsc)[lane];
    float4 h4 = ((const float4*)g_bnsh)[lane];
    float4 p4 = ((const float4*)p)[lane];
    float o[4];
    o[0] = xr * vv.x + ag.x + cb.x;
    o[1] = xr * vv.y + ag.y + cb.y;
    o[2] = xr * vv.z + ag.z + cb.z;
    o[3] = xr * vv.w + ag.w + cb.w;
    float bs[4] = {s4.x, s4.y, s4.z, s4.w};
    float bh[4] = {h4.x, h4.y, h4.z, h4.w};
    float pv[4] = {p4.x, p4.y, p4.z, p4.w};
    float sp = 0.f;
#pragma unroll
    for (int j = 0; j < 4; j++) {
        float v = fmaxf(o[j], 0.f);
        v = v * bs[j] + bh[j];
        v = v > 0.f ? v : a * v;
        o[j] = v;
        sp += v * pv[j];
    }
    ((float4*)g_h2)[(size_t)r * 32 + lane] = make_float4(o[0], o[1], o[2], o[3]);
#pragma unroll
    for (int off = 16; off > 0; off >>= 1) sp += __shfl_xor_sync(0xFFFFFFFFu, sp, off);
    if (lane == 0) g_score[r] = tanhf(sp / g_pnorm[0]);
}

// ---------------- TF32 tensor-core GEMM: C(n x 128) = g_h @ B, 3xTF32 split ----------------
#define GBK 16
template <bool EPI>
__global__ void __launch_bounds__(256) k_gemm(const float* __restrict__ B, int n,
                                              const float* __restrict__ convbL, int L,
                                              const float* __restrict__ pa,
                                              const float* __restrict__ pL) {
    __shared__ float Ah[GBK][136], Al[GBK][136];
    __shared__ float Bh[GBK][136], Bl[GBK][136];
    __shared__ float Ssc[128][5];
    int tid = threadIdx.x;
    int lane = tid & 31;
    int warp = tid >> 5;
    int wm = warp >> 2;
    int wn = warp & 3;
    int group = lane >> 2;
    int tig = lane & 3;
    int row0 = blockIdx.x * 128;

    float acc[4][4][4];
#pragma unroll
    for (int mt = 0; mt < 4; mt++)
#pragma unroll
        for (int nt = 0; nt < 4; nt++)
#pragma unroll
            for (int e = 0; e < 4; e++) acc[mt][nt][e] = 0.f;

    for (int k0 = 0; k0 < 128; k0 += GBK) {
#pragma unroll
        for (int q = 0; q < 2; q++) {
            int f = tid + 256 * q;
            int m = f >> 2;
            int kq = (f & 3) * 4;
            int gr = row0 + m; if (gr >= n) gr = n - 1;
            float4 v = *(const float4*)(g_h + (size_t)gr * 128 + k0 + kq);
            float xs[4] = {v.x, v.y, v.z, v.w};
#pragma unroll
            for (int j = 0; j < 4; j++) {
                float xv = xs[j];
                float hf = __uint_as_float(__float_as_uint(xv) & 0xFFFFE000u);
                Ah[kq + j][m] = hf;
                Al[kq + j][m] = xv - hf;
            }
        }
#pragma unroll
        for (int q = 0; q < 2; q++) {
            int f = tid + 256 * q;
            int kk = f >> 5;
            int nq = (f & 31) * 4;
            float4 v = *(const float4*)(B + (size_t)(k0 + kk) * 128 + nq);
            float xs[4] = {v.x, v.y, v.z, v.w};
            float hi[4], lo[4];
#pragma unroll
            for (int j = 0; j < 4; j++) {
                hi[j] = __uint_as_float(__float_as_uint(xs[j]) & 0xFFFFE000u);
                lo[j] = xs[j] - hi[j];
            }
            *(float4*)&Bh[kk][nq] = make_float4(hi[0], hi[1], hi[2], hi[3]);
            *(float4*)&Bl[kk][nq] = make_float4(lo[0], lo[1], lo[2], lo[3]);
        }
        __syncthreads();
#pragma unroll
        for (int ks = 0; ks < GBK; ks += 8) {
            unsigned ah[4][4], al[4][4];
#pragma unroll
            for (int mt = 0; mt < 4; mt++) {
                int m = wm * 64 + mt * 16 + group;
                ah[mt][0] = __float_as_uint(Ah[ks + tig][m]);
                ah[mt][1] = __float_as_uint(Ah[ks + tig][m + 8]);
                ah[mt][2] = __float_as_uint(Ah[ks + tig + 4][m]);
                ah[mt][3] = __float_as_uint(Ah[ks + tig + 4][m + 8]);
                al[mt][0] = __float_as_uint(Al[ks + tig][m]);
                al[mt][1] = __float_as_uint(Al[ks + tig][m + 8]);
                al[mt][2] = __float_as_uint(Al[ks + tig + 4][m]);
                al[mt][3] = __float_as_uint(Al[ks + tig + 4][m + 8]);
            }
#pragma unroll
            for (int nt = 0; nt < 4; nt++) {
                int c = wn * 32 + nt * 8 + group;
                unsigned bh0 = __float_as_uint(Bh[ks + tig][c]);
                unsigned bh1 = __float_as_uint(Bh[ks + tig + 4][c]);
                unsigned bl0 = __float_as_uint(Bl[ks + tig][c]);
                unsigned bl1 = __float_as_uint(Bl[ks + tig + 4][c]);
#pragma unroll
                for (int mt = 0; mt < 4; mt++) {
                    mma_tf32(acc[mt][nt], ah[mt], bh0, bh1);
                    mma_tf32(acc[mt][nt], ah[mt], bl0, bl1);
                    mma_tf32(acc[mt][nt], al[mt], bh0, bh1);
                }
            }
        }
        __syncthreads();
    }

    if (!EPI) {
#pragma unroll
        for (int mt = 0; mt < 4; mt++) {
#pragma unroll
            for (int h = 0; h < 2; h++) {
                int r = row0 + wm * 64 + mt * 16 + group + 8 * h;
                if (r >= n) continue;
#pragma unroll
                for (int nt = 0; nt < 4; nt++) {
                    int cb = wn * 32 + nt * 8 + tig * 2;
                    *(float2*)(g_hw + (size_t)r * 128 + cb) =
                        make_float2(acc[mt][nt][2 * h], acc[mt][nt][2 * h + 1]);
                }
            }
        }
    } else {
        float aP = pa[0];
        float pn = g_pnorm[L];
        float pv[8], bs8[8], bh8[8], cb8[8];
#pragma unroll
        for (int nt = 0; nt < 4; nt++) {
#pragma unroll
            for (int e = 0; e < 2; e++) {
                int c = wn * 32 + nt * 8 + tig * 2 + e;
                pv[nt * 2 + e] = pL[c];
                bs8[nt * 2 + e] = g_bnsc[L * 128 + c];
                bh8[nt * 2 + e] = g_bnsh[L * 128 + c];
                cb8[nt * 2 + e] = convbL[c];
            }
        }
#pragma unroll
        for (int mt = 0; mt < 4; mt++) {
#pragma unroll
            for (int h = 0; h < 2; h++) {
                int rloc = wm * 64 + mt * 16 + group + 8 * h;
                int r = row0 + rloc;
                const float2* agr = (const float2*)(g_agg + (size_t)r * 128);
                float sp = 0.f;
                float2 outv[4];
#pragma unroll
                for (int nt = 0; nt < 4; nt++) {
                    int cb = wn * 32 + nt * 8 + tig * 2;
                    float2 ag = agr[cb >> 1];
                    float v0 = acc[mt][nt][2 * h] + ag.x + cb8[nt * 2];
                    float v1 = acc[mt][nt][2 * h + 1] + ag.y + cb8[nt * 2 + 1];
                    v0 = fmaxf(v0, 0.f) * bs8[nt * 2] + bh8[nt * 2];
                    v1 = fmaxf(v1, 0.f) * bs8[nt * 2 + 1] + bh8[nt * 2 + 1];
                    v0 = v0 > 0.f ? v0 : aP * v0;
                    v1 = v1 > 0.f ? v1 : aP * v1;
                    sp += v0 * pv[nt * 2] + v1 * pv[nt * 2 + 1];
                    outv[nt] = make_float2(v0, v1);
                }
                if (r < n) {
#pragma unroll
                    for (int nt = 0; nt < 4; nt++) {
                        int cb = wn * 32 + nt * 8 + tig * 2;
                        *(float2*)(g_h2 + (size_t)r * 128 + cb) = outv[nt];
                    }
                }
                sp += __shfl_xor_sync(0xFFFFFFFFu, sp, 1);
                sp += __shfl_xor_sync(0xFFFFFFFFu, sp, 2);
                if (tig == 0) Ssc[rloc][wn] = sp;
            }
        }
        __syncthreads();
        if (tid < 128) {
            int r = row0 + tid;
            if (r < n) {
                float s = Ssc[tid][0] + Ssc[tid][1] + Ssc[tid][2] + Ssc[tid][3];
                g_score[r] = tanhf(s / pn);
            }
        }
    }
}

// ---------------- fused top-k: 3 radix passes + select, grid barriers, redundant scans ----------------
__device__ __forceinline__ void scan_pass(int pass, unsigned kr_in, unsigned* kr_out,
                                          unsigned long long* prefix, int shift) {
    __shared__ unsigned arr[256], rev[256];
    __shared__ unsigned sh_dig, sh_kr;
    int t = threadIdx.x;
    int cb0 = t * 4;
    unsigned s = 0;
#pragma unroll
    for (int q = 0; q < 4; q++) s += g_coarse[pass][cb0 + q];
    arr[t] = s;
    __syncthreads();
    rev[t] = arr[255 - t];
    __syncthreads();
    for (int off = 1; off < 256; off <<= 1) {
        unsigned v = (t >= off) ? rev[t - off] : 0u;
        __syncthreads();
        rev[t] += v;
        __syncthreads();
    }
    unsigned suf = rev[255 - t];
    unsigned above = suf - s;
    if (above < kr_in && suf >= kr_in) {   // exactly one thread
        unsigned running = above;
        for (int b = 3; b >= 0; b--) {
            unsigned c = g_coarse[pass][cb0 + b];
            if (running + c >= kr_in) {
                int fb = (cb0 + b) * 64;
                for (int d = 63; d >= 0; d--) {
                    unsigned fc = g_hist[pass][fb + d];
                    if (running + fc >= kr_in) {
                        sh_kr = kr_in - running;
                        sh_dig = (unsigned)(fb + d);
                        break;
                    }
                    running += fc;
                }
                break;
            }
            running += c;
        }
    }
    __syncthreads();
    *prefix |= ((unsigned long long)sh_dig) << shift;
    *kr_out = sh_kr;
    __syncthreads();  // protect shared reuse next pass
}

__global__ void __launch_bounds__(256) k_topk(int n, unsigned k, int nb) {
    int t = threadIdx.x;
    int i = blockIdx.x * 256 + t;
    bool valid = (i < n);
    unsigned long long key = valid ? make_key(g_score[i], i) : 0ull;
    unsigned long long prefix = 0;
    unsigned kr = k;
#pragma unroll
    for (int pass = 0; pass < 3; pass++) {
        int shift = 32 - 16 * pass;
        bool act = valid && (pass == 0 || ((key >> (shift + 16)) == (prefix >> (shift + 16))));
        if (act) {
            unsigned digit = (unsigned)((key >> shift) & 0xFFFFull);
            atomicAdd(&g_hist[pass][digit], 1u);
            atomicAdd(&g_coarse[pass][digit >> 6], 1u);
        }
        gridbar((unsigned)nb);
        scan_pass(pass, kr, &kr, &prefix, shift);
    }
    if (valid) {
        g_degi[i] = 0;  // degrees consumed; clear for next layer
        if (key >= prefix) {
            unsigned pos = atomicAdd(&g_selcnt, 1u);
            g_sel[pos] = i;
            g_remap[i] = (int)pos;
        }
    }
}

__global__ void __launch_bounds__(128) k_gatherremap(int L, int k, int ebuf, float invk) {
    int c = threadIdx.x;
    int r0 = blockIdx.x * 64;
    float lmax = __int_as_float(0xff800000);
    float lsum = 0.f;
    int rend = r0 + 64; if (rend > k) rend = k;
    for (int r = r0; r < rend; r++) {
        int i = g_sel[r];
        float v = g_h2[(size_t)i * 128 + c] * g_score[i];
        g_h[(size_t)r * 128 + c] = v;
        lmax = fmaxf(lmax, v);
        lsum += v;
    }
    atomicMax(&g_umax[c], fmap(lmax));
    atomicAdd(&g_colsum[c], lsum);

    int cnt = g_ecnt[L];
    const int2* Ein = g_edges[ebuf];
    int2* Eout = g_edges[ebuf ^ 1];
    for (int i = blockIdx.x * 128 + c; i < cnt; i += gridDim.x * 128) {
        int2 e = Ein[i];
        int ns = g_remap[e.x];
        int nd = g_remap[e.y];
        if (ns >= 0 && nd >= 0) {
            int pos = atomicAdd(&g_ecnt[L + 1], 1);
            Eout[pos] = make_int2(ns, nd);
            atomicAdd(&g_degi[nd], 1);
        }
    }

    __threadfence();
    __shared__ int lastb;
    if (c == 0) {
        unsigned v = atomicAdd(&g_doneB, 1u);
        lastb = (v == gridDim.x - 1);
        if (lastb) g_doneB = 0u;
    }
    __syncthreads();
    if (lastb) {
        g_reads[L * 256 + c] = funmap(g_umax[c]);
        g_reads[L * 256 + 128 + c] = g_colsum[c] * invk;
    }
}

// ---------------- MLP head ----------------
__global__ void k_lin1(const float* __restrict__ W) {
    int col = blockIdx.x * 256 + threadIdx.x;
    int r0 = blockIdx.y * 320;
    float acc = 0.f;
    for (int r = r0; r < r0 + 320; r++) acc += g_reads[r] * W[(size_t)r * 1280 + col];
    atomicAdd(&g_z1[col], acc);
}

// fused: z1 bias + prelu, then lin2 + prelu + normalize
__global__ void k_lin2(const float* __restrict__ b1, const float* __restrict__ W2,
                       const float* __restrict__ b2, const float* __restrict__ pa,
                       float* __restrict__ out) {
    int tid = threadIdx.x;
    float a = pa[0];
    float acc[8] = {0, 0, 0, 0, 0, 0, 0, 0};
    for (int i = tid; i < 1280; i += 256) {
        float v = g_z1[i] + b1[i];
        v = v > 0.f ? v : a * v;
#pragma unroll
        for (int j = 0; j < 8; j++) acc[j] += v * W2[i * 8 + j];
    }
    __shared__ float red[256][8];
#pragma unroll
    for (int j = 0; j < 8; j++) red[tid][j] = acc[j];
    __syncthreads();
    for (int s = 128; s > 0; s >>= 1) {
        if (tid < s)
#pragma unroll
            for (int j = 0; j < 8; j++) red[tid][j] += red[tid + s][j];
        __syncthreads();
    }
    if (tid == 0) {
        float z[8];
#pragma unroll
        for (int j = 0; j < 8; j++) {
            float s = red[0][j] + b2[j];
            z[j] = s > 0.f ? s : a * s;
        }
        float mn = z[0];
#pragma unroll
        for (int j = 1; j < 8; j++) mn = fminf(mn, z[j]);
#pragma unroll
        for (int j = 0; j < 8; j++) z[j] -= mn;
        float mx = z[0];
#pragma unroll
        for (int j = 1; j < 8; j++) mx = fmaxf(mx, z[j]);
#pragma unroll
        for (int j = 0; j < 8; j++) z[j] /= mx;
        float sm = 0.f;
#pragma unroll
        for (int j = 0; j < 8; j++) sm += z[j];
#pragma unroll
        for (int j = 0; j < 8; j++) out[j] = z[j] / sm;
    }
}

// ---------------- launcher ----------------
extern "C" void kernel_launch(void* const* d_in, const int* in_sizes, int n_in,
                              void* d_out, int out_size) {
    const float* x       = (const float*)d_in[0];
    const int*   ei      = (const int*)  d_in[1];
    const float* W1      = (const float*)d_in[2];
    const float* V1      = (const float*)d_in[3];
    const float* Ws      = (const float*)d_in[4];
    const float* Vs      = (const float*)d_in[5];
    const float* conv_b  = (const float*)d_in[6];
    const float* bn_g    = (const float*)d_in[7];
    const float* bn_b    = (const float*)d_in[8];
    const float* bn_m    = (const float*)d_in[9];
    const float* bn_v    = (const float*)d_in[10];
    const float* pool_p  = (const float*)d_in[11];
    const float* prelu_a = (const float*)d_in[12];
    const float* lin1_w  = (const float*)d_in[13];
    const float* lin1_b  = (const float*)d_in[14];
    const float* lin2_w  = (const float*)d_in[15];
    const float* lin2_b  = (const float*)d_in[16];
    float* out = (float*)d_out;

    k_zerodeg<<<(NPAD + 255) / 256, 256>>>();
    k_init<<<512, 256>>>(ei);
    k_prep<<<10, 128>>>(bn_g, bn_b, bn_m, bn_v, pool_p);

    for (int L = 0; L < 10; L++) {
        int n = NS[L], k = KS[L];
        int eb = L & 1;

        k_prep_layer<<<PREP_NB, 256>>>(L, n, NT[L], eb);

        if (L == 0)
            k_rank1<<<1024, 256>>>(x, W1, n);
        else
            k_gemm<false><<<(n + 127) / 128, 256>>>(Ws + (size_t)(L - 1) * D * D, n,
                                                    nullptr, 0, nullptr, nullptr);

        k_agg<<<(n * 32 + 255) / 256, 256>>>(n);

        if (L == 0)
            k_l0epi<<<(n * 32 + 255) / 256, 256>>>(x, V1, conv_b, prelu_a, pool_p, n);
        else
            k_gemm<true><<<(n + 127) / 128, 256>>>(Vs + (size_t)(L - 1) * D * D, n,
                                                   conv_b + (size_t)L * D, L, prelu_a,
                                                   pool_p + (size_t)L * D);

        int gN = (n + 255) / 256;
        k_topk<<<gN, 256>>>(n, (unsigned)k, gN);

        k_gatherremap<<<(k + 63) / 64, 128>>>(L, k, eb, 1.0f / (float)k);
    }

    k_lin1<<<dim3(5, 8), 256>>>(lin1_w);
    k_lin2<<<1, 256>>>(lin1_b, lin2_w, lin2_b, prelu_a, out);

    (void)in_sizes; (void)n_in; (void)out_size;
}

// round 9
// speedup vs baseline: 2.8769x; 1.0887x over previous
#include <cuda_runtime.h>
#include <math.h>

#define D 128
#define E_TOTAL 640000
#define NMAX 40000
#define NPAD (NMAX + 1024)

static const int NS[10] = {40000,32000,25600,20480,16384,13108,10487,8390,6712,5370};
static const int KS[10] = {32000,25600,20480,16384,13108,10487,8390,6712,5370,4296};
static const int NT[10] = {40,32,25,20,16,13,11,9,7,6};  // (n+1023)/1024

// ---------------- device scratch ----------------
__device__ float g_h  [NMAX*D];
__device__ float g_h2 [NMAX*D];
__device__ float g_hw [NMAX*D];
__device__ float g_hv [NMAX*D];
__device__ float g_score[NMAX];
__device__ float g_dinv [NMAX];
__device__ __align__(16) int g_degi[NPAD];
__device__ int   g_remap[NMAX];
__device__ int   g_sel  [NMAX];
__device__ int   g_off  [NMAX+1];
__device__ int   g_cur  [NMAX];
__device__ int   g_csr  [E_TOTAL];
__device__ int2  g_edges[2][E_TOTAL];
__device__ int   g_ecnt[11];
__device__ int   g_tilesum[64];
__device__ unsigned g_hist[3][65536];   // zero at load; k_topk restores zeros after use
__device__ unsigned g_coarse[3][1024];
__device__ unsigned g_selcnt;
__device__ unsigned g_doneB;
__device__ unsigned g_barArr;
__device__ volatile unsigned g_barGen;
__device__ unsigned g_umax[D];
__device__ float g_colsum[D];
__device__ float g_reads[2560];
__device__ float g_z1[1280];
__device__ float g_bnsc[10*D];
__device__ float g_bnsh[10*D];
__device__ float g_pnorm[10];

// ---------------- helpers ----------------
__device__ __forceinline__ unsigned fmap(float f) {
    unsigned b = __float_as_uint(f);
    return (b & 0x80000000u) ? ~b : (b | 0x80000000u);
}
__device__ __forceinline__ float funmap(unsigned u) {
    unsigned b = (u & 0x80000000u) ? (u ^ 0x80000000u) : ~u;
    return __uint_as_float(b);
}
// 48-bit key: score (32) | inverted index (16). larger == better; ties -> smaller index.
__device__ __forceinline__ unsigned long long make_key(float s, int i) {
    return (((unsigned long long)fmap(s)) << 16) | (unsigned)(0xFFFFu - (unsigned)i);
}

__device__ __forceinline__ void mma_tf32(float* c, const unsigned* a, unsigned b0, unsigned b1) {
    asm volatile(
        "mma.sync.aligned.m16n8k8.row.col.f32.tf32.tf32.f32 "
        "{%0,%1,%2,%3}, {%4,%5,%6,%7}, {%8,%9}, {%0,%1,%2,%3};\n"
        : "+f"(c[0]), "+f"(c[1]), "+f"(c[2]), "+f"(c[3])
        : "r"(a[0]), "r"(a[1]), "r"(a[2]), "r"(a[3]), "r"(b0), "r"(b1));
}

// grid barrier: safe only when ALL nb blocks are resident (single wave).
__device__ __forceinline__ void gridbar(unsigned nb) {
    __syncthreads();
    if (threadIdx.x == 0) {
        __threadfence();
        unsigned gen = g_barGen;
        if (atomicAdd(&g_barArr, 1u) == nb - 1) {
            g_barArr = 0;
            __threadfence();
            g_barGen = gen + 1;
        } else {
            while (g_barGen == gen) __nanosleep(64);
            __threadfence();
        }
    }
    __syncthreads();
}

// ---------------- init ----------------
__global__ void k_zerodeg() {
    int gid = blockIdx.x * blockDim.x + threadIdx.x;
    if (gid < NPAD) g_degi[gid] = 0;
}

__global__ void k_init(const int* __restrict__ ei) {
    int gid = blockIdx.x * blockDim.x + threadIdx.x;
    int stride = gridDim.x * blockDim.x;
    for (int i = gid; i < E_TOTAL; i += stride) {
        int d = ei[E_TOTAL + i];
        g_edges[0][i] = make_int2(ei[i], d);
        atomicAdd(&g_degi[d], 1);
    }
    if (gid == 0) g_ecnt[0] = E_TOTAL;
}

// fused BN-const precompute + pool-vector norms + z1 zero: grid 10, block 128
__global__ void k_prep(const float* __restrict__ gamma, const float* __restrict__ beta,
                       const float* __restrict__ mean, const float* __restrict__ var,
                       const float* __restrict__ p) {
    int L = blockIdx.x;
    int t = threadIdx.x;
    int idx = L * 128 + t;
    float sc = gamma[idx] / sqrtf(var[idx] + 1e-5f);
    g_bnsc[idx] = sc;
    g_bnsh[idx] = beta[idx] - mean[idx] * sc;
    g_z1[idx] = 0.f;
    __shared__ float sm[128];
    float v = p[idx];
    sm[t] = v * v;
    __syncthreads();
    for (int s = 64; s > 0; s >>= 1) {
        if (t < s) sm[t] += sm[t + s];
        __syncthreads();
    }
    if (t == 0) g_pnorm[L] = sqrtf(sm[0]);
}

// ---------------- fused per-layer prep: tile sums | offsets | csrfill ----------------
#define PREP_NB 128
__global__ void __launch_bounds__(256) k_prep_layer(int L, int n, int ntiles, int ebuf) {
    int t = threadIdx.x;
    int bid = blockIdx.x;
    int gid = bid * 256 + t;
    const int stride = PREP_NB * 256;

    // ---- phase 1: small zeroing + per-tile degree sums ----
    if (gid < 128) { g_umax[gid] = 0u; g_colsum[gid] = 0.f; }
    if (gid == 0) { g_selcnt = 0u; g_ecnt[L + 1] = 0; }

    if (bid < ntiles) {
        int base = bid * 1024 + t * 4;
        int4 dv = *(const int4*)&g_degi[base];
        int s = 0;
        if (base + 0 < n) s += dv.x;
        if (base + 1 < n) s += dv.y;
        if (base + 2 < n) s += dv.z;
        if (base + 3 < n) s += dv.w;
#pragma unroll
        for (int off = 16; off > 0; off >>= 1) s += __shfl_xor_sync(0xFFFFFFFFu, s, off);
        __shared__ int ws[8];
        if ((t & 31) == 0) ws[t >> 5] = s;
        __syncthreads();
        if (t == 0) {
            int tot = 0;
#pragma unroll
            for (int j = 0; j < 8; j++) tot += ws[j];
            g_tilesum[bid] = tot;
        }
    }

    gridbar(PREP_NB);

    // ---- phase 2: offsets expansion, redundant tile prefix ----
    if (bid < ntiles) {
        int pref = 0;
        for (int j = 0; j < bid; j++) pref += g_tilesum[j];
        if (bid == ntiles - 1 && t == 0) g_off[n] = pref + g_tilesum[bid];

        int base = bid * 1024 + t * 4;
        int4 dv = *(const int4*)&g_degi[base];
        int d0 = (base + 0 < n) ? dv.x : 0;
        int d1 = (base + 1 < n) ? dv.y : 0;
        int d2 = (base + 2 < n) ? dv.z : 0;
        int d3 = (base + 3 < n) ? dv.w : 0;
        int s = d0 + d1 + d2 + d3;
        int lane = t & 31, wid = t >> 5;
        int incl = s;
#pragma unroll
        for (int off = 1; off < 32; off <<= 1) {
            int v = __shfl_up_sync(0xFFFFFFFFu, incl, off);
            if (lane >= off) incl += v;
        }
        __shared__ int wsum[8], wpref[8];
        if (lane == 31) wsum[wid] = incl;
        __syncthreads();
        if (t < 8) {
            int pp = 0;
#pragma unroll
            for (int j = 0; j < 8; j++) {
                int u = wsum[j];
                if (j < t) pp += u;
            }
            wpref[t] = pp;
        }
        __syncthreads();
        int excl = incl - s + wpref[wid] + pref;
        int dd[4] = {d0, d1, d2, d3};
#pragma unroll
        for (int j = 0; j < 4; j++) {
            int idx = base + j;
            if (idx < n) {
                g_off[idx] = excl;
                g_cur[idx] = excl;
                g_dinv[idx] = (dd[j] > 0) ? (1.0f / sqrtf((float)dd[j])) : 0.f;
                excl += dd[j];
            }
        }
    }

    gridbar(PREP_NB);

    // ---- phase 3: CSR fill ----
    int cnt = g_ecnt[L];
    const int2* E = g_edges[ebuf];
    for (int i = gid; i < cnt; i += stride) {
        int2 e = E[i];
        int pos = atomicAdd(&g_cur[e.y], 1);
        g_csr[pos] = e.x;
    }
}

// layer 0: hw = x * W1, hv = x * V1
__global__ void k_rank1(const float* __restrict__ x, const float* __restrict__ w,
                        const float* __restrict__ v, int n) {
    int gid = blockIdx.x * blockDim.x + threadIdx.x;
    int stride = gridDim.x * blockDim.x;
    const float4* w4 = (const float4*)w;
    const float4* v4 = (const float4*)v;
    float4* ow = (float4*)g_hw;
    float4* ov = (float4*)g_hv;
    for (int i = gid; i < n * 32; i += stride) {
        float xv = x[i >> 5];
        float4 wv = w4[i & 31];
        float4 vv = v4[i & 31];
        ow[i] = make_float4(xv * wv.x, xv * wv.y, xv * wv.z, xv * wv.w);
        ov[i] = make_float4(xv * vv.x, xv * vv.y, xv * vv.z, xv * vv.w);
    }
}

// agg (warp per node, register acc) + fused conv epilogue + BN + PReLU + score
__global__ void k_aggepi(int L, int n, const float* __restrict__ convb,
                         const float* __restrict__ pa, const float* __restrict__ p) {
    int gid = blockIdx.x * blockDim.x + threadIdx.x;
    int node = gid >> 5;
    int lane = gid & 31;
    if (node >= n) return;
    int st = g_off[node], en = g_off[node + 1];
    float dd = g_dinv[node];
    float4 acc = make_float4(0.f, 0.f, 0.f, 0.f);
    const float4* hw4 = (const float4*)g_hw;
    for (int j = st; j < en; j++) {
        int s = g_csr[j];
        float c = g_dinv[s] * dd;
        float4 v = hw4[(size_t)s * 32 + lane];
        acc.x += v.x * c; acc.y += v.y * c; acc.z += v.z * c; acc.w += v.w * c;
    }
    float a = pa[0];
    float4 hv = ((const float4*)g_hv)[(size_t)node * 32 + lane];
    float4 cb = ((const float4*)convb)[lane];
    float4 s4 = ((const float4*)(g_bnsc + L * 128))[lane];
    float4 h4 = ((const float4*)(g_bnsh + L * 128))[lane];
    float4 p4 = ((const float4*)p)[lane];
    float o[4] = {acc.x + hv.x + cb.x, acc.y + hv.y + cb.y,
                  acc.z + hv.z + cb.z, acc.w + hv.w + cb.w};
    float bs[4] = {s4.x, s4.y, s4.z, s4.w};
    float bh[4] = {h4.x, h4.y, h4.z, h4.w};
    float pv[4] = {p4.x, p4.y, p4.z, p4.w};
    float sp = 0.f;
#pragma unroll
    for (int j = 0; j < 4; j++) {
        float v = fmaxf(o[j], 0.f);
        v = v * bs[j] + bh[j];
        v = v > 0.f ? v : a * v;
        o[j] = v;
        sp += v * pv[j];
    }
    ((float4*)g_h2)[(size_t)node * 32 + lane] = make_float4(o[0], o[1], o[2], o[3]);
#pragma unroll
    for (int off = 16; off > 0; off >>= 1) sp += __shfl_xor_sync(0xFFFFFFFFu, sp, off);
    if (lane == 0) g_score[node] = tanhf(sp / g_pnorm[L]);
}

// ---------------- TF32 tensor-core GEMM: gridDim.y=0 -> hw = h@W, y=1 -> hv = h@V ----------------
#define GBK 16
__global__ void __launch_bounds__(256) k_gemm2(const float* __restrict__ W,
                                               const float* __restrict__ V, int n) {
    __shared__ float Ah[GBK][136], Al[GBK][136];
    __shared__ float Bh[GBK][136], Bl[GBK][136];
    const float* B = blockIdx.y ? V : W;
    float* out = blockIdx.y ? g_hv : g_hw;
    int tid = threadIdx.x;
    int lane = tid & 31;
    int warp = tid >> 5;
    int wm = warp >> 2;
    int wn = warp & 3;
    int group = lane >> 2;
    int tig = lane & 3;
    int row0 = blockIdx.x * 128;

    float acc[4][4][4];
#pragma unroll
    for (int mt = 0; mt < 4; mt++)
#pragma unroll
        for (int nt = 0; nt < 4; nt++)
#pragma unroll
            for (int e = 0; e < 4; e++) acc[mt][nt][e] = 0.f;

    for (int k0 = 0; k0 < 128; k0 += GBK) {
#pragma unroll
        for (int q = 0; q < 2; q++) {
            int f = tid + 256 * q;
            int m = f >> 2;
            int kq = (f & 3) * 4;
            int gr = row0 + m; if (gr >= n) gr = n - 1;
            float4 v = *(const float4*)(g_h + (size_t)gr * 128 + k0 + kq);
            float xs[4] = {v.x, v.y, v.z, v.w};
#pragma unroll
            for (int j = 0; j < 4; j++) {
                float xv = xs[j];
                float hf = __uint_as_float(__float_as_uint(xv) & 0xFFFFE000u);
                Ah[kq + j][m] = hf;
                Al[kq + j][m] = xv - hf;
            }
        }
#pragma unroll
        for (int q = 0; q < 2; q++) {
            int f = tid + 256 * q;
            int kk = f >> 5;
            int nq = (f & 31) * 4;
            float4 v = *(const float4*)(B + (size_t)(k0 + kk) * 128 + nq);
            float xs[4] = {v.x, v.y, v.z, v.w};
            float hi[4], lo[4];
#pragma unroll
            for (int j = 0; j < 4; j++) {
                hi[j] = __uint_as_float(__float_as_uint(xs[j]) & 0xFFFFE000u);
                lo[j] = xs[j] - hi[j];
            }
            *(float4*)&Bh[kk][nq] = make_float4(hi[0], hi[1], hi[2], hi[3]);
            *(float4*)&Bl[kk][nq] = make_float4(lo[0], lo[1], lo[2], lo[3]);
        }
        __syncthreads();
#pragma unroll
        for (int ks = 0; ks < GBK; ks += 8) {
            unsigned ah[4][4], al[4][4];
#pragma unroll
            for (int mt = 0; mt < 4; mt++) {
                int m = wm * 64 + mt * 16 + group;
                ah[mt][0] = __float_as_uint(Ah[ks + tig][m]);
                ah[mt][1] = __float_as_uint(Ah[ks + tig][m + 8]);
                ah[mt][2] = __float_as_uint(Ah[ks + tig + 4][m]);
                ah[mt][3] = __float_as_uint(Ah[ks + tig + 4][m + 8]);
                al[mt][0] = __float_as_uint(Al[ks + tig][m]);
                al[mt][1] = __float_as_uint(Al[ks + tig][m + 8]);
                al[mt][2] = __float_as_uint(Al[ks + tig + 4][m]);
                al[mt][3] = __float_as_uint(Al[ks + tig + 4][m + 8]);
            }
#pragma unroll
            for (int nt = 0; nt < 4; nt++) {
                int c = wn * 32 + nt * 8 + group;
                unsigned bh0 = __float_as_uint(Bh[ks + tig][c]);
                unsigned bh1 = __float_as_uint(Bh[ks + tig + 4][c]);
                unsigned bl0 = __float_as_uint(Bl[ks + tig][c]);
                unsigned bl1 = __float_as_uint(Bl[ks + tig + 4][c]);
#pragma unroll
                for (int mt = 0; mt < 4; mt++) {
                    mma_tf32(acc[mt][nt], ah[mt], bh0, bh1);
                    mma_tf32(acc[mt][nt], ah[mt], bl0, bl1);
                    mma_tf32(acc[mt][nt], al[mt], bh0, bh1);
                }
            }
        }
        __syncthreads();
    }

#pragma unroll
    for (int mt = 0; mt < 4; mt++) {
#pragma unroll
        for (int h = 0; h < 2; h++) {
            int r = row0 + wm * 64 + mt * 16 + group + 8 * h;
            if (r >= n) continue;
#pragma unroll
            for (int nt = 0; nt < 4; nt++) {
                int cb = wn * 32 + nt * 8 + tig * 2;
                *(float2*)(out + (size_t)r * 128 + cb) =
                    make_float2(acc[mt][nt][2 * h], acc[mt][nt][2 * h + 1]);
            }
        }
    }
}

// ---------------- fused top-k: 3 radix passes + self-cleaning hist + select ----------------
__device__ __forceinline__ void scan_pass(int pass, unsigned kr_in, unsigned* kr_out,
                                          unsigned long long* prefix, int shift) {
    __shared__ unsigned arr[256], rev[256];
    __shared__ unsigned sh_dig, sh_kr;
    int t = threadIdx.x;
    int cb0 = t * 4;
    unsigned s = 0;
#pragma unroll
    for (int q = 0; q < 4; q++) s += g_coarse[pass][cb0 + q];
    arr[t] = s;
    __syncthreads();
    rev[t] = arr[255 - t];
    __syncthreads();
    for (int off = 1; off < 256; off <<= 1) {
        unsigned v = (t >= off) ? rev[t - off] : 0u;
        __syncthreads();
        rev[t] += v;
        __syncthreads();
    }
    unsigned suf = rev[255 - t];
    unsigned above = suf - s;
    if (above < kr_in && suf >= kr_in) {   // exactly one thread
        unsigned running = above;
        for (int b = 3; b >= 0; b--) {
            unsigned c = g_coarse[pass][cb0 + b];
            if (running + c >= kr_in) {
                int fb = (cb0 + b) * 64;
                for (int d = 63; d >= 0; d--) {
                    unsigned fc = g_hist[pass][fb + d];
                    if (running + fc >= kr_in) {
                        sh_kr = kr_in - running;
                        sh_dig = (unsigned)(fb + d);
                        break;
                    }
                    running += fc;
                }
                break;
            }
            running += c;
        }
    }
    __syncthreads();
    *prefix |= ((unsigned long long)sh_dig) << shift;
    *kr_out = sh_kr;
    __syncthreads();
}

__global__ void __launch_bounds__(256) k_topk(int n, unsigned k, int nb) {
    int t = threadIdx.x;
    int i = blockIdx.x * 256 + t;
    bool valid = (i < n);
    unsigned long long key = valid ? make_key(g_score[i], i) : 0ull;
    unsigned long long prefix = 0;
    unsigned kr = k;
    unsigned digits[3];
    int actmask = 0;
#pragma unroll
    for (int pass = 0; pass < 3; pass++) {
        int shift = 32 - 16 * pass;
        bool act = valid && (pass == 0 || ((key >> (shift + 16)) == (prefix >> (shift + 16))));
        if (act) {
            unsigned digit = (unsigned)((key >> shift) & 0xFFFFull);
            digits[pass] = digit;
            actmask |= 1 << pass;
            atomicAdd(&g_hist[pass][digit], 1u);
            atomicAdd(&g_coarse[pass][digit >> 6], 1u);
        }
        gridbar((unsigned)nb);
        scan_pass(pass, kr, &kr, &prefix, shift);
    }
    gridbar((unsigned)nb);  // all scans done before clearing
    if (valid) {
#pragma unroll
        for (int pass = 0; pass < 3; pass++) {
            if (actmask & (1 << pass)) {
                g_hist[pass][digits[pass]] = 0u;
                g_coarse[pass][digits[pass] >> 6] = 0u;
            }
        }
        g_degi[i] = 0;  // degrees consumed; clear for next layer
        if (key >= prefix) {
            unsigned pos = atomicAdd(&g_selcnt, 1u);
            g_sel[pos] = i;
            g_remap[i] = (int)pos;
        } else {
            g_remap[i] = -1;
        }
    }
}

__global__ void __launch_bounds__(128) k_gatherremap(int L, int k, int ebuf, float invk) {
    int c = threadIdx.x;
    int r0 = blockIdx.x * 64;
    float lmax = __int_as_float(0xff800000);
    float lsum = 0.f;
    int rend = r0 + 64; if (rend > k) rend = k;
    for (int r = r0; r < rend; r++) {
        int i = g_sel[r];
        float v = g_h2[(size_t)i * 128 + c] * g_score[i];
        g_h[(size_t)r * 128 + c] = v;
        lmax = fmaxf(lmax, v);
        lsum += v;
    }
    atomicMax(&g_umax[c], fmap(lmax));
    atomicAdd(&g_colsum[c], lsum);

    int cnt = g_ecnt[L];
    const int2* Ein = g_edges[ebuf];
    int2* Eout = g_edges[ebuf ^ 1];
    for (int i = blockIdx.x * 128 + c; i < cnt; i += gridDim.x * 128) {
        int2 e = Ein[i];
        int ns = g_remap[e.x];
        int nd = g_remap[e.y];
        if (ns >= 0 && nd >= 0) {
            int pos = atomicAdd(&g_ecnt[L + 1], 1);
            Eout[pos] = make_int2(ns, nd);
            atomicAdd(&g_degi[nd], 1);
        }
    }

    __threadfence();
    __shared__ int lastb;
    if (c == 0) {
        unsigned v = atomicAdd(&g_doneB, 1u);
        lastb = (v == gridDim.x - 1);
        if (lastb) g_doneB = 0u;
    }
    __syncthreads();
    if (lastb) {
        g_reads[L * 256 + c] = funmap(g_umax[c]);
        g_reads[L * 256 + 128 + c] = g_colsum[c] * invk;
    }
}

// ---------------- MLP head ----------------
__global__ void k_lin1(const float* __restrict__ W) {
    int col = blockIdx.x * 256 + threadIdx.x;
    int r0 = blockIdx.y * 320;
    float acc = 0.f;
    for (int r = r0; r < r0 + 320; r++) acc += g_reads[r] * W[(size_t)r * 1280 + col];
    atomicAdd(&g_z1[col], acc);
}

__global__ void k_lin2(const float* __restrict__ b1, const float* __restrict__ W2,
                       const float* __restrict__ b2, const float* __restrict__ pa,
                       float* __restrict__ out) {
    int tid = threadIdx.x;
    float a = pa[0];
    float acc[8] = {0, 0, 0, 0, 0, 0, 0, 0};
    for (int i = tid; i < 1280; i += 256) {
        float v = g_z1[i] + b1[i];
        v = v > 0.f ? v : a * v;
#pragma unroll
        for (int j = 0; j < 8; j++) acc[j] += v * W2[i * 8 + j];
    }
    __shared__ float red[256][8];
#pragma unroll
    for (int j = 0; j < 8; j++) red[tid][j] = acc[j];
    __syncthreads();
    for (int s = 128; s > 0; s >>= 1) {
        if (tid < s)
#pragma unroll
            for (int j = 0; j < 8; j++) red[tid][j] += red[tid + s][j];
        __syncthreads();
    }
    if (tid == 0) {
        float z[8];
#pragma unroll
        for (int j = 0; j < 8; j++) {
            float s = red[0][j] + b2[j];
            z[j] = s > 0.f ? s : a * s;
        }
        float mn = z[0];
#pragma unroll
        for (int j = 1; j < 8; j++) mn = fminf(mn, z[j]);
#pragma unroll
        for (int j = 0; j < 8; j++) z[j] -= mn;
        float mx = z[0];
#pragma unroll
        for (int j = 1; j < 8; j++) mx = fmaxf(mx, z[j]);
#pragma unroll
        for (int j = 0; j < 8; j++) z[j] /= mx;
        float sm = 0.f;
#pragma unroll
        for (int j = 0; j < 8; j++) sm += z[j];
#pragma unroll
        for (int j = 0; j < 8; j++) out[j] = z[j] / sm;
    }
}

// ---------------- launcher ----------------
extern "C" void kernel_launch(void* const* d_in, const int* in_sizes, int n_in,
                              void* d_out, int out_size) {
    const float* x       = (const float*)d_in[0];
    const int*   ei      = (const int*)  d_in[1];
    const float* W1      = (const float*)d_in[2];
    const float* V1      = (const float*)d_in[3];
    const float* Ws      = (const float*)d_in[4];
    const float* Vs      = (const float*)d_in[5];
    const float* conv_b  = (const float*)d_in[6];
    const float* bn_g    = (const float*)d_in[7];
    const float* bn_b    = (const float*)d_in[8];
    const float* bn_m    = (const float*)d_in[9];
    const float* bn_v    = (const float*)d_in[10];
    const float* pool_p  = (const float*)d_in[11];
    const float* prelu_a = (const float*)d_in[12];
    const float* lin1_w  = (const float*)d_in[13];
    const float* lin1_b  = (const float*)d_in[14];
    const float* lin2_w  = (const float*)d_in[15];
    const float* lin2_b  = (const float*)d_in[16];
    float* out = (float*)d_out;

    k_zerodeg<<<(NPAD + 255) / 256, 256>>>();
    k_init<<<512, 256>>>(ei);
    k_prep<<<10, 128>>>(bn_g, bn_b, bn_m, bn_v, pool_p);

    for (int L = 0; L < 10; L++) {
        int n = NS[L], k = KS[L];
        int eb = L & 1;

        k_prep_layer<<<PREP_NB, 256>>>(L, n, NT[L], eb);

        if (L == 0)
            k_rank1<<<1024, 256>>>(x, W1, V1, n);
        else
            k_gemm2<<<dim3((n + 127) / 128, 2), 256>>>(Ws + (size_t)(L - 1) * D * D,
                                                       Vs + (size_t)(L - 1) * D * D, n);

        k_aggepi<<<(n * 32 + 255) / 256, 256>>>(L, n, conv_b + (size_t)L * D,
                                                prelu_a, pool_p + (size_t)L * D);

        int gN = (n + 255) / 256;
        k_topk<<<gN, 256>>>(n, (unsigned)k, gN);

        k_gatherremap<<<(k + 63) / 64, 128>>>(L, k, eb, 1.0f / (float)k);
    }

    k_lin1<<<dim3(5, 8), 256>>>(lin1_w);
    k_lin2<<<1, 256>>>(lin1_b, lin2_w, lin2_b, prelu_a, out);

    (void)in_sizes; (void)n_in; (void)out_size;
}

// round 10
// speedup vs baseline: 3.1391x; 1.0912x over previous
#include <cuda_runtime.h>
#include <math.h>

#define D 128
#define E_TOTAL 640000
#define NMAX 40000
#define NPAD (NMAX + 1024)

static const int NS[10] = {40000,32000,25600,20480,16384,13108,10487,8390,6712,5370};
static const int KS[10] = {32000,25600,20480,16384,13108,10487,8390,6712,5370,4296};
static const int NT[10] = {40,32,25,20,16,13,11,9,7,6};  // (n+1023)/1024

// ---------------- device scratch ----------------
__device__ float g_h  [NMAX*D];
__device__ float g_h2 [NMAX*D];
__device__ float g_hw [NMAX*D];
__device__ float g_hv [NMAX*D];
__device__ float g_score[NMAX];
__device__ float g_dinv [NMAX];
__device__ __align__(16) int g_degi[NPAD];
__device__ int   g_remap[NMAX];
__device__ int   g_sel  [NMAX];
__device__ int   g_off  [NMAX+1];
__device__ int   g_cur  [NMAX];
__device__ int   g_csr  [E_TOTAL];
__device__ int2  g_edges[2][E_TOTAL];
__device__ int   g_ecnt[11];
__device__ int   g_tilesum[64];
__device__ int   g_tilepref[64];
__device__ unsigned g_hist[3][65536];   // zero at load; k_topk restores zeros after use
__device__ unsigned g_coarse[3][1024];
__device__ unsigned g_selcnt;
__device__ unsigned g_doneB;
__device__ unsigned g_doneC;
__device__ unsigned g_barArr;
__device__ volatile unsigned g_barGen;
__device__ unsigned g_umax[D];
__device__ float g_colsum[D];
__device__ float g_reads[2560];
__device__ float g_z1[1280];
__device__ float g_bnsc[10*D];
__device__ float g_bnsh[10*D];
__device__ float g_pnorm[10];

// ---------------- helpers ----------------
__device__ __forceinline__ unsigned fmap(float f) {
    unsigned b = __float_as_uint(f);
    return (b & 0x80000000u) ? ~b : (b | 0x80000000u);
}
__device__ __forceinline__ float funmap(unsigned u) {
    unsigned b = (u & 0x80000000u) ? (u ^ 0x80000000u) : ~u;
    return __uint_as_float(b);
}
// 48-bit key: score (32) | inverted index (16). larger == better; ties -> smaller index.
__device__ __forceinline__ unsigned long long make_key(float s, int i) {
    return (((unsigned long long)fmap(s)) << 16) | (unsigned)(0xFFFFu - (unsigned)i);
}

__device__ __forceinline__ void mma_tf32(float* c, const unsigned* a, unsigned b0, unsigned b1) {
    asm volatile(
        "mma.sync.aligned.m16n8k8.row.col.f32.tf32.tf32.f32 "
        "{%0,%1,%2,%3}, {%4,%5,%6,%7}, {%8,%9}, {%0,%1,%2,%3};\n"
        : "+f"(c[0]), "+f"(c[1]), "+f"(c[2]), "+f"(c[3])
        : "r"(a[0]), "r"(a[1]), "r"(a[2]), "r"(a[3]), "r"(b0), "r"(b1));
}

// grid barrier: safe only when ALL nb blocks are resident (single wave). Used ONLY
// by k_topk, which runs alone on the device.
__device__ __forceinline__ void gridbar(unsigned nb) {
    __syncthreads();
    if (threadIdx.x == 0) {
        __threadfence();
        unsigned gen = g_barGen;
        if (atomicAdd(&g_barArr, 1u) == nb - 1) {
            g_barArr = 0;
            __threadfence();
            g_barGen = gen + 1;
        } else {
            while (g_barGen == gen) __nanosleep(64);
            __threadfence();
        }
    }
    __syncthreads();
}

// ---------------- init ----------------
__global__ void k_zerodeg() {
    int gid = blockIdx.x * blockDim.x + threadIdx.x;
    if (gid < NPAD) g_degi[gid] = 0;
}

__global__ void k_init(const int* __restrict__ ei) {
    int gid = blockIdx.x * blockDim.x + threadIdx.x;
    int stride = gridDim.x * blockDim.x;
    for (int i = gid; i < E_TOTAL; i += stride) {
        int d = ei[E_TOTAL + i];
        g_edges[0][i] = make_int2(ei[i], d);
        atomicAdd(&g_degi[d], 1);
    }
    if (gid == 0) g_ecnt[0] = E_TOTAL;
}

// fused BN-const precompute + pool-vector norms + z1 zero: grid 10, block 128
__global__ void k_prep(const float* __restrict__ gamma, const float* __restrict__ beta,
                       const float* __restrict__ mean, const float* __restrict__ var,
                       const float* __restrict__ p) {
    int L = blockIdx.x;
    int t = threadIdx.x;
    int idx = L * 128 + t;
    float sc = gamma[idx] / sqrtf(var[idx] + 1e-5f);
    g_bnsc[idx] = sc;
    g_bnsh[idx] = beta[idx] - mean[idx] * sc;
    g_z1[idx] = 0.f;
    __shared__ float sm[128];
    float v = p[idx];
    sm[t] = v * v;
    __syncthreads();
    for (int s = 64; s > 0; s >>= 1) {
        if (t < s) sm[t] += sm[t + s];
        __syncthreads();
    }
    if (t == 0) g_pnorm[L] = sqrtf(sm[0]);
}

// ---------------- side-stream prep chain (no spinning barriers) ----------------
// tile degree sums + per-layer scalar zeroing; last block computes tile prefix.
__global__ void __launch_bounds__(256) k_tilesum(int L, int n, int ntiles) {
    int t = threadIdx.x;
    int bid = blockIdx.x;
    int gid = bid * 256 + t;
    if (gid < 128) { g_umax[gid] = 0u; g_colsum[gid] = 0.f; }
    if (gid == 0) { g_selcnt = 0u; g_ecnt[L + 1] = 0; }

    int base = bid * 1024 + t * 4;
    int4 dv = *(const int4*)&g_degi[base];
    int s = 0;
    if (base + 0 < n) s += dv.x;
    if (base + 1 < n) s += dv.y;
    if (base + 2 < n) s += dv.z;
    if (base + 3 < n) s += dv.w;
#pragma unroll
    for (int off = 16; off > 0; off >>= 1) s += __shfl_xor_sync(0xFFFFFFFFu, s, off);
    __shared__ int ws[8];
    if ((t & 31) == 0) ws[t >> 5] = s;
    __syncthreads();
    if (t == 0) {
        int tot = 0;
#pragma unroll
        for (int j = 0; j < 8; j++) tot += ws[j];
        g_tilesum[bid] = tot;
    }
    __threadfence();
    __shared__ int lastb;
    if (t == 0) {
        unsigned v = atomicAdd(&g_doneC, 1u);
        lastb = (v == (unsigned)ntiles - 1);
        if (lastb) g_doneC = 0u;
    }
    __syncthreads();
    if (lastb && t == 0) {
        int run = 0;
        for (int i = 0; i < ntiles; i++) { g_tilepref[i] = run; run += g_tilesum[i]; }
        g_off[n] = run;
    }
}

// expand per-tile offsets: one block per 1024-node tile
__global__ void __launch_bounds__(256) k_offsets(int n) {
    int t = threadIdx.x;
    int base = blockIdx.x * 1024 + t * 4;
    int4 dv = *(const int4*)&g_degi[base];
    int d0 = (base + 0 < n) ? dv.x : 0;
    int d1 = (base + 1 < n) ? dv.y : 0;
    int d2 = (base + 2 < n) ? dv.z : 0;
    int d3 = (base + 3 < n) ? dv.w : 0;
    int s = d0 + d1 + d2 + d3;
    int lane = t & 31, wid = t >> 5;
    int incl = s;
#pragma unroll
    for (int off = 1; off < 32; off <<= 1) {
        int v = __shfl_up_sync(0xFFFFFFFFu, incl, off);
        if (lane >= off) incl += v;
    }
    __shared__ int wsum[8], wpref[8];
    if (lane == 31) wsum[wid] = incl;
    __syncthreads();
    if (t < 8) {
        int pp = 0;
#pragma unroll
        for (int j = 0; j < 8; j++) {
            int u = wsum[j];
            if (j < t) pp += u;
        }
        wpref[t] = pp;
    }
    __syncthreads();
    int excl = incl - s + wpref[wid] + g_tilepref[blockIdx.x];
    int dd[4] = {d0, d1, d2, d3};
#pragma unroll
    for (int j = 0; j < 4; j++) {
        int idx = base + j;
        if (idx < n) {
            g_off[idx] = excl;
            g_cur[idx] = excl;
            g_dinv[idx] = (dd[j] > 0) ? (1.0f / sqrtf((float)dd[j])) : 0.f;
            excl += dd[j];
        }
    }
}

// CSR fill: 1 atomic per edge, grid-stride
__global__ void k_csrfill(int L, int ebuf) {
    int gid = blockIdx.x * blockDim.x + threadIdx.x;
    int stride = gridDim.x * blockDim.x;
    int cnt = g_ecnt[L];
    const int2* E = g_edges[ebuf];
    for (int i = gid; i < cnt; i += stride) {
        int2 e = E[i];
        int pos = atomicAdd(&g_cur[e.y], 1);
        g_csr[pos] = e.x;
    }
}

// layer 0: hw = x * W1, hv = x * V1
__global__ void k_rank1(const float* __restrict__ x, const float* __restrict__ w,
                        const float* __restrict__ v, int n) {
    int gid = blockIdx.x * blockDim.x + threadIdx.x;
    int stride = gridDim.x * blockDim.x;
    const float4* w4 = (const float4*)w;
    const float4* v4 = (const float4*)v;
    float4* ow = (float4*)g_hw;
    float4* ov = (float4*)g_hv;
    for (int i = gid; i < n * 32; i += stride) {
        float xv = x[i >> 5];
        float4 wv = w4[i & 31];
        float4 vv = v4[i & 31];
        ow[i] = make_float4(xv * wv.x, xv * wv.y, xv * wv.z, xv * wv.w);
        ov[i] = make_float4(xv * vv.x, xv * vv.y, xv * vv.z, xv * vv.w);
    }
}

// agg (warp per node, register acc) + fused conv epilogue + BN + PReLU + score
__global__ void k_aggepi(int L, int n, const float* __restrict__ convb,
                         const float* __restrict__ pa, const float* __restrict__ p) {
    int gid = blockIdx.x * blockDim.x + threadIdx.x;
    int node = gid >> 5;
    int lane = gid & 31;
    if (node >= n) return;
    int st = g_off[node], en = g_off[node + 1];
    float dd = g_dinv[node];
    float4 acc = make_float4(0.f, 0.f, 0.f, 0.f);
    const float4* hw4 = (const float4*)g_hw;
    for (int j = st; j < en; j++) {
        int s = g_csr[j];
        float c = g_dinv[s] * dd;
        float4 v = hw4[(size_t)s * 32 + lane];
        acc.x += v.x * c; acc.y += v.y * c; acc.z += v.z * c; acc.w += v.w * c;
    }
    float a = pa[0];
    float4 hv = ((const float4*)g_hv)[(size_t)node * 32 + lane];
    float4 cb = ((const float4*)convb)[lane];
    float4 s4 = ((const float4*)(g_bnsc + L * 128))[lane];
    float4 h4 = ((const float4*)(g_bnsh + L * 128))[lane];
    float4 p4 = ((const float4*)p)[lane];
    float o[4] = {acc.x + hv.x + cb.x, acc.y + hv.y + cb.y,
                  acc.z + hv.z + cb.z, acc.w + hv.w + cb.w};
    float bs[4] = {s4.x, s4.y, s4.z, s4.w};
    float bh[4] = {h4.x, h4.y, h4.z, h4.w};
    float pv[4] = {p4.x, p4.y, p4.z, p4.w};
    float sp = 0.f;
#pragma unroll
    for (int j = 0; j < 4; j++) {
        float v = fmaxf(o[j], 0.f);
        v = v * bs[j] + bh[j];
        v = v > 0.f ? v : a * v;
        o[j] = v;
        sp += v * pv[j];
    }
    ((float4*)g_h2)[(size_t)node * 32 + lane] = make_float4(o[0], o[1], o[2], o[3]);
#pragma unroll
    for (int off = 16; off > 0; off >>= 1) sp += __shfl_xor_sync(0xFFFFFFFFu, sp, off);
    if (lane == 0) g_score[node] = tanhf(sp / g_pnorm[L]);
}

// ---------------- TF32 tensor-core GEMM: gridDim.y=0 -> hw = h@W, y=1 -> hv = h@V ----------------
#define GBK 16
__global__ void __launch_bounds__(256) k_gemm2(const float* __restrict__ W,
                                               const float* __restrict__ V, int n) {
    __shared__ float Ah[GBK][136], Al[GBK][136];
    __shared__ float Bh[GBK][136], Bl[GBK][136];
    const float* B = blockIdx.y ? V : W;
    float* out = blockIdx.y ? g_hv : g_hw;
    int tid = threadIdx.x;
    int lane = tid & 31;
    int warp = tid >> 5;
    int wm = warp >> 2;
    int wn = warp & 3;
    int group = lane >> 2;
    int tig = lane & 3;
    int row0 = blockIdx.x * 128;

    float acc[4][4][4];
#pragma unroll
    for (int mt = 0; mt < 4; mt++)
#pragma unroll
        for (int nt = 0; nt < 4; nt++)
#pragma unroll
            for (int e = 0; e < 4; e++) acc[mt][nt][e] = 0.f;

    for (int k0 = 0; k0 < 128; k0 += GBK) {
#pragma unroll
        for (int q = 0; q < 2; q++) {
            int f = tid + 256 * q;
            int m = f >> 2;
            int kq = (f & 3) * 4;
            int gr = row0 + m; if (gr >= n) gr = n - 1;
            float4 v = *(const float4*)(g_h + (size_t)gr * 128 + k0 + kq);
            float xs[4] = {v.x, v.y, v.z, v.w};
#pragma unroll
            for (int j = 0; j < 4; j++) {
                float xv = xs[j];
                float hf = __uint_as_float(__float_as_uint(xv) & 0xFFFFE000u);
                Ah[kq + j][m] = hf;
                Al[kq + j][m] = xv - hf;
            }
        }
#pragma unroll
        for (int q = 0; q < 2; q++) {
            int f = tid + 256 * q;
            int kk = f >> 5;
            int nq = (f & 31) * 4;
            float4 v = *(const float4*)(B + (size_t)(k0 + kk) * 128 + nq);
            float xs[4] = {v.x, v.y, v.z, v.w};
            float hi[4], lo[4];
#pragma unroll
            for (int j = 0; j < 4; j++) {
                hi[j] = __uint_as_float(__float_as_uint(xs[j]) & 0xFFFFE000u);
                lo[j] = xs[j] - hi[j];
            }
            *(float4*)&Bh[kk][nq] = make_float4(hi[0], hi[1], hi[2], hi[3]);
            *(float4*)&Bl[kk][nq] = make_float4(lo[0], lo[1], lo[2], lo[3]);
        }
        __syncthreads();
#pragma unroll
        for (int ks = 0; ks < GBK; ks += 8) {
            unsigned ah[4][4], al[4][4];
#pragma unroll
            for (int mt = 0; mt < 4; mt++) {
                int m = wm * 64 + mt * 16 + group;
                ah[mt][0] = __float_as_uint(Ah[ks + tig][m]);
                ah[mt][1] = __float_as_uint(Ah[ks + tig][m + 8]);
                ah[mt][2] = __float_as_uint(Ah[ks + tig + 4][m]);
                ah[mt][3] = __float_as_uint(Ah[ks + tig + 4][m + 8]);
                al[mt][0] = __float_as_uint(Al[ks + tig][m]);
                al[mt][1] = __float_as_uint(Al[ks + tig][m + 8]);
                al[mt][2] = __float_as_uint(Al[ks + tig + 4][m]);
                al[mt][3] = __float_as_uint(Al[ks + tig + 4][m + 8]);
            }
#pragma unroll
            for (int nt = 0; nt < 4; nt++) {
                int c = wn * 32 + nt * 8 + group;
                unsigned bh0 = __float_as_uint(Bh[ks + tig][c]);
                unsigned bh1 = __float_as_uint(Bh[ks + tig + 4][c]);
                unsigned bl0 = __float_as_uint(Bl[ks + tig][c]);
                unsigned bl1 = __float_as_uint(Bl[ks + tig + 4][c]);
#pragma unroll
                for (int mt = 0; mt < 4; mt++) {
                    mma_tf32(acc[mt][nt], ah[mt], bh0, bh1);
                    mma_tf32(acc[mt][nt], ah[mt], bl0, bl1);
                    mma_tf32(acc[mt][nt], al[mt], bh0, bh1);
                }
            }
        }
        __syncthreads();
    }

#pragma unroll
    for (int mt = 0; mt < 4; mt++) {
#pragma unroll
        for (int h = 0; h < 2; h++) {
            int r = row0 + wm * 64 + mt * 16 + group + 8 * h;
            if (r >= n) continue;
#pragma unroll
            for (int nt = 0; nt < 4; nt++) {
                int cb = wn * 32 + nt * 8 + tig * 2;
                *(float2*)(out + (size_t)r * 128 + cb) =
                    make_float2(acc[mt][nt][2 * h], acc[mt][nt][2 * h + 1]);
            }
        }
    }
}

// ---------------- fused top-k: 3 radix passes + self-cleaning hist + select ----------------
__device__ __forceinline__ void scan_pass(int pass, unsigned kr_in, unsigned* kr_out,
                                          unsigned long long* prefix, int shift) {
    __shared__ unsigned arr[256], rev[256];
    __shared__ unsigned sh_dig, sh_kr;
    int t = threadIdx.x;
    int cb0 = t * 4;
    unsigned s = 0;
#pragma unroll
    for (int q = 0; q < 4; q++) s += g_coarse[pass][cb0 + q];
    arr[t] = s;
    __syncthreads();
    rev[t] = arr[255 - t];
    __syncthreads();
    for (int off = 1; off < 256; off <<= 1) {
        unsigned v = (t >= off) ? rev[t - off] : 0u;
        __syncthreads();
        rev[t] += v;
        __syncthreads();
    }
    unsigned suf = rev[255 - t];
    unsigned above = suf - s;
    if (above < kr_in && suf >= kr_in) {   // exactly one thread
        unsigned running = above;
        for (int b = 3; b >= 0; b--) {
            unsigned c = g_coarse[pass][cb0 + b];
            if (running + c >= kr_in) {
                int fb = (cb0 + b) * 64;
                for (int d = 63; d >= 0; d--) {
                    unsigned fc = g_hist[pass][fb + d];
                    if (running + fc >= kr_in) {
                        sh_kr = kr_in - running;
                        sh_dig = (unsigned)(fb + d);
                        break;
                    }
                    running += fc;
                }
                break;
            }
            running += c;
        }
    }
    __syncthreads();
    *prefix |= ((unsigned long long)sh_dig) << shift;
    *kr_out = sh_kr;
    __syncthreads();
}

__global__ void __launch_bounds__(256) k_topk(int n, unsigned k, int nb) {
    int t = threadIdx.x;
    int i = blockIdx.x * 256 + t;
    bool valid = (i < n);
    unsigned long long key = valid ? make_key(g_score[i], i) : 0ull;
    unsigned long long prefix = 0;
    unsigned kr = k;
    unsigned digits[3];
    int actmask = 0;
#pragma unroll
    for (int pass = 0; pass < 3; pass++) {
        int shift = 32 - 16 * pass;
        bool act = valid && (pass == 0 || ((key >> (shift + 16)) == (prefix >> (shift + 16))));
        if (act) {
            unsigned digit = (unsigned)((key >> shift) & 0xFFFFull);
            digits[pass] = digit;
            actmask |= 1 << pass;
            atomicAdd(&g_hist[pass][digit], 1u);
            atomicAdd(&g_coarse[pass][digit >> 6], 1u);
        }
        gridbar((unsigned)nb);
        scan_pass(pass, kr, &kr, &prefix, shift);
    }
    gridbar((unsigned)nb);  // all scans done before clearing
    if (valid) {
#pragma unroll
        for (int pass = 0; pass < 3; pass++) {
            if (actmask & (1 << pass)) {
                g_hist[pass][digits[pass]] = 0u;
                g_coarse[pass][digits[pass] >> 6] = 0u;
            }
        }
        g_degi[i] = 0;  // degrees consumed; clear for next layer
        if (key >= prefix) {
            unsigned pos = atomicAdd(&g_selcnt, 1u);
            g_sel[pos] = i;
            g_remap[i] = (int)pos;
        } else {
            g_remap[i] = -1;
        }
    }
}

__global__ void __launch_bounds__(128) k_gatherremap(int L, int k, int ebuf, float invk) {
    int c = threadIdx.x;
    int r0 = blockIdx.x * 64;
    float lmax = __int_as_float(0xff800000);
    float lsum = 0.f;
    int rend = r0 + 64; if (rend > k) rend = k;
    for (int r = r0; r < rend; r++) {
        int i = g_sel[r];
        float v = g_h2[(size_t)i * 128 + c] * g_score[i];
        g_h[(size_t)r * 128 + c] = v;
        lmax = fmaxf(lmax, v);
        lsum += v;
    }
    atomicMax(&g_umax[c], fmap(lmax));
    atomicAdd(&g_colsum[c], lsum);

    int cnt = g_ecnt[L];
    const int2* Ein = g_edges[ebuf];
    int2* Eout = g_edges[ebuf ^ 1];
    for (int i = blockIdx.x * 128 + c; i < cnt; i += gridDim.x * 128) {
        int2 e = Ein[i];
        int ns = g_remap[e.x];
        int nd = g_remap[e.y];
        if (ns >= 0 && nd >= 0) {
            int pos = atomicAdd(&g_ecnt[L + 1], 1);
            Eout[pos] = make_int2(ns, nd);
            atomicAdd(&g_degi[nd], 1);
        }
    }

    __threadfence();
    __shared__ int lastb;
    if (c == 0) {
        unsigned v = atomicAdd(&g_doneB, 1u);
        lastb = (v == gridDim.x - 1);
        if (lastb) g_doneB = 0u;
    }
    __syncthreads();
    if (lastb) {
        g_reads[L * 256 + c] = funmap(g_umax[c]);
        g_reads[L * 256 + 128 + c] = g_colsum[c] * invk;
    }
}

// ---------------- MLP head ----------------
__global__ void k_lin1(const float* __restrict__ W) {
    int col = blockIdx.x * 256 + threadIdx.x;
    int r0 = blockIdx.y * 320;
    float acc = 0.f;
    for (int r = r0; r < r0 + 320; r++) acc += g_reads[r] * W[(size_t)r * 1280 + col];
    atomicAdd(&g_z1[col], acc);
}

__global__ void k_lin2(const float* __restrict__ b1, const float* __restrict__ W2,
                       const float* __restrict__ b2, const float* __restrict__ pa,
                       float* __restrict__ out) {
    int tid = threadIdx.x;
    float a = pa[0];
    float acc[8] = {0, 0, 0, 0, 0, 0, 0, 0};
    for (int i = tid; i < 1280; i += 256) {
        float v = g_z1[i] + b1[i];
        v = v > 0.f ? v : a * v;
#pragma unroll
        for (int j = 0; j < 8; j++) acc[j] += v * W2[i * 8 + j];
    }
    __shared__ float red[256][8];
#pragma unroll
    for (int j = 0; j < 8; j++) red[tid][j] = acc[j];
    __syncthreads();
    for (int s = 128; s > 0; s >>= 1) {
        if (tid < s)
#pragma unroll
            for (int j = 0; j < 8; j++) red[tid][j] += red[tid + s][j];
        __syncthreads();
    }
    if (tid == 0) {
        float z[8];
#pragma unroll
        for (int j = 0; j < 8; j++) {
            float s = red[0][j] + b2[j];
            z[j] = s > 0.f ? s : a * s;
        }
        float mn = z[0];
#pragma unroll
        for (int j = 1; j < 8; j++) mn = fminf(mn, z[j]);
#pragma unroll
        for (int j = 0; j < 8; j++) z[j] -= mn;
        float mx = z[0];
#pragma unroll
        for (int j = 1; j < 8; j++) mx = fmaxf(mx, z[j]);
#pragma unroll
        for (int j = 0; j < 8; j++) z[j] /= mx;
        float sm = 0.f;
#pragma unroll
        for (int j = 0; j < 8; j++) sm += z[j];
#pragma unroll
        for (int j = 0; j < 8; j++) out[j] = z[j] / sm;
    }
}

// ---------------- launcher ----------------
extern "C" void kernel_launch(void* const* d_in, const int* in_sizes, int n_in,
                              void* d_out, int out_size) {
    const float* x       = (const float*)d_in[0];
    const int*   ei      = (const int*)  d_in[1];
    const float* W1      = (const float*)d_in[2];
    const float* V1      = (const float*)d_in[3];
    const float* Ws      = (const float*)d_in[4];
    const float* Vs      = (const float*)d_in[5];
    const float* conv_b  = (const float*)d_in[6];
    const float* bn_g    = (const float*)d_in[7];
    const float* bn_b    = (const float*)d_in[8];
    const float* bn_m    = (const float*)d_in[9];
    const float* bn_v    = (const float*)d_in[10];
    const float* pool_p  = (const float*)d_in[11];
    const float* prelu_a = (const float*)d_in[12];
    const float* lin1_w  = (const float*)d_in[13];
    const float* lin1_b  = (const float*)d_in[14];
    const float* lin2_w  = (const float*)d_in[15];
    const float* lin2_b  = (const float*)d_in[16];
    float* out = (float*)d_out;

    // side stream + fork/join events, created once on the first (non-capturing) call
    static cudaStream_t s2 = nullptr;
    static cudaEvent_t evF = nullptr, evP = nullptr;
    if (!s2) {
        cudaStreamCreateWithFlags(&s2, cudaStreamNonBlocking);
        cudaEventCreateWithFlags(&evF, cudaEventDisableTiming);
        cudaEventCreateWithFlags(&evP, cudaEventDisableTiming);
    }

    k_zerodeg<<<(NPAD + 255) / 256, 256>>>();
    k_init<<<512, 256>>>(ei);
    k_prep<<<10, 128>>>(bn_g, bn_b, bn_m, bn_v, pool_p);

    for (int L = 0; L < 10; L++) {
        int n = NS[L], k = KS[L];
        int eb = L & 1;

        // fork: CSR prep chain on side stream, overlapped with GEMM on main stream
        cudaEventRecord(evF, 0);
        cudaStreamWaitEvent(s2, evF, 0);
        k_tilesum<<<NT[L], 256, 0, s2>>>(L, n, NT[L]);
        k_offsets<<<NT[L], 256, 0, s2>>>(n);
        k_csrfill<<<256, 256, 0, s2>>>(L, eb);
        cudaEventRecord(evP, s2);

        if (L == 0)
            k_rank1<<<1024, 256>>>(x, W1, V1, n);
        else
            k_gemm2<<<dim3((n + 127) / 128, 2), 256>>>(Ws + (size_t)(L - 1) * D * D,
                                                       Vs + (size_t)(L - 1) * D * D, n);

        // join
        cudaStreamWaitEvent(0, evP, 0);

        k_aggepi<<<(n * 32 + 255) / 256, 256>>>(L, n, conv_b + (size_t)L * D,
                                                prelu_a, pool_p + (size_t)L * D);

        int gN = (n + 255) / 256;
        k_topk<<<gN, 256>>>(n, (unsigned)k, gN);

        k_gatherremap<<<(k + 63) / 64, 128>>>(L, k, eb, 1.0f / (float)k);
    }

    k_lin1<<<dim3(5, 8), 256>>>(lin1_w);
    k_lin2<<<1, 256>>>(lin1_b, lin2_w, lin2_b, prelu_a, out);

    (void)in_sizes; (void)n_in; (void)out_size;
}

// round 11
// speedup vs baseline: 3.5167x; 1.1203x over previous
#include <cuda_runtime.h>
#include <math.h>

#define D 128
#define E_TOTAL 640000
#define NMAX 40000
#define NPAD (NMAX + 1024)

static const int NS[10] = {40000,32000,25600,20480,16384,13108,10487,8390,6712,5370};
static const int KS[10] = {32000,25600,20480,16384,13108,10487,8390,6712,5370,4296};
static const int NT[10] = {40,32,25,20,16,13,11,9,7,6};  // (NS+1023)/1024

// ---------------- device scratch ----------------
__device__ float g_h2 [NMAX*D];
__device__ float g_hw [NMAX*D];
__device__ float g_hv [NMAX*D];
__device__ float g_score[NMAX];
__device__ float g_dinv [NMAX];
__device__ __align__(16) int g_degi[NPAD];
__device__ int   g_remap[NMAX];
__device__ int   g_sel  [NMAX];
__device__ int   g_off  [NMAX+1];
__device__ int   g_cur  [NMAX];
__device__ int   g_csr  [E_TOTAL];
__device__ int2  g_edges[2][E_TOTAL];
__device__ int   g_ecnt[11];
__device__ int   g_tilesum[64];
__device__ int   g_tilepref[64];
__device__ unsigned g_hist[3][65536];   // zero at load; k_topk restores zeros after use
__device__ unsigned g_coarse[3][1024];
__device__ unsigned g_selcnt;
__device__ unsigned g_doneB;
__device__ unsigned g_doneC;
__device__ unsigned g_barArr;
__device__ volatile unsigned g_barGen;
__device__ unsigned g_umax[D];
__device__ float g_colsum[D];
__device__ float g_reads[2560];
__device__ float g_z1[1280];
__device__ float g_bnsc[10*D];
__device__ float g_bnsh[10*D];
__device__ float g_pnorm[10];

// ---------------- helpers ----------------
__device__ __forceinline__ unsigned fmap(float f) {
    unsigned b = __float_as_uint(f);
    return (b & 0x80000000u) ? ~b : (b | 0x80000000u);
}
__device__ __forceinline__ float funmap(unsigned u) {
    unsigned b = (u & 0x80000000u) ? (u ^ 0x80000000u) : ~u;
    return __uint_as_float(b);
}
// 48-bit key: score (32) | inverted index (16). larger == better; ties -> smaller index.
__device__ __forceinline__ unsigned long long make_key(float s, int i) {
    return (((unsigned long long)fmap(s)) << 16) | (unsigned)(0xFFFFu - (unsigned)i);
}

__device__ __forceinline__ void mma_tf32(float* c, const unsigned* a, unsigned b0, unsigned b1) {
    asm volatile(
        "mma.sync.aligned.m16n8k8.row.col.f32.tf32.tf32.f32 "
        "{%0,%1,%2,%3}, {%4,%5,%6,%7}, {%8,%9}, {%0,%1,%2,%3};\n"
        : "+f"(c[0]), "+f"(c[1]), "+f"(c[2]), "+f"(c[3])
        : "r"(a[0]), "r"(a[1]), "r"(a[2]), "r"(a[3]), "r"(b0), "r"(b1));
}

// grid barrier: safe only when ALL nb blocks are resident (single wave). Used ONLY
// by k_topk, which runs alone on the device.
__device__ __forceinline__ void gridbar(unsigned nb) {
    __syncthreads();
    if (threadIdx.x == 0) {
        __threadfence();
        unsigned gen = g_barGen;
        if (atomicAdd(&g_barArr, 1u) == nb - 1) {
            g_barArr = 0;
            __threadfence();
            g_barGen = gen + 1;
        } else {
            while (g_barGen == gen) __nanosleep(64);
            __threadfence();
        }
    }
    __syncthreads();
}

// ---------------- init ----------------
__global__ void k_zerodeg() {
    int gid = blockIdx.x * blockDim.x + threadIdx.x;
    if (gid < NPAD) g_degi[gid] = 0;
}

__global__ void k_init(const int* __restrict__ ei) {
    int gid = blockIdx.x * blockDim.x + threadIdx.x;
    int stride = gridDim.x * blockDim.x;
    for (int i = gid; i < E_TOTAL; i += stride) {
        int d = ei[E_TOTAL + i];
        g_edges[0][i] = make_int2(ei[i], d);
        atomicAdd(&g_degi[d], 1);
    }
    if (gid == 0) g_ecnt[0] = E_TOTAL;
}

// fused BN-const precompute + pool-vector norms + z1 zero: grid 10, block 128
__global__ void k_prep(const float* __restrict__ gamma, const float* __restrict__ beta,
                       const float* __restrict__ mean, const float* __restrict__ var,
                       const float* __restrict__ p) {
    int L = blockIdx.x;
    int t = threadIdx.x;
    int idx = L * 128 + t;
    float sc = gamma[idx] / sqrtf(var[idx] + 1e-5f);
    g_bnsc[idx] = sc;
    g_bnsh[idx] = beta[idx] - mean[idx] * sc;
    g_z1[idx] = 0.f;
    __shared__ float sm[128];
    float v = p[idx];
    sm[t] = v * v;
    __syncthreads();
    for (int s = 64; s > 0; s >>= 1) {
        if (t < s) sm[t] += sm[t + s];
        __syncthreads();
    }
    if (t == 0) g_pnorm[L] = sqrtf(sm[0]);
}

// ---------------- side-stream chain ----------------
// edge remap + compaction + next-layer degree accumulation
__global__ void k_remapedges(int L, int ebuf) {
    int gid = blockIdx.x * blockDim.x + threadIdx.x;
    int stride = gridDim.x * blockDim.x;
    int cnt = g_ecnt[L];
    const int2* Ein = g_edges[ebuf];
    int2* Eout = g_edges[ebuf ^ 1];
    for (int i = gid; i < cnt; i += stride) {
        int2 e = Ein[i];
        int ns = g_remap[e.x];
        int nd = g_remap[e.y];
        if (ns >= 0 && nd >= 0) {
            int pos = atomicAdd(&g_ecnt[L + 1], 1);
            Eout[pos] = make_int2(ns, nd);
            atomicAdd(&g_degi[nd], 1);
        }
    }
}

// column max/sum over pooled rows -> g_reads (feeds final MLP only)
__global__ void __launch_bounds__(128) k_readsreduce(int L, int k, float invk) {
    int c = threadIdx.x;
    int r0 = blockIdx.x * 64;
    float lmax = __int_as_float(0xff800000);
    float lsum = 0.f;
    int rend = r0 + 64; if (rend > k) rend = k;
    for (int r = r0; r < rend; r++) {
        int i = g_sel[r];
        float v = g_h2[(size_t)i * 128 + c] * g_score[i];
        lmax = fmaxf(lmax, v);
        lsum += v;
    }
    atomicMax(&g_umax[c], fmap(lmax));
    atomicAdd(&g_colsum[c], lsum);
    __threadfence();
    __shared__ int lastb;
    if (c == 0) {
        unsigned v = atomicAdd(&g_doneB, 1u);
        lastb = (v == gridDim.x - 1);
        if (lastb) g_doneB = 0u;
    }
    __syncthreads();
    if (lastb) {
        g_reads[L * 256 + c] = funmap(g_umax[c]);
        g_reads[L * 256 + 128 + c] = g_colsum[c] * invk;
    }
}

// tile degree sums + per-layer scalar zeroing; last block computes tile prefix.
__global__ void __launch_bounds__(256) k_tilesum(int L, int n, int ntiles) {
    int t = threadIdx.x;
    int bid = blockIdx.x;
    int gid = bid * 256 + t;
    if (gid < 128) { g_umax[gid] = 0u; g_colsum[gid] = 0.f; }
    if (gid == 0) { g_selcnt = 0u; g_ecnt[L + 1] = 0; }

    int base = bid * 1024 + t * 4;
    int4 dv = *(const int4*)&g_degi[base];
    int s = 0;
    if (base + 0 < n) s += dv.x;
    if (base + 1 < n) s += dv.y;
    if (base + 2 < n) s += dv.z;
    if (base + 3 < n) s += dv.w;
#pragma unroll
    for (int off = 16; off > 0; off >>= 1) s += __shfl_xor_sync(0xFFFFFFFFu, s, off);
    __shared__ int ws[8];
    if ((t & 31) == 0) ws[t >> 5] = s;
    __syncthreads();
    if (t == 0) {
        int tot = 0;
#pragma unroll
        for (int j = 0; j < 8; j++) tot += ws[j];
        g_tilesum[bid] = tot;
    }
    __threadfence();
    __shared__ int lastb;
    if (t == 0) {
        unsigned v = atomicAdd(&g_doneC, 1u);
        lastb = (v == (unsigned)ntiles - 1);
        if (lastb) g_doneC = 0u;
    }
    __syncthreads();
    if (lastb && t == 0) {
        int run = 0;
        for (int i = 0; i < ntiles; i++) { g_tilepref[i] = run; run += g_tilesum[i]; }
        g_off[n] = run;
    }
}

// expand per-tile offsets: one block per 1024-node tile
__global__ void __launch_bounds__(256) k_offsets(int n) {
    int t = threadIdx.x;
    int base = blockIdx.x * 1024 + t * 4;
    int4 dv = *(const int4*)&g_degi[base];
    int d0 = (base + 0 < n) ? dv.x : 0;
    int d1 = (base + 1 < n) ? dv.y : 0;
    int d2 = (base + 2 < n) ? dv.z : 0;
    int d3 = (base + 3 < n) ? dv.w : 0;
    int s = d0 + d1 + d2 + d3;
    int lane = t & 31, wid = t >> 5;
    int incl = s;
#pragma unroll
    for (int off = 1; off < 32; off <<= 1) {
        int v = __shfl_up_sync(0xFFFFFFFFu, incl, off);
        if (lane >= off) incl += v;
    }
    __shared__ int wsum[8], wpref[8];
    if (lane == 31) wsum[wid] = incl;
    __syncthreads();
    if (t < 8) {
        int pp = 0;
#pragma unroll
        for (int j = 0; j < 8; j++) {
            int u = wsum[j];
            if (j < t) pp += u;
        }
        wpref[t] = pp;
    }
    __syncthreads();
    int excl = incl - s + wpref[wid] + g_tilepref[blockIdx.x];
    int dd[4] = {d0, d1, d2, d3};
#pragma unroll
    for (int j = 0; j < 4; j++) {
        int idx = base + j;
        if (idx < n) {
            g_off[idx] = excl;
            g_cur[idx] = excl;
            g_dinv[idx] = (dd[j] > 0) ? (1.0f / sqrtf((float)dd[j])) : 0.f;
            excl += dd[j];
        }
    }
}

// CSR fill: 1 atomic per edge, grid-stride
__global__ void k_csrfill(int L, int ebuf) {
    int gid = blockIdx.x * blockDim.x + threadIdx.x;
    int stride = gridDim.x * blockDim.x;
    int cnt = g_ecnt[L];
    const int2* E = g_edges[ebuf];
    for (int i = gid; i < cnt; i += stride) {
        int2 e = E[i];
        int pos = atomicAdd(&g_cur[e.y], 1);
        g_csr[pos] = e.x;
    }
}

// layer 0: hw = x * W1, hv = x * V1
__global__ void k_rank1(const float* __restrict__ x, const float* __restrict__ w,
                        const float* __restrict__ v, int n) {
    int gid = blockIdx.x * blockDim.x + threadIdx.x;
    int stride = gridDim.x * blockDim.x;
    const float4* w4 = (const float4*)w;
    const float4* v4 = (const float4*)v;
    float4* ow = (float4*)g_hw;
    float4* ov = (float4*)g_hv;
    for (int i = gid; i < n * 32; i += stride) {
        float xv = x[i >> 5];
        float4 wv = w4[i & 31];
        float4 vv = v4[i & 31];
        ow[i] = make_float4(xv * wv.x, xv * wv.y, xv * wv.z, xv * wv.w);
        ov[i] = make_float4(xv * vv.x, xv * vv.y, xv * vv.z, xv * vv.w);
    }
}

// agg (warp per node, register acc) + fused conv epilogue + BN + PReLU + score
__global__ void k_aggepi(int L, int n, const float* __restrict__ convb,
                         const float* __restrict__ pa, const float* __restrict__ p) {
    int gid = blockIdx.x * blockDim.x + threadIdx.x;
    int node = gid >> 5;
    int lane = gid & 31;
    if (node >= n) return;
    int st = g_off[node], en = g_off[node + 1];
    float dd = g_dinv[node];
    float4 acc = make_float4(0.f, 0.f, 0.f, 0.f);
    const float4* hw4 = (const float4*)g_hw;
    for (int j = st; j < en; j++) {
        int s = g_csr[j];
        float c = g_dinv[s] * dd;
        float4 v = hw4[(size_t)s * 32 + lane];
        acc.x += v.x * c; acc.y += v.y * c; acc.z += v.z * c; acc.w += v.w * c;
    }
    float a = pa[0];
    float4 hv = ((const float4*)g_hv)[(size_t)node * 32 + lane];
    float4 cb = ((const float4*)convb)[lane];
    float4 s4 = ((const float4*)(g_bnsc + L * 128))[lane];
    float4 h4 = ((const float4*)(g_bnsh + L * 128))[lane];
    float4 p4 = ((const float4*)p)[lane];
    float o[4] = {acc.x + hv.x + cb.x, acc.y + hv.y + cb.y,
                  acc.z + hv.z + cb.z, acc.w + hv.w + cb.w};
    float bs[4] = {s4.x, s4.y, s4.z, s4.w};
    float bh[4] = {h4.x, h4.y, h4.z, h4.w};
    float pv[4] = {p4.x, p4.y, p4.z, p4.w};
    float sp = 0.f;
#pragma unroll
    for (int j = 0; j < 4; j++) {
        float v = fmaxf(o[j], 0.f);
        v = v * bs[j] + bh[j];
        v = v > 0.f ? v : a * v;
        o[j] = v;
        sp += v * pv[j];
    }
    ((float4*)g_h2)[(size_t)node * 32 + lane] = make_float4(o[0], o[1], o[2], o[3]);
#pragma unroll
    for (int off = 16; off > 0; off >>= 1) sp += __shfl_xor_sync(0xFFFFFFFFu, sp, off);
    if (lane == 0) g_score[node] = tanhf(sp / g_pnorm[L]);
}

// ---------------- TF32 tensor-core GEMM with indirect pooled A ----------------
// A row r = g_h2[g_sel[r]] * g_score[g_sel[r]]   (pooled output of previous layer)
#define GBK 16
__global__ void __launch_bounds__(256) k_gemm2(const float* __restrict__ W,
                                               const float* __restrict__ V, int n) {
    __shared__ float Ah[GBK][136], Al[GBK][136];
    __shared__ float Bh[GBK][136], Bl[GBK][136];
    const float* B = blockIdx.y ? V : W;
    float* out = blockIdx.y ? g_hv : g_hw;
    int tid = threadIdx.x;
    int lane = tid & 31;
    int warp = tid >> 5;
    int wm = warp >> 2;
    int wn = warp & 3;
    int group = lane >> 2;
    int tig = lane & 3;
    int row0 = blockIdx.x * 128;

    float acc[4][4][4];
#pragma unroll
    for (int mt = 0; mt < 4; mt++)
#pragma unroll
        for (int nt = 0; nt < 4; nt++)
#pragma unroll
            for (int e = 0; e < 4; e++) acc[mt][nt][e] = 0.f;

    for (int k0 = 0; k0 < 128; k0 += GBK) {
#pragma unroll
        for (int q = 0; q < 2; q++) {
            int f = tid + 256 * q;
            int m = f >> 2;
            int kq = (f & 3) * 4;
            int gr = row0 + m; if (gr >= n) gr = n - 1;
            int src = g_sel[gr];
            float sc = g_score[src];
            float4 v = *(const float4*)(g_h2 + (size_t)src * 128 + k0 + kq);
            float xs[4] = {v.x * sc, v.y * sc, v.z * sc, v.w * sc};
#pragma unroll
            for (int j = 0; j < 4; j++) {
                float xv = xs[j];
                float hf = __uint_as_float(__float_as_uint(xv) & 0xFFFFE000u);
                Ah[kq + j][m] = hf;
                Al[kq + j][m] = xv - hf;
            }
        }
#pragma unroll
        for (int q = 0; q < 2; q++) {
            int f = tid + 256 * q;
            int kk = f >> 5;
            int nq = (f & 31) * 4;
            float4 v = *(const float4*)(B + (size_t)(k0 + kk) * 128 + nq);
            float xs[4] = {v.x, v.y, v.z, v.w};
            float hi[4], lo[4];
#pragma unroll
            for (int j = 0; j < 4; j++) {
                hi[j] = __uint_as_float(__float_as_uint(xs[j]) & 0xFFFFE000u);
                lo[j] = xs[j] - hi[j];
            }
            *(float4*)&Bh[kk][nq] = make_float4(hi[0], hi[1], hi[2], hi[3]);
            *(float4*)&Bl[kk][nq] = make_float4(lo[0], lo[1], lo[2], lo[3]);
        }
        __syncthreads();
#pragma unroll
        for (int ks = 0; ks < GBK; ks += 8) {
            unsigned ah[4][4], al[4][4];
#pragma unroll
            for (int mt = 0; mt < 4; mt++) {
                int m = wm * 64 + mt * 16 + group;
                ah[mt][0] = __float_as_uint(Ah[ks + tig][m]);
                ah[mt][1] = __float_as_uint(Ah[ks + tig][m + 8]);
                ah[mt][2] = __float_as_uint(Ah[ks + tig + 4][m]);
                ah[mt][3] = __float_as_uint(Ah[ks + tig + 4][m + 8]);
                al[mt][0] = __float_as_uint(Al[ks + tig][m]);
                al[mt][1] = __float_as_uint(Al[ks + tig][m + 8]);
                al[mt][2] = __float_as_uint(Al[ks + tig + 4][m]);
                al[mt][3] = __float_as_uint(Al[ks + tig + 4][m + 8]);
            }
#pragma unroll
            for (int nt = 0; nt < 4; nt++) {
                int c = wn * 32 + nt * 8 + group;
                unsigned bh0 = __float_as_uint(Bh[ks + tig][c]);
                unsigned bh1 = __float_as_uint(Bh[ks + tig + 4][c]);
                unsigned bl0 = __float_as_uint(Bl[ks + tig][c]);
                unsigned bl1 = __float_as_uint(Bl[ks + tig + 4][c]);
#pragma unroll
                for (int mt = 0; mt < 4; mt++) {
                    mma_tf32(acc[mt][nt], ah[mt], bh0, bh1);
                    mma_tf32(acc[mt][nt], ah[mt], bl0, bl1);
                    mma_tf32(acc[mt][nt], al[mt], bh0, bh1);
                }
            }
        }
        __syncthreads();
    }

#pragma unroll
    for (int mt = 0; mt < 4; mt++) {
#pragma unroll
        for (int h = 0; h < 2; h++) {
            int r = row0 + wm * 64 + mt * 16 + group + 8 * h;
            if (r >= n) continue;
#pragma unroll
            for (int nt = 0; nt < 4; nt++) {
                int cb = wn * 32 + nt * 8 + tig * 2;
                *(float2*)(out + (size_t)r * 128 + cb) =
                    make_float2(acc[mt][nt][2 * h], acc[mt][nt][2 * h + 1]);
            }
        }
    }
}

// ---------------- fused top-k: 3 radix passes + self-cleaning hist + select ----------------
__device__ __forceinline__ void scan_pass(int pass, unsigned kr_in, unsigned* kr_out,
                                          unsigned long long* prefix, int shift) {
    __shared__ unsigned arr[256], rev[256];
    __shared__ unsigned sh_dig, sh_kr;
    int t = threadIdx.x;
    int cb0 = t * 4;
    unsigned s = 0;
#pragma unroll
    for (int q = 0; q < 4; q++) s += g_coarse[pass][cb0 + q];
    arr[t] = s;
    __syncthreads();
    rev[t] = arr[255 - t];
    __syncthreads();
    for (int off = 1; off < 256; off <<= 1) {
        unsigned v = (t >= off) ? rev[t - off] : 0u;
        __syncthreads();
        rev[t] += v;
        __syncthreads();
    }
    unsigned suf = rev[255 - t];
    unsigned above = suf - s;
    if (above < kr_in && suf >= kr_in) {   // exactly one thread
        unsigned running = above;
        for (int b = 3; b >= 0; b--) {
            unsigned c = g_coarse[pass][cb0 + b];
            if (running + c >= kr_in) {
                int fb = (cb0 + b) * 64;
                for (int d = 63; d >= 0; d--) {
                    unsigned fc = g_hist[pass][fb + d];
                    if (running + fc >= kr_in) {
                        sh_kr = kr_in - running;
                        sh_dig = (unsigned)(fb + d);
                        break;
                    }
                    running += fc;
                }
                break;
            }
            running += c;
        }
    }
    __syncthreads();
    *prefix |= ((unsigned long long)sh_dig) << shift;
    *kr_out = sh_kr;
    __syncthreads();
}

__global__ void __launch_bounds__(256) k_topk(int n, unsigned k, int nb) {
    int t = threadIdx.x;
    int i = blockIdx.x * 256 + t;
    bool valid = (i < n);
    unsigned long long key = valid ? make_key(g_score[i], i) : 0ull;
    unsigned long long prefix = 0;
    unsigned kr = k;
    unsigned digits[3];
    int actmask = 0;
#pragma unroll
    for (int pass = 0; pass < 3; pass++) {
        int shift = 32 - 16 * pass;
        bool act = valid && (pass == 0 || ((key >> (shift + 16)) == (prefix >> (shift + 16))));
        if (act) {
            unsigned digit = (unsigned)((key >> shift) & 0xFFFFull);
            digits[pass] = digit;
            actmask |= 1 << pass;
            atomicAdd(&g_hist[pass][digit], 1u);
            atomicAdd(&g_coarse[pass][digit >> 6], 1u);
        }
        gridbar((unsigned)nb);
        scan_pass(pass, kr, &kr, &prefix, shift);
    }
    gridbar((unsigned)nb);  // all scans done before clearing
    if (valid) {
#pragma unroll
        for (int pass = 0; pass < 3; pass++) {
            if (actmask & (1 << pass)) {
                g_hist[pass][digits[pass]] = 0u;
                g_coarse[pass][digits[pass] >> 6] = 0u;
            }
        }
        g_degi[i] = 0;  // degrees consumed; clear for next layer
        if (key >= prefix) {
            unsigned pos = atomicAdd(&g_selcnt, 1u);
            g_sel[pos] = i;
            g_remap[i] = (int)pos;
        } else {
            g_remap[i] = -1;
        }
    }
}

// ---------------- MLP head ----------------
__global__ void k_lin1(const float* __restrict__ W) {
    int col = blockIdx.x * 256 + threadIdx.x;
    int r0 = blockIdx.y * 320;
    float acc = 0.f;
    for (int r = r0; r < r0 + 320; r++) acc += g_reads[r] * W[(size_t)r * 1280 + col];
    atomicAdd(&g_z1[col], acc);
}

__global__ void k_lin2(const float* __restrict__ b1, const float* __restrict__ W2,
                       const float* __restrict__ b2, const float* __restrict__ pa,
                       float* __restrict__ out) {
    int tid = threadIdx.x;
    float a = pa[0];
    float acc[8] = {0, 0, 0, 0, 0, 0, 0, 0};
    for (int i = tid; i < 1280; i += 256) {
        float v = g_z1[i] + b1[i];
        v = v > 0.f ? v : a * v;
#pragma unroll
        for (int j = 0; j < 8; j++) acc[j] += v * W2[i * 8 + j];
    }
    __shared__ float red[256][8];
#pragma unroll
    for (int j = 0; j < 8; j++) red[tid][j] = acc[j];
    __syncthreads();
    for (int s = 128; s > 0; s >>= 1) {
        if (tid < s)
#pragma unroll
            for (int j = 0; j < 8; j++) red[tid][j] += red[tid + s][j];
        __syncthreads();
    }
    if (tid == 0) {
        float z[8];
#pragma unroll
        for (int j = 0; j < 8; j++) {
            float s = red[0][j] + b2[j];
            z[j] = s > 0.f ? s : a * s;
        }
        float mn = z[0];
#pragma unroll
        for (int j = 1; j < 8; j++) mn = fminf(mn, z[j]);
#pragma unroll
        for (int j = 0; j < 8; j++) z[j] -= mn;
        float mx = z[0];
#pragma unroll
        for (int j = 1; j < 8; j++) mx = fmaxf(mx, z[j]);
#pragma unroll
        for (int j = 0; j < 8; j++) z[j] /= mx;
        float sm = 0.f;
#pragma unroll
        for (int j = 0; j < 8; j++) sm += z[j];
#pragma unroll
        for (int j = 0; j < 8; j++) out[j] = z[j] / sm;
    }
}

// ---------------- launcher ----------------
extern "C" void kernel_launch(void* const* d_in, const int* in_sizes, int n_in,
                              void* d_out, int out_size) {
    const float* x       = (const float*)d_in[0];
    const int*   ei      = (const int*)  d_in[1];
    const float* W1      = (const float*)d_in[2];
    const float* V1      = (const float*)d_in[3];
    const float* Ws      = (const float*)d_in[4];
    const float* Vs      = (const float*)d_in[5];
    const float* conv_b  = (const float*)d_in[6];
    const float* bn_g    = (const float*)d_in[7];
    const float* bn_b    = (const float*)d_in[8];
    const float* bn_m    = (const float*)d_in[9];
    const float* bn_v    = (const float*)d_in[10];
    const float* pool_p  = (const float*)d_in[11];
    const float* prelu_a = (const float*)d_in[12];
    const float* lin1_w  = (const float*)d_in[13];
    const float* lin1_b  = (const float*)d_in[14];
    const float* lin2_w  = (const float*)d_in[15];
    const float* lin2_b  = (const float*)d_in[16];
    float* out = (float*)d_out;

    // side stream + fork/join events, created once on the first (non-capturing) call
    static cudaStream_t s2 = nullptr;
    static cudaEvent_t evF = nullptr, evP = nullptr;
    if (!s2) {
        cudaStreamCreateWithFlags(&s2, cudaStreamNonBlocking);
        cudaEventCreateWithFlags(&evF, cudaEventDisableTiming);
        cudaEventCreateWithFlags(&evP, cudaEventDisableTiming);
    }

    // pre-loop: edges/degrees, constants, layer-0 CSR, layer-0 rank-1 "GEMM"
    k_zerodeg<<<(NPAD + 255) / 256, 256>>>();
    k_init<<<512, 256>>>(ei);
    k_prep<<<10, 128>>>(bn_g, bn_b, bn_m, bn_v, pool_p);
    k_tilesum<<<NT[0], 256>>>(0, NS[0], NT[0]);
    k_offsets<<<NT[0], 256>>>(NS[0]);
    k_csrfill<<<256, 256>>>(0, 0);
    k_rank1<<<1024, 256>>>(x, W1, V1, NS[0]);

    for (int L = 0; L < 10; L++) {
        int n = NS[L], k = KS[L];
        int eb = L & 1;

        if (L > 0) cudaStreamWaitEvent(0, evP, 0);   // CSR(L) ready

        k_aggepi<<<(n * 32 + 255) / 256, 256>>>(L, n, conv_b + (size_t)L * D,
                                                prelu_a, pool_p + (size_t)L * D);

        int gN = (n + 255) / 256;
        k_topk<<<gN, 256>>>(n, (unsigned)k, gN);

        // fork: side chain (edge remap, reads reduce, next-layer CSR prep)
        cudaEventRecord(evF, 0);
        cudaStreamWaitEvent(s2, evF, 0);
        if (L < 9) {
            k_remapedges<<<256, 256, 0, s2>>>(L, eb);
            k_readsreduce<<<(k + 63) / 64, 128, 0, s2>>>(L, k, 1.0f / (float)k);
            k_tilesum<<<NT[L + 1], 256, 0, s2>>>(L + 1, k, NT[L + 1]);
            k_offsets<<<NT[L + 1], 256, 0, s2>>>(k);
            k_csrfill<<<256, 256, 0, s2>>>(L + 1, eb ^ 1);
        } else {
            k_readsreduce<<<(k + 63) / 64, 128, 0, s2>>>(L, k, 1.0f / (float)k);
        }
        cudaEventRecord(evP, s2);

        // main: next layer's GEMM reads pooled rows via g_sel/g_score indirection
        if (L < 9)
            k_gemm2<<<dim3((k + 127) / 128, 2), 256>>>(Ws + (size_t)L * D * D,
                                                       Vs + (size_t)L * D * D, k);
    }

    cudaStreamWaitEvent(0, evP, 0);   // reads(9) complete
    k_lin1<<<dim3(5, 8), 256>>>(lin1_w);
    k_lin2<<<1, 256>>>(lin1_b, lin2_w, lin2_b, prelu_a, out);

    (void)in_sizes; (void)n_in; (void)out_size;
}

// round 12
// speedup vs baseline: 3.6774x; 1.0457x over previous
#include <cuda_runtime.h>
#include <math.h>

#define D 128
#define E_TOTAL 640000
#define NMAX 40000
#define NPAD (NMAX + 1024)

static const int NS[10] = {40000,32000,25600,20480,16384,13108,10487,8390,6712,5370};
static const int KS[10] = {32000,25600,20480,16384,13108,10487,8390,6712,5370,4296};
static const int NT[10] = {40,32,25,20,16,13,11,9,7,6};  // (NS+1023)/1024

// ---------------- device scratch ----------------
__device__ float g_h2 [NMAX*D];
__device__ float g_hw [NMAX*D];
__device__ float g_hv [NMAX*D];
__device__ float g_score[NMAX];
__device__ float g_dinv [NMAX];
__device__ __align__(16) int g_degi[NPAD];
__device__ int   g_remap[NMAX];
__device__ int   g_sel  [NMAX];
__device__ int   g_off  [NMAX+1];
__device__ int   g_cur  [NMAX];
__device__ int   g_csr  [E_TOTAL];
__device__ int2  g_edges[2][E_TOTAL];
__device__ int   g_ecnt[11];
__device__ int   g_tilesum[64];
__device__ int   g_tilepref[64];
__device__ unsigned g_hist[3][65536];   // zero at load; k_topk restores zeros after use
__device__ unsigned g_coarse[3][1024];
__device__ unsigned g_selcnt;
__device__ unsigned g_doneB;
__device__ unsigned g_doneC;
__device__ unsigned g_barArr;
__device__ volatile unsigned g_barGen;
__device__ unsigned g_umax[D];
__device__ float g_colsum[D];
__device__ float g_reads[2560];
__device__ float g_z1[1280];
__device__ float g_bnsc[10*D];
__device__ float g_bnsh[10*D];
__device__ float g_pnorm[10];

// ---------------- helpers ----------------
__device__ __forceinline__ unsigned fmap(float f) {
    unsigned b = __float_as_uint(f);
    return (b & 0x80000000u) ? ~b : (b | 0x80000000u);
}
__device__ __forceinline__ float funmap(unsigned u) {
    unsigned b = (u & 0x80000000u) ? (u ^ 0x80000000u) : ~u;
    return __uint_as_float(b);
}
// 48-bit key: score (32) | inverted index (16). larger == better; ties -> smaller index.
__device__ __forceinline__ unsigned long long make_key(float s, int i) {
    return (((unsigned long long)fmap(s)) << 16) | (unsigned)(0xFFFFu - (unsigned)i);
}

__device__ __forceinline__ void mma_tf32(float* c, const unsigned* a, unsigned b0, unsigned b1) {
    asm volatile(
        "mma.sync.aligned.m16n8k8.row.col.f32.tf32.tf32.f32 "
        "{%0,%1,%2,%3}, {%4,%5,%6,%7}, {%8,%9}, {%0,%1,%2,%3};\n"
        : "+f"(c[0]), "+f"(c[1]), "+f"(c[2]), "+f"(c[3])
        : "r"(a[0]), "r"(a[1]), "r"(a[2]), "r"(a[3]), "r"(b0), "r"(b1));
}

// grid barrier: safe only when ALL nb blocks are resident (single wave). Used ONLY
// by k_topk, which runs alone on the device.
__device__ __forceinline__ void gridbar(unsigned nb) {
    __syncthreads();
    if (threadIdx.x == 0) {
        __threadfence();
        unsigned gen = g_barGen;
        if (atomicAdd(&g_barArr, 1u) == nb - 1) {
            g_barArr = 0;
            __threadfence();
            g_barGen = gen + 1;
        } else {
            while (g_barGen == gen) __nanosleep(64);
            __threadfence();
        }
    }
    __syncthreads();
}

// ---------------- init ----------------
__global__ void k_zerodeg() {
    int gid = blockIdx.x * blockDim.x + threadIdx.x;
    if (gid < NPAD) g_degi[gid] = 0;
}

__global__ void k_init(const int* __restrict__ ei) {
    int gid = blockIdx.x * blockDim.x + threadIdx.x;
    int stride = gridDim.x * blockDim.x;
    for (int i = gid; i < E_TOTAL; i += stride) {
        int d = ei[E_TOTAL + i];
        g_edges[0][i] = make_int2(ei[i], d);
        atomicAdd(&g_degi[d], 1);
    }
    if (gid == 0) g_ecnt[0] = E_TOTAL;
}

// fused BN-const precompute + pool-vector norms + z1 zero: grid 10, block 128
__global__ void k_prep(const float* __restrict__ gamma, const float* __restrict__ beta,
                       const float* __restrict__ mean, const float* __restrict__ var,
                       const float* __restrict__ p) {
    int L = blockIdx.x;
    int t = threadIdx.x;
    int idx = L * 128 + t;
    float sc = gamma[idx] / sqrtf(var[idx] + 1e-5f);
    g_bnsc[idx] = sc;
    g_bnsh[idx] = beta[idx] - mean[idx] * sc;
    g_z1[idx] = 0.f;
    __shared__ float sm[128];
    float v = p[idx];
    sm[t] = v * v;
    __syncthreads();
    for (int s = 64; s > 0; s >>= 1) {
        if (t < s) sm[t] += sm[t + s];
        __syncthreads();
    }
    if (t == 0) g_pnorm[L] = sqrtf(sm[0]);
}

// ---------------- side-stream chain ----------------
// edge remap + compaction + next-layer degrees, warp-aggregated pack counter
__global__ void k_remapedges(int L, int ebuf) {
    int gid = blockIdx.x * blockDim.x + threadIdx.x;
    int stride = gridDim.x * blockDim.x;
    int lane = threadIdx.x & 31;
    int cnt = g_ecnt[L];
    const int2* Ein = g_edges[ebuf];
    int2* Eout = g_edges[ebuf ^ 1];
    int iters = (cnt + stride - 1) / stride;   // uniform trip count across the grid
    for (int it = 0; it < iters; it++) {
        int i = gid + it * stride;
        int ns = -1, nd = -1;
        if (i < cnt) {
            int2 e = Ein[i];
            ns = g_remap[e.x];
            nd = g_remap[e.y];
        }
        bool keep = (ns >= 0) && (nd >= 0);
        unsigned bm = __ballot_sync(0xFFFFFFFFu, keep);
        if (keep) {
            int leader = __ffs(bm) - 1;
            unsigned base;
            if (lane == leader) base = (unsigned)atomicAdd(&g_ecnt[L + 1], __popc(bm));
            base = __shfl_sync(bm, base, leader);
            unsigned pos = base + __popc(bm & ((1u << lane) - 1u));
            Eout[pos] = make_int2(ns, nd);
            atomicAdd(&g_degi[nd], 1);
        }
    }
}

// column max/sum over pooled rows -> g_reads (feeds final MLP only)
__global__ void __launch_bounds__(128) k_readsreduce(int L, int k, float invk) {
    int c = threadIdx.x;
    int r0 = blockIdx.x * 64;
    float lmax = __int_as_float(0xff800000);
    float lsum = 0.f;
    int rend = r0 + 64; if (rend > k) rend = k;
    for (int r = r0; r < rend; r++) {
        int i = g_sel[r];
        float v = g_h2[(size_t)i * 128 + c] * g_score[i];
        lmax = fmaxf(lmax, v);
        lsum += v;
    }
    atomicMax(&g_umax[c], fmap(lmax));
    atomicAdd(&g_colsum[c], lsum);
    __threadfence();
    __shared__ int lastb;
    if (c == 0) {
        unsigned v = atomicAdd(&g_doneB, 1u);
        lastb = (v == gridDim.x - 1);
        if (lastb) g_doneB = 0u;
    }
    __syncthreads();
    if (lastb) {
        g_reads[L * 256 + c] = funmap(g_umax[c]);
        g_reads[L * 256 + 128 + c] = g_colsum[c] * invk;
    }
}

// tile degree sums + per-layer scalar zeroing; last block computes tile prefix.
__global__ void __launch_bounds__(256) k_tilesum(int L, int n, int ntiles) {
    int t = threadIdx.x;
    int bid = blockIdx.x;
    int gid = bid * 256 + t;
    if (gid < 128) { g_umax[gid] = 0u; g_colsum[gid] = 0.f; }
    if (gid == 0) { g_selcnt = 0u; g_ecnt[L + 1] = 0; }

    int base = bid * 1024 + t * 4;
    int4 dv = *(const int4*)&g_degi[base];
    int s = 0;
    if (base + 0 < n) s += dv.x;
    if (base + 1 < n) s += dv.y;
    if (base + 2 < n) s += dv.z;
    if (base + 3 < n) s += dv.w;
#pragma unroll
    for (int off = 16; off > 0; off >>= 1) s += __shfl_xor_sync(0xFFFFFFFFu, s, off);
    __shared__ int ws[8];
    if ((t & 31) == 0) ws[t >> 5] = s;
    __syncthreads();
    if (t == 0) {
        int tot = 0;
#pragma unroll
        for (int j = 0; j < 8; j++) tot += ws[j];
        g_tilesum[bid] = tot;
    }
    __threadfence();
    __shared__ int lastb;
    if (t == 0) {
        unsigned v = atomicAdd(&g_doneC, 1u);
        lastb = (v == (unsigned)ntiles - 1);
        if (lastb) g_doneC = 0u;
    }
    __syncthreads();
    if (lastb && t == 0) {
        int run = 0;
        for (int i = 0; i < ntiles; i++) { g_tilepref[i] = run; run += g_tilesum[i]; }
        g_off[n] = run;
    }
}

// expand per-tile offsets: one block per 1024-node tile
__global__ void __launch_bounds__(256) k_offsets(int n) {
    int t = threadIdx.x;
    int base = blockIdx.x * 1024 + t * 4;
    int4 dv = *(const int4*)&g_degi[base];
    int d0 = (base + 0 < n) ? dv.x : 0;
    int d1 = (base + 1 < n) ? dv.y : 0;
    int d2 = (base + 2 < n) ? dv.z : 0;
    int d3 = (base + 3 < n) ? dv.w : 0;
    int s = d0 + d1 + d2 + d3;
    int lane = t & 31, wid = t >> 5;
    int incl = s;
#pragma unroll
    for (int off = 1; off < 32; off <<= 1) {
        int v = __shfl_up_sync(0xFFFFFFFFu, incl, off);
        if (lane >= off) incl += v;
    }
    __shared__ int wsum[8], wpref[8];
    if (lane == 31) wsum[wid] = incl;
    __syncthreads();
    if (t < 8) {
        int pp = 0;
#pragma unroll
        for (int j = 0; j < 8; j++) {
            int u = wsum[j];
            if (j < t) pp += u;
        }
        wpref[t] = pp;
    }
    __syncthreads();
    int excl = incl - s + wpref[wid] + g_tilepref[blockIdx.x];
    int dd[4] = {d0, d1, d2, d3};
#pragma unroll
    for (int j = 0; j < 4; j++) {
        int idx = base + j;
        if (idx < n) {
            g_off[idx] = excl;
            g_cur[idx] = excl;
            g_dinv[idx] = (dd[j] > 0) ? (1.0f / sqrtf((float)dd[j])) : 0.f;
            excl += dd[j];
        }
    }
}

// CSR fill: 1 atomic per edge, grid-stride (addresses mostly distinct -> no aggregation)
__global__ void k_csrfill(int L, int ebuf) {
    int gid = blockIdx.x * blockDim.x + threadIdx.x;
    int stride = gridDim.x * blockDim.x;
    int cnt = g_ecnt[L];
    const int2* E = g_edges[ebuf];
    for (int i = gid; i < cnt; i += stride) {
        int2 e = E[i];
        int pos = atomicAdd(&g_cur[e.y], 1);
        g_csr[pos] = e.x;
    }
}

// layer 0: hw = x * W1, hv = x * V1
__global__ void k_rank1(const float* __restrict__ x, const float* __restrict__ w,
                        const float* __restrict__ v, int n) {
    int gid = blockIdx.x * blockDim.x + threadIdx.x;
    int stride = gridDim.x * blockDim.x;
    const float4* w4 = (const float4*)w;
    const float4* v4 = (const float4*)v;
    float4* ow = (float4*)g_hw;
    float4* ov = (float4*)g_hv;
    for (int i = gid; i < n * 32; i += stride) {
        float xv = x[i >> 5];
        float4 wv = w4[i & 31];
        float4 vv = v4[i & 31];
        ow[i] = make_float4(xv * wv.x, xv * wv.y, xv * wv.z, xv * wv.w);
        ov[i] = make_float4(xv * vv.x, xv * vv.y, xv * vv.z, xv * vv.w);
    }
}

// agg (warp per node, register acc) + fused conv epilogue + BN + PReLU + score
__global__ void k_aggepi(int L, int n, const float* __restrict__ convb,
                         const float* __restrict__ pa, const float* __restrict__ p) {
    int gid = blockIdx.x * blockDim.x + threadIdx.x;
    int node = gid >> 5;
    int lane = gid & 31;
    if (node >= n) return;
    int st = g_off[node], en = g_off[node + 1];
    float dd = g_dinv[node];
    float4 acc = make_float4(0.f, 0.f, 0.f, 0.f);
    const float4* hw4 = (const float4*)g_hw;
    for (int j = st; j < en; j++) {
        int s = g_csr[j];
        float c = g_dinv[s] * dd;
        float4 v = hw4[(size_t)s * 32 + lane];
        acc.x += v.x * c; acc.y += v.y * c; acc.z += v.z * c; acc.w += v.w * c;
    }
    float a = pa[0];
    float4 hv = ((const float4*)g_hv)[(size_t)node * 32 + lane];
    float4 cb = ((const float4*)convb)[lane];
    float4 s4 = ((const float4*)(g_bnsc + L * 128))[lane];
    float4 h4 = ((const float4*)(g_bnsh + L * 128))[lane];
    float4 p4 = ((const float4*)p)[lane];
    float o[4] = {acc.x + hv.x + cb.x, acc.y + hv.y + cb.y,
                  acc.z + hv.z + cb.z, acc.w + hv.w + cb.w};
    float bs[4] = {s4.x, s4.y, s4.z, s4.w};
    float bh[4] = {h4.x, h4.y, h4.z, h4.w};
    float pv[4] = {p4.x, p4.y, p4.z, p4.w};
    float sp = 0.f;
#pragma unroll
    for (int j = 0; j < 4; j++) {
        float v = fmaxf(o[j], 0.f);
        v = v * bs[j] + bh[j];
        v = v > 0.f ? v : a * v;
        o[j] = v;
        sp += v * pv[j];
    }
    ((float4*)g_h2)[(size_t)node * 32 + lane] = make_float4(o[0], o[1], o[2], o[3]);
#pragma unroll
    for (int off = 16; off > 0; off >>= 1) sp += __shfl_xor_sync(0xFFFFFFFFu, sp, off);
    if (lane == 0) g_score[node] = tanhf(sp / g_pnorm[L]);
}

// ---------------- TF32 tensor-core GEMM with indirect pooled A ----------------
// A row r = g_h2[g_sel[r]] * g_score[g_sel[r]]   (pooled output of previous layer)
#define GBK 16
__global__ void __launch_bounds__(256) k_gemm2(const float* __restrict__ W,
                                               const float* __restrict__ V, int n) {
    __shared__ float Ah[GBK][136], Al[GBK][136];
    __shared__ float Bh[GBK][136], Bl[GBK][136];
    const float* B = blockIdx.y ? V : W;
    float* out = blockIdx.y ? g_hv : g_hw;
    int tid = threadIdx.x;
    int lane = tid & 31;
    int warp = tid >> 5;
    int wm = warp >> 2;
    int wn = warp & 3;
    int group = lane >> 2;
    int tig = lane & 3;
    int row0 = blockIdx.x * 128;

    float acc[4][4][4];
#pragma unroll
    for (int mt = 0; mt < 4; mt++)
#pragma unroll
        for (int nt = 0; nt < 4; nt++)
#pragma unroll
            for (int e = 0; e < 4; e++) acc[mt][nt][e] = 0.f;

    for (int k0 = 0; k0 < 128; k0 += GBK) {
#pragma unroll
        for (int q = 0; q < 2; q++) {
            int f = tid + 256 * q;
            int m = f >> 2;
            int kq = (f & 3) * 4;
            int gr = row0 + m; if (gr >= n) gr = n - 1;
            int src = g_sel[gr];
            float sc = g_score[src];
            float4 v = *(const float4*)(g_h2 + (size_t)src * 128 + k0 + kq);
            float xs[4] = {v.x * sc, v.y * sc, v.z * sc, v.w * sc};
#pragma unroll
            for (int j = 0; j < 4; j++) {
                float xv = xs[j];
                float hf = __uint_as_float(__float_as_uint(xv) & 0xFFFFE000u);
                Ah[kq + j][m] = hf;
                Al[kq + j][m] = xv - hf;
            }
        }
#pragma unroll
        for (int q = 0; q < 2; q++) {
            int f = tid + 256 * q;
            int kk = f >> 5;
            int nq = (f & 31) * 4;
            float4 v = *(const float4*)(B + (size_t)(k0 + kk) * 128 + nq);
            float xs[4] = {v.x, v.y, v.z, v.w};
            float hi[4], lo[4];
#pragma unroll
            for (int j = 0; j < 4; j++) {
                hi[j] = __uint_as_float(__float_as_uint(xs[j]) & 0xFFFFE000u);
                lo[j] = xs[j] - hi[j];
            }
            *(float4*)&Bh[kk][nq] = make_float4(hi[0], hi[1], hi[2], hi[3]);
            *(float4*)&Bl[kk][nq] = make_float4(lo[0], lo[1], lo[2], lo[3]);
        }
        __syncthreads();
#pragma unroll
        for (int ks = 0; ks < GBK; ks += 8) {
            unsigned ah[4][4], al[4][4];
#pragma unroll
            for (int mt = 0; mt < 4; mt++) {
                int m = wm * 64 + mt * 16 + group;
                ah[mt][0] = __float_as_uint(Ah[ks + tig][m]);
                ah[mt][1] = __float_as_uint(Ah[ks + tig][m + 8]);
                ah[mt][2] = __float_as_uint(Ah[ks + tig + 4][m]);
                ah[mt][3] = __float_as_uint(Ah[ks + tig + 4][m + 8]);
                al[mt][0] = __float_as_uint(Al[ks + tig][m]);
                al[mt][1] = __float_as_uint(Al[ks + tig][m + 8]);
                al[mt][2] = __float_as_uint(Al[ks + tig + 4][m]);
                al[mt][3] = __float_as_uint(Al[ks + tig + 4][m + 8]);
            }
#pragma unroll
            for (int nt = 0; nt < 4; nt++) {
                int c = wn * 32 + nt * 8 + group;
                unsigned bh0 = __float_as_uint(Bh[ks + tig][c]);
                unsigned bh1 = __float_as_uint(Bh[ks + tig + 4][c]);
                unsigned bl0 = __float_as_uint(Bl[ks + tig][c]);
                unsigned bl1 = __float_as_uint(Bl[ks + tig + 4][c]);
#pragma unroll
                for (int mt = 0; mt < 4; mt++) {
                    mma_tf32(acc[mt][nt], ah[mt], bh0, bh1);
                    mma_tf32(acc[mt][nt], ah[mt], bl0, bl1);
                    mma_tf32(acc[mt][nt], al[mt], bh0, bh1);
                }
            }
        }
        __syncthreads();
    }

#pragma unroll
    for (int mt = 0; mt < 4; mt++) {
#pragma unroll
        for (int h = 0; h < 2; h++) {
            int r = row0 + wm * 64 + mt * 16 + group + 8 * h;
            if (r >= n) continue;
#pragma unroll
            for (int nt = 0; nt < 4; nt++) {
                int cb = wn * 32 + nt * 8 + tig * 2;
                *(float2*)(out + (size_t)r * 128 + cb) =
                    make_float2(acc[mt][nt][2 * h], acc[mt][nt][2 * h + 1]);
            }
        }
    }
}

// ---------------- fused top-k: 3 radix passes, warp-aggregated atomics ----------------
__device__ __forceinline__ void scan_pass(int pass, unsigned kr_in, unsigned* kr_out,
                                          unsigned long long* prefix, int shift) {
    __shared__ unsigned arr[256], rev[256];
    __shared__ unsigned sh_dig, sh_kr;
    int t = threadIdx.x;
    int cb0 = t * 4;
    unsigned s = 0;
#pragma unroll
    for (int q = 0; q < 4; q++) s += g_coarse[pass][cb0 + q];
    arr[t] = s;
    __syncthreads();
    rev[t] = arr[255 - t];
    __syncthreads();
    for (int off = 1; off < 256; off <<= 1) {
        unsigned v = (t >= off) ? rev[t - off] : 0u;
        __syncthreads();
        rev[t] += v;
        __syncthreads();
    }
    unsigned suf = rev[255 - t];
    unsigned above = suf - s;
    if (above < kr_in && suf >= kr_in) {   // exactly one thread
        unsigned running = above;
        for (int b = 3; b >= 0; b--) {
            unsigned c = g_coarse[pass][cb0 + b];
            if (running + c >= kr_in) {
                int fb = (cb0 + b) * 64;
                for (int d = 63; d >= 0; d--) {
                    unsigned fc = g_hist[pass][fb + d];
                    if (running + fc >= kr_in) {
                        sh_kr = kr_in - running;
                        sh_dig = (unsigned)(fb + d);
                        break;
                    }
                    running += fc;
                }
                break;
            }
            running += c;
        }
    }
    __syncthreads();
    *prefix |= ((unsigned long long)sh_dig) << shift;
    *kr_out = sh_kr;
    __syncthreads();
}

__global__ void __launch_bounds__(256) k_topk(int n, unsigned k, int nb) {
    int t = threadIdx.x;
    int lane = t & 31;
    int i = blockIdx.x * 256 + t;
    bool valid = (i < n);
    unsigned long long key = valid ? make_key(g_score[i], i) : 0ull;
    unsigned long long prefix = 0;
    unsigned kr = k;
    unsigned digits[3];
    int actmask = 0;
#pragma unroll
    for (int pass = 0; pass < 3; pass++) {
        int shift = 32 - 16 * pass;
        bool act = valid && (pass == 0 || ((key >> (shift + 16)) == (prefix >> (shift + 16))));
        unsigned digit = (unsigned)((key >> shift) & 0xFFFFull);
        unsigned am = __ballot_sync(0xFFFFFFFFu, act);
        if (act) {
            digits[pass] = digit;
            actmask |= 1 << pass;
            // warp-aggregate equal digits (saturated scores concentrate in one bin)
            unsigned peers = __match_any_sync(am, digit);
            if (lane == (__ffs(peers) - 1)) {
                unsigned cnt = (unsigned)__popc(peers);
                atomicAdd(&g_hist[pass][digit], cnt);
                atomicAdd(&g_coarse[pass][digit >> 6], cnt);
            }
        }
        gridbar((unsigned)nb);
        scan_pass(pass, kr, &kr, &prefix, shift);
    }
    gridbar((unsigned)nb);  // all scans done before clearing
    // clear touched bins (leaders only; plain stores)
#pragma unroll
    for (int pass = 0; pass < 3; pass++) {
        bool a = (actmask >> pass) & 1;
        unsigned am = __ballot_sync(0xFFFFFFFFu, a);
        if (a) {
            unsigned peers = __match_any_sync(am, digits[pass]);
            if (lane == (__ffs(peers) - 1)) {
                g_hist[pass][digits[pass]] = 0u;
                g_coarse[pass][digits[pass] >> 6] = 0u;
            }
        }
    }
    if (valid) g_degi[i] = 0;  // degrees consumed; clear for next layer
    bool sel = valid && (key >= prefix);
    unsigned bm = __ballot_sync(0xFFFFFFFFu, sel);
    if (sel) {
        int leader = __ffs(bm) - 1;
        unsigned base;
        if (lane == leader) base = atomicAdd(&g_selcnt, (unsigned)__popc(bm));
        base = __shfl_sync(bm, base, leader);
        unsigned pos = base + __popc(bm & ((1u << lane) - 1u));
        g_sel[pos] = i;
        g_remap[i] = (int)pos;
    } else if (valid) {
        g_remap[i] = -1;
    }
}

// ---------------- MLP head ----------------
__global__ void k_lin1(const float* __restrict__ W) {
    int col = blockIdx.x * 256 + threadIdx.x;
    int r0 = blockIdx.y * 320;
    float acc = 0.f;
    for (int r = r0; r < r0 + 320; r++) acc += g_reads[r] * W[(size_t)r * 1280 + col];
    atomicAdd(&g_z1[col], acc);
}

__global__ void k_lin2(const float* __restrict__ b1, const float* __restrict__ W2,
                       const float* __restrict__ b2, const float* __restrict__ pa,
                       float* __restrict__ out) {
    int tid = threadIdx.x;
    float a = pa[0];
    float acc[8] = {0, 0, 0, 0, 0, 0, 0, 0};
    for (int i = tid; i < 1280; i += 256) {
        float v = g_z1[i] + b1[i];
        v = v > 0.f ? v : a * v;
#pragma unroll
        for (int j = 0; j < 8; j++) acc[j] += v * W2[i * 8 + j];
    }
    __shared__ float red[256][8];
#pragma unroll
    for (int j = 0; j < 8; j++) red[tid][j] = acc[j];
    __syncthreads();
    for (int s = 128; s > 0; s >>= 1) {
        if (tid < s)
#pragma unroll
            for (int j = 0; j < 8; j++) red[tid][j] += red[tid + s][j];
        __syncthreads();
    }
    if (tid == 0) {
        float z[8];
#pragma unroll
        for (int j = 0; j < 8; j++) {
            float s = red[0][j] + b2[j];
            z[j] = s > 0.f ? s : a * s;
        }
        float mn = z[0];
#pragma unroll
        for (int j = 1; j < 8; j++) mn = fminf(mn, z[j]);
#pragma unroll
        for (int j = 0; j < 8; j++) z[j] -= mn;
        float mx = z[0];
#pragma unroll
        for (int j = 1; j < 8; j++) mx = fmaxf(mx, z[j]);
#pragma unroll
        for (int j = 0; j < 8; j++) z[j] /= mx;
        float sm = 0.f;
#pragma unroll
        for (int j = 0; j < 8; j++) sm += z[j];
#pragma unroll
        for (int j = 0; j < 8; j++) out[j] = z[j] / sm;
    }
}

// ---------------- launcher ----------------
extern "C" void kernel_launch(void* const* d_in, const int* in_sizes, int n_in,
                              void* d_out, int out_size) {
    const float* x       = (const float*)d_in[0];
    const int*   ei      = (const int*)  d_in[1];
    const float* W1      = (const float*)d_in[2];
    const float* V1      = (const float*)d_in[3];
    const float* Ws      = (const float*)d_in[4];
    const float* Vs      = (const float*)d_in[5];
    const float* conv_b  = (const float*)d_in[6];
    const float* bn_g    = (const float*)d_in[7];
    const float* bn_b    = (const float*)d_in[8];
    const float* bn_m    = (const float*)d_in[9];
    const float* bn_v    = (const float*)d_in[10];
    const float* pool_p  = (const float*)d_in[11];
    const float* prelu_a = (const float*)d_in[12];
    const float* lin1_w  = (const float*)d_in[13];
    const float* lin1_b  = (const float*)d_in[14];
    const float* lin2_w  = (const float*)d_in[15];
    const float* lin2_b  = (const float*)d_in[16];
    float* out = (float*)d_out;

    // side stream + fork/join events, created once on the first (non-capturing) call
    static cudaStream_t s2 = nullptr;
    static cudaEvent_t evF = nullptr, evP = nullptr;
    if (!s2) {
        cudaStreamCreateWithFlags(&s2, cudaStreamNonBlocking);
        cudaEventCreateWithFlags(&evF, cudaEventDisableTiming);
        cudaEventCreateWithFlags(&evP, cudaEventDisableTiming);
    }

    // pre-loop: edges/degrees, constants, layer-0 CSR, layer-0 rank-1 "GEMM"
    k_zerodeg<<<(NPAD + 255) / 256, 256>>>();
    k_init<<<512, 256>>>(ei);
    k_prep<<<10, 128>>>(bn_g, bn_b, bn_m, bn_v, pool_p);
    k_tilesum<<<NT[0], 256>>>(0, NS[0], NT[0]);
    k_offsets<<<NT[0], 256>>>(NS[0]);
    k_csrfill<<<256, 256>>>(0, 0);
    k_rank1<<<1024, 256>>>(x, W1, V1, NS[0]);

    for (int L = 0; L < 10; L++) {
        int n = NS[L], k = KS[L];
        int eb = L & 1;

        if (L > 0) cudaStreamWaitEvent(0, evP, 0);   // CSR(L) ready

        k_aggepi<<<(n * 32 + 255) / 256, 256>>>(L, n, conv_b + (size_t)L * D,
                                                prelu_a, pool_p + (size_t)L * D);

        int gN = (n + 255) / 256;
        k_topk<<<gN, 256>>>(n, (unsigned)k, gN);

        // fork: side chain (edge remap, reads reduce, next-layer CSR prep)
        cudaEventRecord(evF, 0);
        cudaStreamWaitEvent(s2, evF, 0);
        if (L < 9) {
            k_remapedges<<<256, 256, 0, s2>>>(L, eb);
            k_readsreduce<<<(k + 63) / 64, 128, 0, s2>>>(L, k, 1.0f / (float)k);
            k_tilesum<<<NT[L + 1], 256, 0, s2>>>(L + 1, k, NT[L + 1]);
            k_offsets<<<NT[L + 1], 256, 0, s2>>>(k);
            k_csrfill<<<256, 256, 0, s2>>>(L + 1, eb ^ 1);
        } else {
            k_readsreduce<<<(k + 63) / 64, 128, 0, s2>>>(L, k, 1.0f / (float)k);
        }
        cudaEventRecord(evP, s2);

        // main: next layer's GEMM reads pooled rows via g_sel/g_score indirection
        if (L < 9)
            k_gemm2<<<dim3((k + 127) / 128, 2), 256>>>(Ws + (size_t)L * D * D,
                                                       Vs + (size_t)L * D * D, k);
    }

    cudaStreamWaitEvent(0, evP, 0);   // reads(9) complete
    k_lin1<<<dim3(5, 8), 256>>>(lin1_w);
    k_lin2<<<1, 256>>>(lin1_b, lin2_w, lin2_b, prelu_a, out);

    (void)in_sizes; (void)n_in; (void)out_size;
}